// round 8
// baseline (speedup 1.0000x reference)
#include <cuda_runtime.h>
#include <cuda_bf16.h>
#include <cstddef>
#include <cstdint>

// Problem constants
#define BATCH 8
#define SEQ   1024
#define DIM   1024
#define HEADS 16
#define HDIM  64
#define MROWS (BATCH * SEQ)          // 8192
#define QKVN  (3 * DIM)              // 3072
#define SCALE 0.03125f               // DIM^-0.5 = 1/32
#define MASKV (-3.402823466e38f)
#define NEGINF (-__int_as_float(0x7f800000) * 1.0f)

// Scratch (static device globals: allocation-free rule)
__device__ float g_q[BATCH * HEADS * SEQ * HDIM];     // [b,h,n,d]  (tf32-rounded)
__device__ float g_k[BATCH * HEADS * SEQ * HDIM];
__device__ float g_v[BATCH * HEADS * SEQ * HDIM];
__device__ float g_attn[BATCH * SEQ * DIM];           // [b,n,h*d]  (tf32-rounded)
// tf32-rounded input copies (rounding hoisted out of GEMM hot loops)
__device__ float g_xr[MROWS * DIM];
__device__ float g_wqkr[2 * DIM * DIM];
__device__ float g_wvr[DIM * DIM];
__device__ float g_woutr[DIM * DIM];

// ---------------------------------------------------------------------------
// helpers
// ---------------------------------------------------------------------------
__device__ __forceinline__ float tf32_rna(float x) {
    uint32_t u;
    asm("cvt.rna.tf32.f32 %0, %1;" : "=r"(u) : "f"(x));
    return __uint_as_float(u);
}

__device__ __forceinline__ void mma_tf32_16x8x8(float* c, const float* a, const float* b) {
    asm volatile(
        "mma.sync.aligned.m16n8k8.row.col.f32.tf32.tf32.f32 "
        "{%0,%1,%2,%3}, {%4,%5,%6,%7}, {%8,%9}, {%0,%1,%2,%3};"
        : "+f"(c[0]), "+f"(c[1]), "+f"(c[2]), "+f"(c[3])
        : "r"(__float_as_uint(a[0])), "r"(__float_as_uint(a[1])),
          "r"(__float_as_uint(a[2])), "r"(__float_as_uint(a[3])),
          "r"(__float_as_uint(b[0])), "r"(__float_as_uint(b[1])));
}

__device__ __forceinline__ void cp16(void* smem, const void* g) {
    uint32_t s = (uint32_t)__cvta_generic_to_shared(smem);
    asm volatile("cp.async.cg.shared.global [%0], [%1], 16;" :: "r"(s), "l"(g));
}
__device__ __forceinline__ void cp_commit() {
    asm volatile("cp.async.commit_group;");
}

// ---------------------------------------------------------------------------
// Kernel 0: round fp32 -> tf32-valued fp32 (vectorized)
// ---------------------------------------------------------------------------
__global__ __launch_bounds__(256) void round_kernel(
    const float4* __restrict__ src, float4* __restrict__ dst, int n4)
{
    int i = blockIdx.x * 256 + threadIdx.x;
    if (i < n4) {
        float4 v = src[i];
        v.x = tf32_rna(v.x); v.y = tf32_rna(v.y);
        v.z = tf32_rna(v.z); v.w = tf32_rna(v.w);
        dst[i] = v;
    }
}

// ---------------------------------------------------------------------------
// tf32 GEMM core, cp.async 2-stage pipeline. CTA tile 256x128, K-tile 32,
// 256 threads, 8 warps in 4(M) x 2(N); warp tile 64x64 via m16n8k8.
// Lower smem-fragment duplication than 128x128/2x4 (1.5x fewer LDS bytes
// per output element). Inputs must already be tf32-valued.
// ---------------------------------------------------------------------------
#define TPAD 36   // row stride 144 B (16B-aligned, bank-permuting)
#define CTAM 256
#define CTAN 128

struct GemmAcc { float acc[4][8][4]; };   // [mi][ni][reg]

__device__ __forceinline__ void gemm_core_async(
    const float* __restrict__ Abase, const float* __restrict__ B0,
    const float* __restrict__ B1, int bm, int bn, bool splitB,
    float* sm, GemmAcc& g)
{
    // layout: As[2][256][TPAD], Bs[2][128][TPAD]
    float (*As)[CTAM][TPAD] = (float(*)[CTAM][TPAD])sm;
    float (*Bs)[CTAN][TPAD] = (float(*)[CTAN][TPAD])(sm + 2 * CTAM * TPAD);

    const int tid = threadIdx.x;
    const int lane = tid & 31;
    const int wid = tid >> 5;
    const int gid = lane >> 2, tg = lane & 3;
    const int wm = (wid & 3) * 64;     // 4 warps along M
    const int wn = (wid >> 2) * 64;    // 2 warps along N

#pragma unroll
    for (int mi = 0; mi < 4; mi++)
#pragma unroll
        for (int ni = 0; ni < 8; ni++)
#pragma unroll
            for (int r = 0; r < 4; r++) g.acc[mi][ni][r] = 0.f;

    auto load_tiles = [&](int st, int k0) {
#pragma unroll
        for (int i = tid; i < CTAM * 8; i += 256) {           // 2048 units
            int row = i >> 3, c4 = (i & 7) * 4;
            cp16(&As[st][row][c4], &Abase[(size_t)(bm + row) * DIM + k0 + c4]);
        }
#pragma unroll
        for (int i = tid; i < CTAN * 8; i += 256) {           // 1024 units
            int row = i >> 3, c4 = (i & 7) * 4;
            int gn = bn + row;
            const float* Brow = (splitB && gn >= 2 * DIM)
                                ? B1 + (size_t)(gn - 2 * DIM) * DIM
                                : B0 + (size_t)gn * DIM;
            cp16(&Bs[st][row][c4], &Brow[k0 + c4]);
        }
    };

    load_tiles(0, 0);
    cp_commit();

    const int NT = DIM / 32;  // 32
    for (int it = 0; it < NT; it++) {
        int cur = it & 1;
        if (it + 1 < NT) {
            load_tiles(cur ^ 1, (it + 1) * 32);
            cp_commit();
            asm volatile("cp.async.wait_group 1;");
        } else {
            asm volatile("cp.async.wait_group 0;");
        }
        __syncthreads();

#pragma unroll
        for (int ks = 0; ks < 32; ks += 8) {
            float a[4][4];
#pragma unroll
            for (int mi = 0; mi < 4; mi++) {
                int r0 = wm + mi * 16 + gid;
                a[mi][0] = As[cur][r0][ks + tg];
                a[mi][1] = As[cur][r0 + 8][ks + tg];
                a[mi][2] = As[cur][r0][ks + tg + 4];
                a[mi][3] = As[cur][r0 + 8][ks + tg + 4];
            }
            float b[8][2];
#pragma unroll
            for (int ni = 0; ni < 8; ni++) {
                int n0 = wn + ni * 8 + gid;
                b[ni][0] = Bs[cur][n0][ks + tg];
                b[ni][1] = Bs[cur][n0][ks + tg + 4];
            }
#pragma unroll
            for (int mi = 0; mi < 4; mi++)
#pragma unroll
                for (int ni = 0; ni < 8; ni++)
                    mma_tf32_16x8x8(g.acc[mi][ni], a[mi], b[ni]);
        }
        __syncthreads();
    }
}

#define GEMM_SMEM_BYTES ((2 * CTAM * TPAD + 2 * CTAN * TPAD) * 4)   // 110592

// ---------------------------------------------------------------------------
// Kernel 1: fused QKV projection. Epilogue adds pos (fp32), rounds result to
// tf32 (feeds attention MMAs), scatters to [b,h,n,d].
// ---------------------------------------------------------------------------
__global__ __launch_bounds__(256, 1) void qkv_gemm_kernel(const float* __restrict__ pos)
{
    extern __shared__ float sm[];
    const int bm = blockIdx.y * CTAM;
    const int bn = blockIdx.x * CTAN;
    const int lane = threadIdx.x & 31;
    const int wid = threadIdx.x >> 5;
    const int gid = lane >> 2, tg = lane & 3;
    const int wm = (wid & 3) * 64;
    const int wn = (wid >> 2) * 64;

    GemmAcc g;
    gemm_core_async(g_xr, g_wqkr, g_wvr, bm, bn, true, sm, g);

#pragma unroll
    for (int mi = 0; mi < 4; mi++) {
#pragma unroll
        for (int ni = 0; ni < 8; ni++) {
#pragma unroll
            for (int r = 0; r < 4; r++) {
                int m = bm + wm + mi * 16 + gid + ((r >= 2) ? 8 : 0);
                int gn = bn + wn + ni * 8 + 2 * tg + (r & 1);
                int b = m >> 10, row = m & 1023;
                float val = g.acc[mi][ni][r];
                if (gn < DIM) {
                    int c = gn, h = c >> 6, d = c & 63;
                    val = tf32_rna(val + pos[(size_t)m * DIM + c]);
                    g_q[(((size_t)b * HEADS + h) * SEQ + row) * HDIM + d] = val;
                } else if (gn < 2 * DIM) {
                    int c = gn - DIM, h = c >> 6, d = c & 63;
                    val = tf32_rna(val + pos[(size_t)m * DIM + c]);
                    g_k[(((size_t)b * HEADS + h) * SEQ + row) * HDIM + d] = val;
                } else {
                    int c = gn - 2 * DIM, h = c >> 6, d = c & 63;
                    g_v[(((size_t)b * HEADS + h) * SEQ + row) * HDIM + d] = tf32_rna(val);
                }
            }
        }
    }
}

// ---------------------------------------------------------------------------
// Kernel 3: output projection. out = g_attn @ W_out^T + b_out (fp32 epilogue)
// ---------------------------------------------------------------------------
__global__ __launch_bounds__(256, 1) void out_gemm_kernel(
    const float* __restrict__ bout, float* __restrict__ out)
{
    extern __shared__ float sm[];
    const int bm = blockIdx.y * CTAM;
    const int bn = blockIdx.x * CTAN;
    const int lane = threadIdx.x & 31;
    const int wid = threadIdx.x >> 5;
    const int gid = lane >> 2, tg = lane & 3;
    const int wm = (wid & 3) * 64;
    const int wn = (wid >> 2) * 64;

    GemmAcc g;
    gemm_core_async(g_attn, g_woutr, nullptr, bm, bn, false, sm, g);

#pragma unroll
    for (int mi = 0; mi < 4; mi++) {
#pragma unroll
        for (int ni = 0; ni < 8; ni++) {
#pragma unroll
            for (int r = 0; r < 4; r++) {
                int m = bm + wm + mi * 16 + gid + ((r >= 2) ? 8 : 0);
                int gn = bn + wn + ni * 8 + 2 * tg + (r & 1);
                out[(size_t)m * DIM + gn] = g.acc[mi][ni][r] + bout[gn];
            }
        }
    }
}

// ---------------------------------------------------------------------------
// Kernel 2: tensor-core flash attention with cp.async double-buffered K/V.
// Identical to the R5 version (known-good, 805us total).
// ---------------------------------------------------------------------------
#define AKPAD 68
#define AVPAD 72
#define ATT_SMEM_FLOATS (128 * AKPAD + 2 * 64 * AKPAD + 2 * 64 * AVPAD + 2 * 64)
#define ATT_SMEM_BYTES  (ATT_SMEM_FLOATS * 4)   // 107008

__global__ __launch_bounds__(256) void attn_kernel(const int* __restrict__ mask)
{
    extern __shared__ float sm[];
    float (*QP)[AKPAD]  = (float(*)[AKPAD])sm;                       // Q tile, later P
    float (*KsB)[AKPAD] = (float(*)[AKPAD])(sm + 128 * AKPAD);      // [2*64][AKPAD]
    float (*VsB)[AVPAD] = (float(*)[AVPAD])(sm + 128 * AKPAD + 2 * 64 * AKPAD);
    float* kmB = sm + 128 * AKPAD + 2 * 64 * AKPAD + 2 * 64 * AVPAD; // [2][64]

    const int bh = blockIdx.y;
    const int b = bh >> 4, h = bh & 15;
    const int i0 = blockIdx.x * 128;
    const int tid = threadIdx.x;
    const int lane = tid & 31, wid = tid >> 5;
    const int gid = lane >> 2, tg = lane & 3;
    const int r0 = wid * 16 + gid;
    const int r1 = r0 + 8;

    const float* qb = g_q + ((size_t)bh * SEQ + i0) * HDIM;
    const float* kb = g_k + (size_t)bh * SEQ * HDIM;
    const float* vb = g_v + (size_t)bh * SEQ * HDIM;

    auto load_kv = [&](int st, int j0) {
        float (*K)[AKPAD] = KsB + st * 64;
        float (*V)[AVPAD] = VsB + st * 64;
#pragma unroll
        for (int i = tid; i < 64 * 16; i += 256) {
            int row = i >> 4, c4 = (i & 15) * 4;
            cp16(&K[row][c4], &kb[(size_t)(j0 + row) * HDIM + c4]);
            cp16(&V[row][c4], &vb[(size_t)(j0 + row) * HDIM + c4]);
        }
    };
    auto load_km = [&](int st, int j0) {
        if (tid < 64) {
            int gj = j0 + tid;
            kmB[st * 64 + tid] =
                (gj == 0) ? 1.f : (mask[(size_t)b * (SEQ - 1) + gj - 1] ? 1.f : 0.f);
        }
    };

    load_kv(0, 0);
    cp_commit();
    load_km(0, 0);

    for (int i = tid; i < 128 * 16; i += 256) {
        int row = i >> 4, c4 = (i & 15) * 4;
        *(float4*)&QP[row][c4] = *(const float4*)&qb[(size_t)row * HDIM + c4];
    }
    __syncthreads();

    float qa[8][4];
#pragma unroll
    for (int ks = 0; ks < 8; ks++) {
        qa[ks][0] = QP[r0][ks * 8 + tg];
        qa[ks][1] = QP[r1][ks * 8 + tg];
        qa[ks][2] = QP[r0][ks * 8 + tg + 4];
        qa[ks][3] = QP[r1][ks * 8 + tg + 4];
    }
    const int gi0 = i0 + r0, gi1 = i0 + r1;
    const bool qok0 = (gi0 == 0) || (mask[(size_t)b * (SEQ - 1) + gi0 - 1] != 0);
    const bool qok1 = (gi1 == 0) || (mask[(size_t)b * (SEQ - 1) + gi1 - 1] != 0);

    float m0 = NEGINF, m1 = NEGINF, l0 = 0.f, l1 = 0.f;
    float o[8][4] = {};

    const int NT = SEQ / 64;   // 16
    for (int it = 0; it < NT; it++) {
        const int cur = it & 1;
        if (it + 1 < NT) {
            load_kv(cur ^ 1, (it + 1) * 64);
            cp_commit();
            load_km(cur ^ 1, (it + 1) * 64);
            asm volatile("cp.async.wait_group 1;");
        } else {
            asm volatile("cp.async.wait_group 0;");
        }
        __syncthreads();

        float (*Ks)[AKPAD] = KsB + cur * 64;
        float (*Vs)[AVPAD] = VsB + cur * 64;
        const float* km = kmB + cur * 64;

        float s[8][4] = {};
#pragma unroll
        for (int ks = 0; ks < 8; ks++) {
#pragma unroll
            for (int ni = 0; ni < 8; ni++) {
                float bf[2] = { Ks[ni * 8 + gid][ks * 8 + tg],
                                Ks[ni * 8 + gid][ks * 8 + tg + 4] };
                mma_tf32_16x8x8(s[ni], qa[ks], bf);
            }
        }

        float rmax0 = NEGINF, rmax1 = NEGINF;
#pragma unroll
        for (int ni = 0; ni < 8; ni++) {
            bool k0ok = km[ni * 8 + 2 * tg] != 0.f;
            bool k1ok = km[ni * 8 + 2 * tg + 1] != 0.f;
            s[ni][0] = (qok0 && k0ok) ? s[ni][0] * SCALE : MASKV;
            s[ni][1] = (qok0 && k1ok) ? s[ni][1] * SCALE : MASKV;
            s[ni][2] = (qok1 && k0ok) ? s[ni][2] * SCALE : MASKV;
            s[ni][3] = (qok1 && k1ok) ? s[ni][3] * SCALE : MASKV;
            rmax0 = fmaxf(rmax0, fmaxf(s[ni][0], s[ni][1]));
            rmax1 = fmaxf(rmax1, fmaxf(s[ni][2], s[ni][3]));
        }
        rmax0 = fmaxf(rmax0, __shfl_xor_sync(0xffffffffu, rmax0, 1));
        rmax0 = fmaxf(rmax0, __shfl_xor_sync(0xffffffffu, rmax0, 2));
        rmax1 = fmaxf(rmax1, __shfl_xor_sync(0xffffffffu, rmax1, 1));
        rmax1 = fmaxf(rmax1, __shfl_xor_sync(0xffffffffu, rmax1, 2));

        float nm0 = fmaxf(m0, rmax0), nm1 = fmaxf(m1, rmax1);
        float fac0 = __expf(m0 - nm0), fac1 = __expf(m1 - nm1);
        m0 = nm0; m1 = nm1;

        float sum0 = 0.f, sum1 = 0.f;
#pragma unroll
        for (int ni = 0; ni < 8; ni++) {
            float p0 = tf32_rna(__expf(s[ni][0] - m0));
            float p1 = tf32_rna(__expf(s[ni][1] - m0));
            float p2 = tf32_rna(__expf(s[ni][2] - m1));
            float p3 = tf32_rna(__expf(s[ni][3] - m1));
            sum0 += p0 + p1; sum1 += p2 + p3;
            QP[r0][ni * 8 + 2 * tg]     = p0;
            QP[r0][ni * 8 + 2 * tg + 1] = p1;
            QP[r1][ni * 8 + 2 * tg]     = p2;
            QP[r1][ni * 8 + 2 * tg + 1] = p3;
        }
        sum0 += __shfl_xor_sync(0xffffffffu, sum0, 1);
        sum0 += __shfl_xor_sync(0xffffffffu, sum0, 2);
        sum1 += __shfl_xor_sync(0xffffffffu, sum1, 1);
        sum1 += __shfl_xor_sync(0xffffffffu, sum1, 2);
        l0 = l0 * fac0 + sum0;
        l1 = l1 * fac1 + sum1;

#pragma unroll
        for (int ni = 0; ni < 8; ni++) {
            o[ni][0] *= fac0; o[ni][1] *= fac0;
            o[ni][2] *= fac1; o[ni][3] *= fac1;
        }
        __syncwarp();

#pragma unroll
        for (int ks = 0; ks < 8; ks++) {
            float pa[4] = { QP[r0][ks * 8 + tg], QP[r1][ks * 8 + tg],
                            QP[r0][ks * 8 + tg + 4], QP[r1][ks * 8 + tg + 4] };
#pragma unroll
            for (int ni = 0; ni < 8; ni++) {
                float bf[2] = { Vs[ks * 8 + tg][ni * 8 + gid],
                                Vs[ks * 8 + tg + 4][ni * 8 + gid] };
                mma_tf32_16x8x8(o[ni], pa, bf);
            }
        }
        __syncthreads();
    }

    float inv0 = 1.f / l0, inv1 = 1.f / l1;
    size_t row0 = (size_t)b * SEQ + i0 + r0;
    size_t row1 = (size_t)b * SEQ + i0 + r1;
#pragma unroll
    for (int ni = 0; ni < 8; ni++) {
        float2 v0 = { tf32_rna(o[ni][0] * inv0), tf32_rna(o[ni][1] * inv0) };
        float2 v1 = { tf32_rna(o[ni][2] * inv1), tf32_rna(o[ni][3] * inv1) };
        *(float2*)&g_attn[row0 * DIM + h * HDIM + ni * 8 + 2 * tg] = v0;
        *(float2*)&g_attn[row1 * DIM + h * HDIM + ni * 8 + 2 * tg] = v1;
    }
}

// ---------------------------------------------------------------------------
extern "C" void kernel_launch(void* const* d_in, const int* in_sizes, int n_in,
                              void* d_out, int out_size)
{
    const float* x    = (const float*)d_in[0];
    const int*   mask = (const int*)d_in[1];     // bool widened to int32 by harness
    const float* pos  = (const float*)d_in[2];
    const float* Wqk  = (const float*)d_in[3];
    const float* Wv   = (const float*)d_in[4];
    const float* Wout = (const float*)d_in[5];
    const float* bout = (const float*)d_in[6];
    float*       out  = (float*)d_out;

    cudaFuncSetAttribute(qkv_gemm_kernel, cudaFuncAttributeMaxDynamicSharedMemorySize,
                         GEMM_SMEM_BYTES);
    cudaFuncSetAttribute(out_gemm_kernel, cudaFuncAttributeMaxDynamicSharedMemorySize,
                         GEMM_SMEM_BYTES);
    cudaFuncSetAttribute(attn_kernel, cudaFuncAttributeMaxDynamicSharedMemorySize,
                         ATT_SMEM_BYTES);

    float* d_xr; float* d_wqkr; float* d_wvr; float* d_woutr;
    cudaGetSymbolAddress((void**)&d_xr,    g_xr);
    cudaGetSymbolAddress((void**)&d_wqkr,  g_wqkr);
    cudaGetSymbolAddress((void**)&d_wvr,   g_wvr);
    cudaGetSymbolAddress((void**)&d_woutr, g_woutr);

    {   // prep: round inputs to tf32 once
        int n4;
        n4 = MROWS * DIM / 4;
        round_kernel<<<(n4 + 255) / 256, 256>>>((const float4*)x, (float4*)d_xr, n4);
        n4 = 2 * DIM * DIM / 4;
        round_kernel<<<(n4 + 255) / 256, 256>>>((const float4*)Wqk, (float4*)d_wqkr, n4);
        n4 = DIM * DIM / 4;
        round_kernel<<<(n4 + 255) / 256, 256>>>((const float4*)Wv, (float4*)d_wvr, n4);
        round_kernel<<<(n4 + 255) / 256, 256>>>((const float4*)Wout, (float4*)d_woutr, n4);
    }
    {   // QKV projection: M=8192, N=3072 -> 32 x 24 CTAs
        dim3 grid(QKVN / CTAN, MROWS / CTAM);
        qkv_gemm_kernel<<<grid, 256, GEMM_SMEM_BYTES>>>(pos);
    }
    {   // Attention: 8 row-tiles x 128 (b,h) pairs
        dim3 grid(SEQ / 128, BATCH * HEADS);
        attn_kernel<<<grid, 256, ATT_SMEM_BYTES>>>(mask);
    }
    {   // Output projection: M=8192, N=1024 -> 32 x 8 CTAs
        dim3 grid(DIM / CTAN, MROWS / CTAM);
        out_gemm_kernel<<<grid, 256, GEMM_SMEM_BYTES>>>(bout, out);
    }
}

// round 9
// speedup vs baseline: 1.1026x; 1.1026x over previous
#include <cuda_runtime.h>
#include <cuda_bf16.h>
#include <cstddef>
#include <cstdint>

// Problem constants
#define BATCH 8
#define SEQ   1024
#define DIM   1024
#define HEADS 16
#define HDIM  64
#define MROWS (BATCH * SEQ)          // 8192
#define QKVN  (3 * DIM)              // 3072
#define SCALE 0.03125f               // DIM^-0.5 = 1/32
#define MASKV (-3.402823466e38f)
#define NEGINF (-__int_as_float(0x7f800000) * 1.0f)

// Scratch (static device globals: allocation-free rule)
__device__ float g_q[BATCH * HEADS * SEQ * HDIM];     // [b,h,n,d]  (tf32-rounded)
__device__ float g_k[BATCH * HEADS * SEQ * HDIM];
__device__ float g_v[BATCH * HEADS * SEQ * HDIM];
__device__ float g_attn[BATCH * SEQ * DIM];           // [b,n,h*d]  (tf32-rounded)
// tf32-rounded input copies (rounding hoisted out of GEMM hot loops)
__device__ float g_xr[MROWS * DIM];
__device__ float g_wqkr[2 * DIM * DIM];
__device__ float g_wvr[DIM * DIM];
__device__ float g_woutr[DIM * DIM];

// ---------------------------------------------------------------------------
// helpers
// ---------------------------------------------------------------------------
__device__ __forceinline__ float tf32_rna(float x) {
    uint32_t u;
    asm("cvt.rna.tf32.f32 %0, %1;" : "=r"(u) : "f"(x));
    return __uint_as_float(u);
}

__device__ __forceinline__ void mma_tf32_16x8x8(float* c, const float* a, const float* b) {
    asm volatile(
        "mma.sync.aligned.m16n8k8.row.col.f32.tf32.tf32.f32 "
        "{%0,%1,%2,%3}, {%4,%5,%6,%7}, {%8,%9}, {%0,%1,%2,%3};"
        : "+f"(c[0]), "+f"(c[1]), "+f"(c[2]), "+f"(c[3])
        : "r"(__float_as_uint(a[0])), "r"(__float_as_uint(a[1])),
          "r"(__float_as_uint(a[2])), "r"(__float_as_uint(a[3])),
          "r"(__float_as_uint(b[0])), "r"(__float_as_uint(b[1])));
}

__device__ __forceinline__ void cp16(void* smem, const void* g) {
    uint32_t s = (uint32_t)__cvta_generic_to_shared(smem);
    asm volatile("cp.async.cg.shared.global [%0], [%1], 16;" :: "r"(s), "l"(g));
}
__device__ __forceinline__ void cp_commit() {
    asm volatile("cp.async.commit_group;");
}

// ---------------------------------------------------------------------------
// Kernel 0: round fp32 -> tf32-valued fp32 (vectorized)
// ---------------------------------------------------------------------------
__global__ __launch_bounds__(256) void round_kernel(
    const float4* __restrict__ src, float4* __restrict__ dst, int n4)
{
    int i = blockIdx.x * 256 + threadIdx.x;
    if (i < n4) {
        float4 v = src[i];
        v.x = tf32_rna(v.x); v.y = tf32_rna(v.y);
        v.z = tf32_rna(v.z); v.w = tf32_rna(v.w);
        dst[i] = v;
    }
}

// ---------------------------------------------------------------------------
// tf32 GEMM core, cp.async 3-stage pipeline. 128x128 tile, K-tile 32,
// 256 threads, 8 warps (2M x 4N), warp tile 64x32 via m16n8k8.
// (R5 config: 124 regs, 2 CTAs/SM; only change vs R5 is pipeline depth 2->3.)
// ---------------------------------------------------------------------------
#define TPAD 36   // row stride 144 B (16B-aligned, bank-permuting)

struct GemmAcc { float acc[4][4][4]; };

__device__ __forceinline__ void gemm_core_async(
    const float* __restrict__ Abase, const float* __restrict__ B0,
    const float* __restrict__ B1, int bm, int bn, bool splitB,
    float* sm, GemmAcc& g)
{
    // layout: As[3][128][TPAD], Bs[3][128][TPAD]
    float (*As)[128][TPAD] = (float(*)[128][TPAD])sm;
    float (*Bs)[128][TPAD] = (float(*)[128][TPAD])(sm + 3 * 128 * TPAD);

    const int tid = threadIdx.x;
    const int lane = tid & 31;
    const int wid = tid >> 5;
    const int gid = lane >> 2, tg = lane & 3;
    const int wm = (wid & 1) * 64;
    const int wn = (wid >> 1) * 32;

#pragma unroll
    for (int mi = 0; mi < 4; mi++)
#pragma unroll
        for (int ni = 0; ni < 4; ni++)
#pragma unroll
            for (int r = 0; r < 4; r++) g.acc[mi][ni][r] = 0.f;

    auto load_tiles = [&](int st, int k0) {
#pragma unroll
        for (int i = tid; i < 128 * 8; i += 256) {
            int row = i >> 3, c4 = (i & 7) * 4;
            cp16(&As[st][row][c4], &Abase[(size_t)(bm + row) * DIM + k0 + c4]);
        }
#pragma unroll
        for (int i = tid; i < 128 * 8; i += 256) {
            int row = i >> 3, c4 = (i & 7) * 4;
            int gn = bn + row;
            const float* Brow = (splitB && gn >= 2 * DIM)
                                ? B1 + (size_t)(gn - 2 * DIM) * DIM
                                : B0 + (size_t)gn * DIM;
            cp16(&Bs[st][row][c4], &Brow[k0 + c4]);
        }
    };

    load_tiles(0, 0);  cp_commit();
    load_tiles(1, 32); cp_commit();

    const int NT = DIM / 32;  // 32
    for (int it = 0; it < NT; it++) {
        int cur = it % 3;
        if (it + 2 < NT) {
            load_tiles((it + 2) % 3, (it + 2) * 32);
            cp_commit();
            asm volatile("cp.async.wait_group 2;");
        } else if (it + 1 < NT) {
            asm volatile("cp.async.wait_group 1;");
        } else {
            asm volatile("cp.async.wait_group 0;");
        }
        __syncthreads();

#pragma unroll
        for (int ks = 0; ks < 32; ks += 8) {
            float a[4][4];
#pragma unroll
            for (int mi = 0; mi < 4; mi++) {
                int r0 = wm + mi * 16 + gid;
                a[mi][0] = As[cur][r0][ks + tg];
                a[mi][1] = As[cur][r0 + 8][ks + tg];
                a[mi][2] = As[cur][r0][ks + tg + 4];
                a[mi][3] = As[cur][r0 + 8][ks + tg + 4];
            }
            float b[4][2];
#pragma unroll
            for (int ni = 0; ni < 4; ni++) {
                int n0 = wn + ni * 8 + gid;
                b[ni][0] = Bs[cur][n0][ks + tg];
                b[ni][1] = Bs[cur][n0][ks + tg + 4];
            }
#pragma unroll
            for (int mi = 0; mi < 4; mi++)
#pragma unroll
                for (int ni = 0; ni < 4; ni++)
                    mma_tf32_16x8x8(g.acc[mi][ni], a[mi], b[ni]);
        }
        __syncthreads();
    }
}

#define GEMM_SMEM_BYTES (6 * 128 * TPAD * 4)   // 110592

// ---------------------------------------------------------------------------
// Kernel 1: fused QKV projection. Epilogue adds pos (fp32), rounds result to
// tf32 (feeds attention MMAs), scatters to [b,h,n,d].
// ---------------------------------------------------------------------------
__global__ __launch_bounds__(256) void qkv_gemm_kernel(const float* __restrict__ pos)
{
    extern __shared__ float sm[];
    const int bm = blockIdx.y * 128;
    const int bn = blockIdx.x * 128;
    const int lane = threadIdx.x & 31;
    const int wid = threadIdx.x >> 5;
    const int gid = lane >> 2, tg = lane & 3;
    const int wm = (wid & 1) * 64;
    const int wn = (wid >> 1) * 32;

    GemmAcc g;
    gemm_core_async(g_xr, g_wqkr, g_wvr, bm, bn, true, sm, g);

#pragma unroll
    for (int mi = 0; mi < 4; mi++) {
#pragma unroll
        for (int ni = 0; ni < 4; ni++) {
#pragma unroll
            for (int r = 0; r < 4; r++) {
                int m = bm + wm + mi * 16 + gid + ((r >= 2) ? 8 : 0);
                int gn = bn + wn + ni * 8 + 2 * tg + (r & 1);
                int b = m >> 10, row = m & 1023;
                float val = g.acc[mi][ni][r];
                if (gn < DIM) {
                    int c = gn, h = c >> 6, d = c & 63;
                    val = tf32_rna(val + pos[(size_t)m * DIM + c]);
                    g_q[(((size_t)b * HEADS + h) * SEQ + row) * HDIM + d] = val;
                } else if (gn < 2 * DIM) {
                    int c = gn - DIM, h = c >> 6, d = c & 63;
                    val = tf32_rna(val + pos[(size_t)m * DIM + c]);
                    g_k[(((size_t)b * HEADS + h) * SEQ + row) * HDIM + d] = val;
                } else {
                    int c = gn - 2 * DIM, h = c >> 6, d = c & 63;
                    g_v[(((size_t)b * HEADS + h) * SEQ + row) * HDIM + d] = tf32_rna(val);
                }
            }
        }
    }
}

// ---------------------------------------------------------------------------
// Kernel 3: output projection. out = g_attn @ W_out^T + b_out (fp32 epilogue)
// ---------------------------------------------------------------------------
__global__ __launch_bounds__(256) void out_gemm_kernel(
    const float* __restrict__ bout, float* __restrict__ out)
{
    extern __shared__ float sm[];
    const int bm = blockIdx.y * 128;
    const int bn = blockIdx.x * 128;
    const int lane = threadIdx.x & 31;
    const int wid = threadIdx.x >> 5;
    const int gid = lane >> 2, tg = lane & 3;
    const int wm = (wid & 1) * 64;
    const int wn = (wid >> 1) * 32;

    GemmAcc g;
    gemm_core_async(g_attn, g_woutr, nullptr, bm, bn, false, sm, g);

#pragma unroll
    for (int mi = 0; mi < 4; mi++) {
#pragma unroll
        for (int ni = 0; ni < 4; ni++) {
#pragma unroll
            for (int r = 0; r < 4; r++) {
                int m = bm + wm + mi * 16 + gid + ((r >= 2) ? 8 : 0);
                int gn = bn + wn + ni * 8 + 2 * tg + (r & 1);
                out[(size_t)m * DIM + gn] = g.acc[mi][ni][r] + bout[gn];
            }
        }
    }
}

// ---------------------------------------------------------------------------
// Kernel 2: tensor-core flash attention with cp.async double-buffered K/V.
// Identical to the R5 version (known-good).
// ---------------------------------------------------------------------------
#define AKPAD 68
#define AVPAD 72
#define ATT_SMEM_FLOATS (128 * AKPAD + 2 * 64 * AKPAD + 2 * 64 * AVPAD + 2 * 64)
#define ATT_SMEM_BYTES  (ATT_SMEM_FLOATS * 4)   // 107008

__global__ __launch_bounds__(256) void attn_kernel(const int* __restrict__ mask)
{
    extern __shared__ float sm[];
    float (*QP)[AKPAD]  = (float(*)[AKPAD])sm;                       // Q tile, later P
    float (*KsB)[AKPAD] = (float(*)[AKPAD])(sm + 128 * AKPAD);      // [2*64][AKPAD]
    float (*VsB)[AVPAD] = (float(*)[AVPAD])(sm + 128 * AKPAD + 2 * 64 * AKPAD);
    float* kmB = sm + 128 * AKPAD + 2 * 64 * AKPAD + 2 * 64 * AVPAD; // [2][64]

    const int bh = blockIdx.y;
    const int b = bh >> 4, h = bh & 15;
    const int i0 = blockIdx.x * 128;
    const int tid = threadIdx.x;
    const int lane = tid & 31, wid = tid >> 5;
    const int gid = lane >> 2, tg = lane & 3;
    const int r0 = wid * 16 + gid;
    const int r1 = r0 + 8;

    const float* qb = g_q + ((size_t)bh * SEQ + i0) * HDIM;
    const float* kb = g_k + (size_t)bh * SEQ * HDIM;
    const float* vb = g_v + (size_t)bh * SEQ * HDIM;

    auto load_kv = [&](int st, int j0) {
        float (*K)[AKPAD] = KsB + st * 64;
        float (*V)[AVPAD] = VsB + st * 64;
#pragma unroll
        for (int i = tid; i < 64 * 16; i += 256) {
            int row = i >> 4, c4 = (i & 15) * 4;
            cp16(&K[row][c4], &kb[(size_t)(j0 + row) * HDIM + c4]);
            cp16(&V[row][c4], &vb[(size_t)(j0 + row) * HDIM + c4]);
        }
    };
    auto load_km = [&](int st, int j0) {
        if (tid < 64) {
            int gj = j0 + tid;
            kmB[st * 64 + tid] =
                (gj == 0) ? 1.f : (mask[(size_t)b * (SEQ - 1) + gj - 1] ? 1.f : 0.f);
        }
    };

    load_kv(0, 0);
    cp_commit();
    load_km(0, 0);

    for (int i = tid; i < 128 * 16; i += 256) {
        int row = i >> 4, c4 = (i & 15) * 4;
        *(float4*)&QP[row][c4] = *(const float4*)&qb[(size_t)row * HDIM + c4];
    }
    __syncthreads();

    float qa[8][4];
#pragma unroll
    for (int ks = 0; ks < 8; ks++) {
        qa[ks][0] = QP[r0][ks * 8 + tg];
        qa[ks][1] = QP[r1][ks * 8 + tg];
        qa[ks][2] = QP[r0][ks * 8 + tg + 4];
        qa[ks][3] = QP[r1][ks * 8 + tg + 4];
    }
    const int gi0 = i0 + r0, gi1 = i0 + r1;
    const bool qok0 = (gi0 == 0) || (mask[(size_t)b * (SEQ - 1) + gi0 - 1] != 0);
    const bool qok1 = (gi1 == 0) || (mask[(size_t)b * (SEQ - 1) + gi1 - 1] != 0);

    float m0 = NEGINF, m1 = NEGINF, l0 = 0.f, l1 = 0.f;
    float o[8][4] = {};

    const int NT = SEQ / 64;   // 16
    for (int it = 0; it < NT; it++) {
        const int cur = it & 1;
        if (it + 1 < NT) {
            load_kv(cur ^ 1, (it + 1) * 64);
            cp_commit();
            load_km(cur ^ 1, (it + 1) * 64);
            asm volatile("cp.async.wait_group 1;");
        } else {
            asm volatile("cp.async.wait_group 0;");
        }
        __syncthreads();

        float (*Ks)[AKPAD] = KsB + cur * 64;
        float (*Vs)[AVPAD] = VsB + cur * 64;
        const float* km = kmB + cur * 64;

        float s[8][4] = {};
#pragma unroll
        for (int ks = 0; ks < 8; ks++) {
#pragma unroll
            for (int ni = 0; ni < 8; ni++) {
                float bf[2] = { Ks[ni * 8 + gid][ks * 8 + tg],
                                Ks[ni * 8 + gid][ks * 8 + tg + 4] };
                mma_tf32_16x8x8(s[ni], qa[ks], bf);
            }
        }

        float rmax0 = NEGINF, rmax1 = NEGINF;
#pragma unroll
        for (int ni = 0; ni < 8; ni++) {
            bool k0ok = km[ni * 8 + 2 * tg] != 0.f;
            bool k1ok = km[ni * 8 + 2 * tg + 1] != 0.f;
            s[ni][0] = (qok0 && k0ok) ? s[ni][0] * SCALE : MASKV;
            s[ni][1] = (qok0 && k1ok) ? s[ni][1] * SCALE : MASKV;
            s[ni][2] = (qok1 && k0ok) ? s[ni][2] * SCALE : MASKV;
            s[ni][3] = (qok1 && k1ok) ? s[ni][3] * SCALE : MASKV;
            rmax0 = fmaxf(rmax0, fmaxf(s[ni][0], s[ni][1]));
            rmax1 = fmaxf(rmax1, fmaxf(s[ni][2], s[ni][3]));
        }
        rmax0 = fmaxf(rmax0, __shfl_xor_sync(0xffffffffu, rmax0, 1));
        rmax0 = fmaxf(rmax0, __shfl_xor_sync(0xffffffffu, rmax0, 2));
        rmax1 = fmaxf(rmax1, __shfl_xor_sync(0xffffffffu, rmax1, 1));
        rmax1 = fmaxf(rmax1, __shfl_xor_sync(0xffffffffu, rmax1, 2));

        float nm0 = fmaxf(m0, rmax0), nm1 = fmaxf(m1, rmax1);
        float fac0 = __expf(m0 - nm0), fac1 = __expf(m1 - nm1);
        m0 = nm0; m1 = nm1;

        float sum0 = 0.f, sum1 = 0.f;
#pragma unroll
        for (int ni = 0; ni < 8; ni++) {
            float p0 = tf32_rna(__expf(s[ni][0] - m0));
            float p1 = tf32_rna(__expf(s[ni][1] - m0));
            float p2 = tf32_rna(__expf(s[ni][2] - m1));
            float p3 = tf32_rna(__expf(s[ni][3] - m1));
            sum0 += p0 + p1; sum1 += p2 + p3;
            QP[r0][ni * 8 + 2 * tg]     = p0;
            QP[r0][ni * 8 + 2 * tg + 1] = p1;
            QP[r1][ni * 8 + 2 * tg]     = p2;
            QP[r1][ni * 8 + 2 * tg + 1] = p3;
        }
        sum0 += __shfl_xor_sync(0xffffffffu, sum0, 1);
        sum0 += __shfl_xor_sync(0xffffffffu, sum0, 2);
        sum1 += __shfl_xor_sync(0xffffffffu, sum1, 1);
        sum1 += __shfl_xor_sync(0xffffffffu, sum1, 2);
        l0 = l0 * fac0 + sum0;
        l1 = l1 * fac1 + sum1;

#pragma unroll
        for (int ni = 0; ni < 8; ni++) {
            o[ni][0] *= fac0; o[ni][1] *= fac0;
            o[ni][2] *= fac1; o[ni][3] *= fac1;
        }
        __syncwarp();

#pragma unroll
        for (int ks = 0; ks < 8; ks++) {
            float pa[4] = { QP[r0][ks * 8 + tg], QP[r1][ks * 8 + tg],
                            QP[r0][ks * 8 + tg + 4], QP[r1][ks * 8 + tg + 4] };
#pragma unroll
            for (int ni = 0; ni < 8; ni++) {
                float bf[2] = { Vs[ks * 8 + tg][ni * 8 + gid],
                                Vs[ks * 8 + tg + 4][ni * 8 + gid] };
                mma_tf32_16x8x8(o[ni], pa, bf);
            }
        }
        __syncthreads();
    }

    float inv0 = 1.f / l0, inv1 = 1.f / l1;
    size_t row0 = (size_t)b * SEQ + i0 + r0;
    size_t row1 = (size_t)b * SEQ + i0 + r1;
#pragma unroll
    for (int ni = 0; ni < 8; ni++) {
        float2 v0 = { tf32_rna(o[ni][0] * inv0), tf32_rna(o[ni][1] * inv0) };
        float2 v1 = { tf32_rna(o[ni][2] * inv1), tf32_rna(o[ni][3] * inv1) };
        *(float2*)&g_attn[row0 * DIM + h * HDIM + ni * 8 + 2 * tg] = v0;
        *(float2*)&g_attn[row1 * DIM + h * HDIM + ni * 8 + 2 * tg] = v1;
    }
}

// ---------------------------------------------------------------------------
extern "C" void kernel_launch(void* const* d_in, const int* in_sizes, int n_in,
                              void* d_out, int out_size)
{
    const float* x    = (const float*)d_in[0];
    const int*   mask = (const int*)d_in[1];     // bool widened to int32 by harness
    const float* pos  = (const float*)d_in[2];
    const float* Wqk  = (const float*)d_in[3];
    const float* Wv   = (const float*)d_in[4];
    const float* Wout = (const float*)d_in[5];
    const float* bout = (const float*)d_in[6];
    float*       out  = (float*)d_out;

    cudaFuncSetAttribute(qkv_gemm_kernel, cudaFuncAttributeMaxDynamicSharedMemorySize,
                         GEMM_SMEM_BYTES);
    cudaFuncSetAttribute(out_gemm_kernel, cudaFuncAttributeMaxDynamicSharedMemorySize,
                         GEMM_SMEM_BYTES);
    cudaFuncSetAttribute(attn_kernel, cudaFuncAttributeMaxDynamicSharedMemorySize,
                         ATT_SMEM_BYTES);

    float* d_xr; float* d_wqkr; float* d_wvr; float* d_woutr;
    cudaGetSymbolAddress((void**)&d_xr,    g_xr);
    cudaGetSymbolAddress((void**)&d_wqkr,  g_wqkr);
    cudaGetSymbolAddress((void**)&d_wvr,   g_wvr);
    cudaGetSymbolAddress((void**)&d_woutr, g_woutr);

    {   // prep: round inputs to tf32 once
        int n4;
        n4 = MROWS * DIM / 4;
        round_kernel<<<(n4 + 255) / 256, 256>>>((const float4*)x, (float4*)d_xr, n4);
        n4 = 2 * DIM * DIM / 4;
        round_kernel<<<(n4 + 255) / 256, 256>>>((const float4*)Wqk, (float4*)d_wqkr, n4);
        n4 = DIM * DIM / 4;
        round_kernel<<<(n4 + 255) / 256, 256>>>((const float4*)Wv, (float4*)d_wvr, n4);
        round_kernel<<<(n4 + 255) / 256, 256>>>((const float4*)Wout, (float4*)d_woutr, n4);
    }
    {   // QKV projection: M=8192, N=3072
        dim3 grid(QKVN / 128, MROWS / 128);
        qkv_gemm_kernel<<<grid, 256, GEMM_SMEM_BYTES>>>(pos);
    }
    {   // Attention: 8 row-tiles x 128 (b,h) pairs
        dim3 grid(SEQ / 128, BATCH * HEADS);
        attn_kernel<<<grid, 256, ATT_SMEM_BYTES>>>(mask);
    }
    {   // Output projection: M=8192, N=1024
        dim3 grid(DIM / 128, MROWS / 128);
        out_gemm_kernel<<<grid, 256, GEMM_SMEM_BYTES>>>(bout, out);
    }
}

// round 10
// speedup vs baseline: 1.1668x; 1.0583x over previous
#include <cuda_runtime.h>
#include <cuda_bf16.h>
#include <cstddef>
#include <cstdint>

// Problem constants
#define BATCH 8
#define SEQ   1024
#define DIM   1024
#define HEADS 16
#define HDIM  64
#define MROWS (BATCH * SEQ)          // 8192
#define QKVN  (3 * DIM)              // 3072
#define SCALE 0.03125f               // DIM^-0.5 = 1/32
#define MASKV (-3.402823466e38f)
#define NEGINF (-__int_as_float(0x7f800000) * 1.0f)

// Scratch (static device globals: allocation-free rule)
__device__ float g_q[BATCH * HEADS * SEQ * HDIM];     // [b,h,n,d]  (tf32-rounded)
__device__ float g_k[BATCH * HEADS * SEQ * HDIM];
__device__ float g_v[BATCH * HEADS * SEQ * HDIM];
__device__ float g_attn[BATCH * SEQ * DIM];           // [b,n,h*d]  (tf32-rounded)
// tf32-rounded input copies (rounding hoisted out of GEMM hot loops)
__device__ float g_xr[MROWS * DIM];
__device__ float g_wqkr[2 * DIM * DIM];
__device__ float g_wvr[DIM * DIM];
__device__ float g_woutr[DIM * DIM];

// ---------------------------------------------------------------------------
// helpers
// ---------------------------------------------------------------------------
__device__ __forceinline__ float tf32_rna(float x) {
    uint32_t u;
    asm("cvt.rna.tf32.f32 %0, %1;" : "=r"(u) : "f"(x));
    return __uint_as_float(u);
}

__device__ __forceinline__ void mma_tf32_16x8x8(float* c, const float* a, const float* b) {
    asm volatile(
        "mma.sync.aligned.m16n8k8.row.col.f32.tf32.tf32.f32 "
        "{%0,%1,%2,%3}, {%4,%5,%6,%7}, {%8,%9}, {%0,%1,%2,%3};"
        : "+f"(c[0]), "+f"(c[1]), "+f"(c[2]), "+f"(c[3])
        : "r"(__float_as_uint(a[0])), "r"(__float_as_uint(a[1])),
          "r"(__float_as_uint(a[2])), "r"(__float_as_uint(a[3])),
          "r"(__float_as_uint(b[0])), "r"(__float_as_uint(b[1])));
}

__device__ __forceinline__ void mma_tf32_u(float* c, const uint32_t* a, const uint32_t* b) {
    asm volatile(
        "mma.sync.aligned.m16n8k8.row.col.f32.tf32.tf32.f32 "
        "{%0,%1,%2,%3}, {%4,%5,%6,%7}, {%8,%9}, {%0,%1,%2,%3};"
        : "+f"(c[0]), "+f"(c[1]), "+f"(c[2]), "+f"(c[3])
        : "r"(a[0]), "r"(a[1]), "r"(a[2]), "r"(a[3]),
          "r"(b[0]), "r"(b[1]));
}

__device__ __forceinline__ uint32_t smem_u32(const void* p) {
    return (uint32_t)__cvta_generic_to_shared(p);
}
__device__ __forceinline__ void ldsm_x4(uint32_t addr, uint32_t* r) {
    asm volatile("ldmatrix.sync.aligned.m8n8.x4.shared.b16 {%0,%1,%2,%3}, [%4];"
                 : "=r"(r[0]), "=r"(r[1]), "=r"(r[2]), "=r"(r[3]) : "r"(addr));
}
__device__ __forceinline__ void cp16(void* smem, const void* g) {
    asm volatile("cp.async.cg.shared.global [%0], [%1], 16;"
                 :: "r"(smem_u32(smem)), "l"(g));
}
__device__ __forceinline__ void cp_commit() {
    asm volatile("cp.async.commit_group;");
}

// ---------------------------------------------------------------------------
// Kernel 0: round fp32 -> tf32-valued fp32 (vectorized)
// ---------------------------------------------------------------------------
__global__ __launch_bounds__(256) void round_kernel(
    const float4* __restrict__ src, float4* __restrict__ dst, int n4)
{
    int i = blockIdx.x * 256 + threadIdx.x;
    if (i < n4) {
        float4 v = src[i];
        v.x = tf32_rna(v.x); v.y = tf32_rna(v.y);
        v.z = tf32_rna(v.z); v.w = tf32_rna(v.w);
        dst[i] = v;
    }
}

// ---------------------------------------------------------------------------
// tf32 GEMM core, cp.async 2-stage pipeline + ldmatrix fragment loads.
// 128x128 tile, K-tile 32, 256 threads, 8 warps (2M x 4N), warp tile 64x32.
// Fragment loads via ldmatrix.x4 (b32 tiles viewed as b16 m8n8): 16 LDSM for A
// + 8 for B per slab vs 96 scalar LDS. Inputs must already be tf32-valued.
// ---------------------------------------------------------------------------
#define TPAD 36   // row stride 144 B (16B-aligned; ldmatrix phases conflict-free)

struct GemmAcc { float acc[4][4][4]; };

__device__ __forceinline__ void gemm_core_async(
    const float* __restrict__ Abase, const float* __restrict__ B0,
    const float* __restrict__ B1, int bm, int bn, bool splitB,
    float* sm, GemmAcc& g)
{
    // layout: As[2][128][TPAD], Bs[2][128][TPAD]
    float (*As)[128][TPAD] = (float(*)[128][TPAD])sm;
    float (*Bs)[128][TPAD] = (float(*)[128][TPAD])(sm + 2 * 128 * TPAD);

    const int tid = threadIdx.x;
    const int lane = tid & 31;
    const int wid = tid >> 5;
    const int wm = (wid & 1) * 64;
    const int wn = (wid >> 1) * 32;

    // ldmatrix per-thread row/col assignment
    //  A x4 tiles (mi,ks): T0 rows wm+16mi+0..7 col ks | T1 rows +8 | T2 col ks+4 | T3 both
    const int rowA = wm + ((lane >> 3) & 1) * 8 + (lane & 7);
    const int colA = (lane >> 4) * 4;
    //  B x4 tiles (nipair,ks): T0 (n0..n0+7, ks) T1 (.., ks+4) T2 (n0+8.., ks) T3 (.., ks+4)
    const int rowB = wn + ((lane >> 4) & 1) * 8 + (lane & 7);
    const int colB = ((lane >> 3) & 1) * 4;

    const uint32_t aBase = smem_u32(&As[0][0][0]) + (uint32_t)((rowA * TPAD + colA) << 2);
    const uint32_t bBase = smem_u32(&Bs[0][0][0]) + (uint32_t)((rowB * TPAD + colB) << 2);
    const uint32_t STAGE = 128 * TPAD * 4;

#pragma unroll
    for (int mi = 0; mi < 4; mi++)
#pragma unroll
        for (int ni = 0; ni < 4; ni++)
#pragma unroll
            for (int r = 0; r < 4; r++) g.acc[mi][ni][r] = 0.f;

    auto load_tiles = [&](int st, int k0) {
#pragma unroll
        for (int i = tid; i < 128 * 8; i += 256) {
            int row = i >> 3, c4 = (i & 7) * 4;
            cp16(&As[st][row][c4], &Abase[(size_t)(bm + row) * DIM + k0 + c4]);
        }
#pragma unroll
        for (int i = tid; i < 128 * 8; i += 256) {
            int row = i >> 3, c4 = (i & 7) * 4;
            int gn = bn + row;
            const float* Brow = (splitB && gn >= 2 * DIM)
                                ? B1 + (size_t)(gn - 2 * DIM) * DIM
                                : B0 + (size_t)gn * DIM;
            cp16(&Bs[st][row][c4], &Brow[k0 + c4]);
        }
    };

    load_tiles(0, 0);
    cp_commit();

    const int NT = DIM / 32;  // 32
    for (int it = 0; it < NT; it++) {
        int cur = it & 1;
        if (it + 1 < NT) {
            load_tiles(cur ^ 1, (it + 1) * 32);
            cp_commit();
            asm volatile("cp.async.wait_group 1;");
        } else {
            asm volatile("cp.async.wait_group 0;");
        }
        __syncthreads();

        const uint32_t aCur = aBase + cur * STAGE;
        const uint32_t bCur = bBase + cur * STAGE;
#pragma unroll
        for (int ks = 0; ks < 32; ks += 8) {
            uint32_t a[4][4];
#pragma unroll
            for (int mi = 0; mi < 4; mi++)
                ldsm_x4(aCur + (uint32_t)((mi * 16 * TPAD + ks) << 2), a[mi]);
            uint32_t b[2][4];
#pragma unroll
            for (int np = 0; np < 2; np++)
                ldsm_x4(bCur + (uint32_t)((np * 16 * TPAD + ks) << 2), b[np]);
#pragma unroll
            for (int mi = 0; mi < 4; mi++)
#pragma unroll
                for (int ni = 0; ni < 4; ni++)
                    mma_tf32_u(g.acc[mi][ni], a[mi], &b[ni >> 1][(ni & 1) * 2]);
        }
        __syncthreads();
    }
}

#define GEMM_SMEM_BYTES (4 * 128 * TPAD * 4)   // 73728

// ---------------------------------------------------------------------------
// Kernel 1: fused QKV projection. Epilogue adds pos (fp32), rounds result to
// tf32 (feeds attention MMAs), scatters to [b,h,n,d].
// ---------------------------------------------------------------------------
__global__ __launch_bounds__(256) void qkv_gemm_kernel(const float* __restrict__ pos)
{
    extern __shared__ float sm[];
    const int bm = blockIdx.y * 128;
    const int bn = blockIdx.x * 128;
    const int lane = threadIdx.x & 31;
    const int wid = threadIdx.x >> 5;
    const int gid = lane >> 2, tg = lane & 3;
    const int wm = (wid & 1) * 64;
    const int wn = (wid >> 1) * 32;

    GemmAcc g;
    gemm_core_async(g_xr, g_wqkr, g_wvr, bm, bn, true, sm, g);

#pragma unroll
    for (int mi = 0; mi < 4; mi++) {
#pragma unroll
        for (int ni = 0; ni < 4; ni++) {
#pragma unroll
            for (int r = 0; r < 4; r++) {
                int m = bm + wm + mi * 16 + gid + ((r >= 2) ? 8 : 0);
                int gn = bn + wn + ni * 8 + 2 * tg + (r & 1);
                int b = m >> 10, row = m & 1023;
                float val = g.acc[mi][ni][r];
                if (gn < DIM) {
                    int c = gn, h = c >> 6, d = c & 63;
                    val = tf32_rna(val + pos[(size_t)m * DIM + c]);
                    g_q[(((size_t)b * HEADS + h) * SEQ + row) * HDIM + d] = val;
                } else if (gn < 2 * DIM) {
                    int c = gn - DIM, h = c >> 6, d = c & 63;
                    val = tf32_rna(val + pos[(size_t)m * DIM + c]);
                    g_k[(((size_t)b * HEADS + h) * SEQ + row) * HDIM + d] = val;
                } else {
                    int c = gn - 2 * DIM, h = c >> 6, d = c & 63;
                    g_v[(((size_t)b * HEADS + h) * SEQ + row) * HDIM + d] = tf32_rna(val);
                }
            }
        }
    }
}

// ---------------------------------------------------------------------------
// Kernel 3: output projection. out = g_attn @ W_out^T + b_out (fp32 epilogue)
// ---------------------------------------------------------------------------
__global__ __launch_bounds__(256) void out_gemm_kernel(
    const float* __restrict__ bout, float* __restrict__ out)
{
    extern __shared__ float sm[];
    const int bm = blockIdx.y * 128;
    const int bn = blockIdx.x * 128;
    const int lane = threadIdx.x & 31;
    const int wid = threadIdx.x >> 5;
    const int gid = lane >> 2, tg = lane & 3;
    const int wm = (wid & 1) * 64;
    const int wn = (wid >> 1) * 32;

    GemmAcc g;
    gemm_core_async(g_attn, g_woutr, nullptr, bm, bn, false, sm, g);

#pragma unroll
    for (int mi = 0; mi < 4; mi++) {
#pragma unroll
        for (int ni = 0; ni < 4; ni++) {
#pragma unroll
            for (int r = 0; r < 4; r++) {
                int m = bm + wm + mi * 16 + gid + ((r >= 2) ? 8 : 0);
                int gn = bn + wn + ni * 8 + 2 * tg + (r & 1);
                out[(size_t)m * DIM + gn] = g.acc[mi][ni][r] + bout[gn];
            }
        }
    }
}

// ---------------------------------------------------------------------------
// Kernel 2: tensor-core flash attention with cp.async double-buffered K/V.
// Identical to the R5 version (known-good).
// ---------------------------------------------------------------------------
#define AKPAD 68
#define AVPAD 72
#define ATT_SMEM_FLOATS (128 * AKPAD + 2 * 64 * AKPAD + 2 * 64 * AVPAD + 2 * 64)
#define ATT_SMEM_BYTES  (ATT_SMEM_FLOATS * 4)   // 107008

__global__ __launch_bounds__(256) void attn_kernel(const int* __restrict__ mask)
{
    extern __shared__ float sm[];
    float (*QP)[AKPAD]  = (float(*)[AKPAD])sm;                       // Q tile, later P
    float (*KsB)[AKPAD] = (float(*)[AKPAD])(sm + 128 * AKPAD);      // [2*64][AKPAD]
    float (*VsB)[AVPAD] = (float(*)[AVPAD])(sm + 128 * AKPAD + 2 * 64 * AKPAD);
    float* kmB = sm + 128 * AKPAD + 2 * 64 * AKPAD + 2 * 64 * AVPAD; // [2][64]

    const int bh = blockIdx.y;
    const int b = bh >> 4, h = bh & 15;
    const int i0 = blockIdx.x * 128;
    const int tid = threadIdx.x;
    const int lane = tid & 31, wid = tid >> 5;
    const int gid = lane >> 2, tg = lane & 3;
    const int r0 = wid * 16 + gid;
    const int r1 = r0 + 8;

    const float* qb = g_q + ((size_t)bh * SEQ + i0) * HDIM;
    const float* kb = g_k + (size_t)bh * SEQ * HDIM;
    const float* vb = g_v + (size_t)bh * SEQ * HDIM;

    auto load_kv = [&](int st, int j0) {
        float (*K)[AKPAD] = KsB + st * 64;
        float (*V)[AVPAD] = VsB + st * 64;
#pragma unroll
        for (int i = tid; i < 64 * 16; i += 256) {
            int row = i >> 4, c4 = (i & 15) * 4;
            cp16(&K[row][c4], &kb[(size_t)(j0 + row) * HDIM + c4]);
            cp16(&V[row][c4], &vb[(size_t)(j0 + row) * HDIM + c4]);
        }
    };
    auto load_km = [&](int st, int j0) {
        if (tid < 64) {
            int gj = j0 + tid;
            kmB[st * 64 + tid] =
                (gj == 0) ? 1.f : (mask[(size_t)b * (SEQ - 1) + gj - 1] ? 1.f : 0.f);
        }
    };

    load_kv(0, 0);
    cp_commit();
    load_km(0, 0);

    for (int i = tid; i < 128 * 16; i += 256) {
        int row = i >> 4, c4 = (i & 15) * 4;
        *(float4*)&QP[row][c4] = *(const float4*)&qb[(size_t)row * HDIM + c4];
    }
    __syncthreads();

    float qa[8][4];
#pragma unroll
    for (int ks = 0; ks < 8; ks++) {
        qa[ks][0] = QP[r0][ks * 8 + tg];
        qa[ks][1] = QP[r1][ks * 8 + tg];
        qa[ks][2] = QP[r0][ks * 8 + tg + 4];
        qa[ks][3] = QP[r1][ks * 8 + tg + 4];
    }
    const int gi0 = i0 + r0, gi1 = i0 + r1;
    const bool qok0 = (gi0 == 0) || (mask[(size_t)b * (SEQ - 1) + gi0 - 1] != 0);
    const bool qok1 = (gi1 == 0) || (mask[(size_t)b * (SEQ - 1) + gi1 - 1] != 0);

    float m0 = NEGINF, m1 = NEGINF, l0 = 0.f, l1 = 0.f;
    float o[8][4] = {};

    const int NT = SEQ / 64;   // 16
    for (int it = 0; it < NT; it++) {
        const int cur = it & 1;
        if (it + 1 < NT) {
            load_kv(cur ^ 1, (it + 1) * 64);
            cp_commit();
            load_km(cur ^ 1, (it + 1) * 64);
            asm volatile("cp.async.wait_group 1;");
        } else {
            asm volatile("cp.async.wait_group 0;");
        }
        __syncthreads();

        float (*Ks)[AKPAD] = KsB + cur * 64;
        float (*Vs)[AVPAD] = VsB + cur * 64;
        const float* km = kmB + cur * 64;

        float s[8][4] = {};
#pragma unroll
        for (int ks = 0; ks < 8; ks++) {
#pragma unroll
            for (int ni = 0; ni < 8; ni++) {
                float bf[2] = { Ks[ni * 8 + gid][ks * 8 + tg],
                                Ks[ni * 8 + gid][ks * 8 + tg + 4] };
                mma_tf32_16x8x8(s[ni], qa[ks], bf);
            }
        }

        float rmax0 = NEGINF, rmax1 = NEGINF;
#pragma unroll
        for (int ni = 0; ni < 8; ni++) {
            bool k0ok = km[ni * 8 + 2 * tg] != 0.f;
            bool k1ok = km[ni * 8 + 2 * tg + 1] != 0.f;
            s[ni][0] = (qok0 && k0ok) ? s[ni][0] * SCALE : MASKV;
            s[ni][1] = (qok0 && k1ok) ? s[ni][1] * SCALE : MASKV;
            s[ni][2] = (qok1 && k0ok) ? s[ni][2] * SCALE : MASKV;
            s[ni][3] = (qok1 && k1ok) ? s[ni][3] * SCALE : MASKV;
            rmax0 = fmaxf(rmax0, fmaxf(s[ni][0], s[ni][1]));
            rmax1 = fmaxf(rmax1, fmaxf(s[ni][2], s[ni][3]));
        }
        rmax0 = fmaxf(rmax0, __shfl_xor_sync(0xffffffffu, rmax0, 1));
        rmax0 = fmaxf(rmax0, __shfl_xor_sync(0xffffffffu, rmax0, 2));
        rmax1 = fmaxf(rmax1, __shfl_xor_sync(0xffffffffu, rmax1, 1));
        rmax1 = fmaxf(rmax1, __shfl_xor_sync(0xffffffffu, rmax1, 2));

        float nm0 = fmaxf(m0, rmax0), nm1 = fmaxf(m1, rmax1);
        float fac0 = __expf(m0 - nm0), fac1 = __expf(m1 - nm1);
        m0 = nm0; m1 = nm1;

        float sum0 = 0.f, sum1 = 0.f;
#pragma unroll
        for (int ni = 0; ni < 8; ni++) {
            float p0 = tf32_rna(__expf(s[ni][0] - m0));
            float p1 = tf32_rna(__expf(s[ni][1] - m0));
            float p2 = tf32_rna(__expf(s[ni][2] - m1));
            float p3 = tf32_rna(__expf(s[ni][3] - m1));
            sum0 += p0 + p1; sum1 += p2 + p3;
            QP[r0][ni * 8 + 2 * tg]     = p0;
            QP[r0][ni * 8 + 2 * tg + 1] = p1;
            QP[r1][ni * 8 + 2 * tg]     = p2;
            QP[r1][ni * 8 + 2 * tg + 1] = p3;
        }
        sum0 += __shfl_xor_sync(0xffffffffu, sum0, 1);
        sum0 += __shfl_xor_sync(0xffffffffu, sum0, 2);
        sum1 += __shfl_xor_sync(0xffffffffu, sum1, 1);
        sum1 += __shfl_xor_sync(0xffffffffu, sum1, 2);
        l0 = l0 * fac0 + sum0;
        l1 = l1 * fac1 + sum1;

#pragma unroll
        for (int ni = 0; ni < 8; ni++) {
            o[ni][0] *= fac0; o[ni][1] *= fac0;
            o[ni][2] *= fac1; o[ni][3] *= fac1;
        }
        __syncwarp();

#pragma unroll
        for (int ks = 0; ks < 8; ks++) {
            float pa[4] = { QP[r0][ks * 8 + tg], QP[r1][ks * 8 + tg],
                            QP[r0][ks * 8 + tg + 4], QP[r1][ks * 8 + tg + 4] };
#pragma unroll
            for (int ni = 0; ni < 8; ni++) {
                float bf[2] = { Vs[ks * 8 + tg][ni * 8 + gid],
                                Vs[ks * 8 + tg + 4][ni * 8 + gid] };
                mma_tf32_16x8x8(o[ni], pa, bf);
            }
        }
        __syncthreads();
    }

    float inv0 = 1.f / l0, inv1 = 1.f / l1;
    size_t row0 = (size_t)b * SEQ + i0 + r0;
    size_t row1 = (size_t)b * SEQ + i0 + r1;
#pragma unroll
    for (int ni = 0; ni < 8; ni++) {
        float2 v0 = { tf32_rna(o[ni][0] * inv0), tf32_rna(o[ni][1] * inv0) };
        float2 v1 = { tf32_rna(o[ni][2] * inv1), tf32_rna(o[ni][3] * inv1) };
        *(float2*)&g_attn[row0 * DIM + h * HDIM + ni * 8 + 2 * tg] = v0;
        *(float2*)&g_attn[row1 * DIM + h * HDIM + ni * 8 + 2 * tg] = v1;
    }
}

// ---------------------------------------------------------------------------
extern "C" void kernel_launch(void* const* d_in, const int* in_sizes, int n_in,
                              void* d_out, int out_size)
{
    const float* x    = (const float*)d_in[0];
    const int*   mask = (const int*)d_in[1];     // bool widened to int32 by harness
    const float* pos  = (const float*)d_in[2];
    const float* Wqk  = (const float*)d_in[3];
    const float* Wv   = (const float*)d_in[4];
    const float* Wout = (const float*)d_in[5];
    const float* bout = (const float*)d_in[6];
    float*       out  = (float*)d_out;

    cudaFuncSetAttribute(qkv_gemm_kernel, cudaFuncAttributeMaxDynamicSharedMemorySize,
                         GEMM_SMEM_BYTES);
    cudaFuncSetAttribute(out_gemm_kernel, cudaFuncAttributeMaxDynamicSharedMemorySize,
                         GEMM_SMEM_BYTES);
    cudaFuncSetAttribute(attn_kernel, cudaFuncAttributeMaxDynamicSharedMemorySize,
                         ATT_SMEM_BYTES);

    float* d_xr; float* d_wqkr; float* d_wvr; float* d_woutr;
    cudaGetSymbolAddress((void**)&d_xr,    g_xr);
    cudaGetSymbolAddress((void**)&d_wqkr,  g_wqkr);
    cudaGetSymbolAddress((void**)&d_wvr,   g_wvr);
    cudaGetSymbolAddress((void**)&d_woutr, g_woutr);

    {   // prep: round inputs to tf32 once
        int n4;
        n4 = MROWS * DIM / 4;
        round_kernel<<<(n4 + 255) / 256, 256>>>((const float4*)x, (float4*)d_xr, n4);
        n4 = 2 * DIM * DIM / 4;
        round_kernel<<<(n4 + 255) / 256, 256>>>((const float4*)Wqk, (float4*)d_wqkr, n4);
        n4 = DIM * DIM / 4;
        round_kernel<<<(n4 + 255) / 256, 256>>>((const float4*)Wv, (float4*)d_wvr, n4);
        round_kernel<<<(n4 + 255) / 256, 256>>>((const float4*)Wout, (float4*)d_woutr, n4);
    }
    {   // QKV projection: M=8192, N=3072
        dim3 grid(QKVN / 128, MROWS / 128);
        qkv_gemm_kernel<<<grid, 256, GEMM_SMEM_BYTES>>>(pos);
    }
    {   // Attention: 8 row-tiles x 128 (b,h) pairs
        dim3 grid(SEQ / 128, BATCH * HEADS);
        attn_kernel<<<grid, 256, ATT_SMEM_BYTES>>>(mask);
    }
    {   // Output projection: M=8192, N=1024
        dim3 grid(DIM / 128, MROWS / 128);
        out_gemm_kernel<<<grid, 256, GEMM_SMEM_BYTES>>>(bout, out);
    }
}

// round 11
// speedup vs baseline: 1.1892x; 1.0192x over previous
#include <cuda_runtime.h>
#include <cuda_bf16.h>
#include <cstddef>
#include <cstdint>

// Problem constants
#define BATCH 8
#define SEQ   1024
#define DIM   1024
#define HEADS 16
#define HDIM  64
#define MROWS (BATCH * SEQ)          // 8192
#define QKVN  (3 * DIM)              // 3072
#define SCALE 0.03125f               // DIM^-0.5 = 1/32
#define MASKV (-3.402823466e38f)
#define NEGINF (-__int_as_float(0x7f800000) * 1.0f)

// Scratch (static device globals: allocation-free rule)
__device__ float g_q[BATCH * HEADS * SEQ * HDIM];     // [b,h,n,d]  (tf32-rounded)
__device__ float g_k[BATCH * HEADS * SEQ * HDIM];
__device__ float g_v[BATCH * HEADS * SEQ * HDIM];
__device__ float g_attn[BATCH * SEQ * DIM];           // [b,n,h*d]  (tf32-rounded)
// tf32-rounded input copies (rounding hoisted out of GEMM hot loops)
__device__ float g_xr[MROWS * DIM];
__device__ float g_wqkr[2 * DIM * DIM];
__device__ float g_wvr[DIM * DIM];
__device__ float g_woutr[DIM * DIM];

// ---------------------------------------------------------------------------
// helpers
// ---------------------------------------------------------------------------
__device__ __forceinline__ float tf32_rna(float x) {
    uint32_t u;
    asm("cvt.rna.tf32.f32 %0, %1;" : "=r"(u) : "f"(x));
    return __uint_as_float(u);
}

__device__ __forceinline__ void mma_tf32_16x8x8(float* c, const float* a, const float* b) {
    asm volatile(
        "mma.sync.aligned.m16n8k8.row.col.f32.tf32.tf32.f32 "
        "{%0,%1,%2,%3}, {%4,%5,%6,%7}, {%8,%9}, {%0,%1,%2,%3};"
        : "+f"(c[0]), "+f"(c[1]), "+f"(c[2]), "+f"(c[3])
        : "r"(__float_as_uint(a[0])), "r"(__float_as_uint(a[1])),
          "r"(__float_as_uint(a[2])), "r"(__float_as_uint(a[3])),
          "r"(__float_as_uint(b[0])), "r"(__float_as_uint(b[1])));
}

__device__ __forceinline__ void mma_tf32_u(float* c, const uint32_t* a, const uint32_t* b) {
    asm volatile(
        "mma.sync.aligned.m16n8k8.row.col.f32.tf32.tf32.f32 "
        "{%0,%1,%2,%3}, {%4,%5,%6,%7}, {%8,%9}, {%0,%1,%2,%3};"
        : "+f"(c[0]), "+f"(c[1]), "+f"(c[2]), "+f"(c[3])
        : "r"(a[0]), "r"(a[1]), "r"(a[2]), "r"(a[3]),
          "r"(b[0]), "r"(b[1]));
}

__device__ __forceinline__ void mma_tf32_au(float* c, const uint32_t* a, const float* b) {
    asm volatile(
        "mma.sync.aligned.m16n8k8.row.col.f32.tf32.tf32.f32 "
        "{%0,%1,%2,%3}, {%4,%5,%6,%7}, {%8,%9}, {%0,%1,%2,%3};"
        : "+f"(c[0]), "+f"(c[1]), "+f"(c[2]), "+f"(c[3])
        : "r"(a[0]), "r"(a[1]), "r"(a[2]), "r"(a[3]),
          "r"(__float_as_uint(b[0])), "r"(__float_as_uint(b[1])));
}

__device__ __forceinline__ uint32_t smem_u32(const void* p) {
    return (uint32_t)__cvta_generic_to_shared(p);
}
__device__ __forceinline__ void ldsm_x4(uint32_t addr, uint32_t* r) {
    asm volatile("ldmatrix.sync.aligned.m8n8.x4.shared.b16 {%0,%1,%2,%3}, [%4];"
                 : "=r"(r[0]), "=r"(r[1]), "=r"(r[2]), "=r"(r[3]) : "r"(addr));
}
__device__ __forceinline__ void cp16(void* smem, const void* g) {
    asm volatile("cp.async.cg.shared.global [%0], [%1], 16;"
                 :: "r"(smem_u32(smem)), "l"(g));
}
__device__ __forceinline__ void cp_commit() {
    asm volatile("cp.async.commit_group;");
}

// ---------------------------------------------------------------------------
// Kernel 0: round fp32 -> tf32-valued fp32 (vectorized)
// ---------------------------------------------------------------------------
__global__ __launch_bounds__(256) void round_kernel(
    const float4* __restrict__ src, float4* __restrict__ dst, int n4)
{
    int i = blockIdx.x * 256 + threadIdx.x;
    if (i < n4) {
        float4 v = src[i];
        v.x = tf32_rna(v.x); v.y = tf32_rna(v.y);
        v.z = tf32_rna(v.z); v.w = tf32_rna(v.w);
        dst[i] = v;
    }
}

// ---------------------------------------------------------------------------
// tf32 GEMM core, cp.async 2-stage pipeline + ldmatrix fragment loads.
// (Unchanged from R10: 762us known-good.)
// ---------------------------------------------------------------------------
#define TPAD 36

struct GemmAcc { float acc[4][4][4]; };

__device__ __forceinline__ void gemm_core_async(
    const float* __restrict__ Abase, const float* __restrict__ B0,
    const float* __restrict__ B1, int bm, int bn, bool splitB,
    float* sm, GemmAcc& g)
{
    float (*As)[128][TPAD] = (float(*)[128][TPAD])sm;
    float (*Bs)[128][TPAD] = (float(*)[128][TPAD])(sm + 2 * 128 * TPAD);

    const int tid = threadIdx.x;
    const int lane = tid & 31;
    const int wid = tid >> 5;
    const int wm = (wid & 1) * 64;
    const int wn = (wid >> 1) * 32;

    const int rowA = wm + ((lane >> 3) & 1) * 8 + (lane & 7);
    const int colA = (lane >> 4) * 4;
    const int rowB = wn + ((lane >> 4) & 1) * 8 + (lane & 7);
    const int colB = ((lane >> 3) & 1) * 4;

    const uint32_t aBase = smem_u32(&As[0][0][0]) + (uint32_t)((rowA * TPAD + colA) << 2);
    const uint32_t bBase = smem_u32(&Bs[0][0][0]) + (uint32_t)((rowB * TPAD + colB) << 2);
    const uint32_t STAGE = 128 * TPAD * 4;

#pragma unroll
    for (int mi = 0; mi < 4; mi++)
#pragma unroll
        for (int ni = 0; ni < 4; ni++)
#pragma unroll
            for (int r = 0; r < 4; r++) g.acc[mi][ni][r] = 0.f;

    auto load_tiles = [&](int st, int k0) {
#pragma unroll
        for (int i = tid; i < 128 * 8; i += 256) {
            int row = i >> 3, c4 = (i & 7) * 4;
            cp16(&As[st][row][c4], &Abase[(size_t)(bm + row) * DIM + k0 + c4]);
        }
#pragma unroll
        for (int i = tid; i < 128 * 8; i += 256) {
            int row = i >> 3, c4 = (i & 7) * 4;
            int gn = bn + row;
            const float* Brow = (splitB && gn >= 2 * DIM)
                                ? B1 + (size_t)(gn - 2 * DIM) * DIM
                                : B0 + (size_t)gn * DIM;
            cp16(&Bs[st][row][c4], &Brow[k0 + c4]);
        }
    };

    load_tiles(0, 0);
    cp_commit();

    const int NT = DIM / 32;
    for (int it = 0; it < NT; it++) {
        int cur = it & 1;
        if (it + 1 < NT) {
            load_tiles(cur ^ 1, (it + 1) * 32);
            cp_commit();
            asm volatile("cp.async.wait_group 1;");
        } else {
            asm volatile("cp.async.wait_group 0;");
        }
        __syncthreads();

        const uint32_t aCur = aBase + cur * STAGE;
        const uint32_t bCur = bBase + cur * STAGE;
#pragma unroll
        for (int ks = 0; ks < 32; ks += 8) {
            uint32_t a[4][4];
#pragma unroll
            for (int mi = 0; mi < 4; mi++)
                ldsm_x4(aCur + (uint32_t)((mi * 16 * TPAD + ks) << 2), a[mi]);
            uint32_t b[2][4];
#pragma unroll
            for (int np = 0; np < 2; np++)
                ldsm_x4(bCur + (uint32_t)((np * 16 * TPAD + ks) << 2), b[np]);
#pragma unroll
            for (int mi = 0; mi < 4; mi++)
#pragma unroll
                for (int ni = 0; ni < 4; ni++)
                    mma_tf32_u(g.acc[mi][ni], a[mi], &b[ni >> 1][(ni & 1) * 2]);
        }
        __syncthreads();
    }
}

#define GEMM_SMEM_BYTES (4 * 128 * TPAD * 4)   // 73728

// ---------------------------------------------------------------------------
// Kernel 1: fused QKV projection.
// ---------------------------------------------------------------------------
__global__ __launch_bounds__(256) void qkv_gemm_kernel(const float* __restrict__ pos)
{
    extern __shared__ float sm[];
    const int bm = blockIdx.y * 128;
    const int bn = blockIdx.x * 128;
    const int lane = threadIdx.x & 31;
    const int wid = threadIdx.x >> 5;
    const int gid = lane >> 2, tg = lane & 3;
    const int wm = (wid & 1) * 64;
    const int wn = (wid >> 1) * 32;

    GemmAcc g;
    gemm_core_async(g_xr, g_wqkr, g_wvr, bm, bn, true, sm, g);

#pragma unroll
    for (int mi = 0; mi < 4; mi++) {
#pragma unroll
        for (int ni = 0; ni < 4; ni++) {
#pragma unroll
            for (int r = 0; r < 4; r++) {
                int m = bm + wm + mi * 16 + gid + ((r >= 2) ? 8 : 0);
                int gn = bn + wn + ni * 8 + 2 * tg + (r & 1);
                int b = m >> 10, row = m & 1023;
                float val = g.acc[mi][ni][r];
                if (gn < DIM) {
                    int c = gn, h = c >> 6, d = c & 63;
                    val = tf32_rna(val + pos[(size_t)m * DIM + c]);
                    g_q[(((size_t)b * HEADS + h) * SEQ + row) * HDIM + d] = val;
                } else if (gn < 2 * DIM) {
                    int c = gn - DIM, h = c >> 6, d = c & 63;
                    val = tf32_rna(val + pos[(size_t)m * DIM + c]);
                    g_k[(((size_t)b * HEADS + h) * SEQ + row) * HDIM + d] = val;
                } else {
                    int c = gn - 2 * DIM, h = c >> 6, d = c & 63;
                    g_v[(((size_t)b * HEADS + h) * SEQ + row) * HDIM + d] = tf32_rna(val);
                }
            }
        }
    }
}

// ---------------------------------------------------------------------------
// Kernel 3: output projection.
// ---------------------------------------------------------------------------
__global__ __launch_bounds__(256) void out_gemm_kernel(
    const float* __restrict__ bout, float* __restrict__ out)
{
    extern __shared__ float sm[];
    const int bm = blockIdx.y * 128;
    const int bn = blockIdx.x * 128;
    const int lane = threadIdx.x & 31;
    const int wid = threadIdx.x >> 5;
    const int gid = lane >> 2, tg = lane & 3;
    const int wm = (wid & 1) * 64;
    const int wn = (wid >> 1) * 32;

    GemmAcc g;
    gemm_core_async(g_attn, g_woutr, nullptr, bm, bn, false, sm, g);

#pragma unroll
    for (int mi = 0; mi < 4; mi++) {
#pragma unroll
        for (int ni = 0; ni < 4; ni++) {
#pragma unroll
            for (int r = 0; r < 4; r++) {
                int m = bm + wm + mi * 16 + gid + ((r >= 2) ? 8 : 0);
                int gn = bn + wn + ni * 8 + 2 * tg + (r & 1);
                out[(size_t)m * DIM + gn] = g.acc[mi][ni][r] + bout[gn];
            }
        }
    }
}

// ---------------------------------------------------------------------------
// Kernel 2: tensor-core flash attention. R10 math, but K fragments (S-loop)
// and P fragments (PV-loop) now via ldmatrix.x4 using the GEMM-proven
// mappings. V fragments stay scalar (stored [key][d]; AVPAD keeps them
// conflict-free).
// ---------------------------------------------------------------------------
#define AKPAD 68
#define AVPAD 72
#define ATT_SMEM_FLOATS (128 * AKPAD + 2 * 64 * AKPAD + 2 * 64 * AVPAD + 2 * 64)
#define ATT_SMEM_BYTES  (ATT_SMEM_FLOATS * 4)   // 107008

__global__ __launch_bounds__(256) void attn_kernel(const int* __restrict__ mask)
{
    extern __shared__ float sm[];
    float (*QP)[AKPAD]  = (float(*)[AKPAD])sm;                       // Q tile, later P
    float (*KsB)[AKPAD] = (float(*)[AKPAD])(sm + 128 * AKPAD);      // [2*64][AKPAD]
    float (*VsB)[AVPAD] = (float(*)[AVPAD])(sm + 128 * AKPAD + 2 * 64 * AKPAD);
    float* kmB = sm + 128 * AKPAD + 2 * 64 * AKPAD + 2 * 64 * AVPAD; // [2][64]

    const int bh = blockIdx.y;
    const int b = bh >> 4, h = bh & 15;
    const int i0 = blockIdx.x * 128;
    const int tid = threadIdx.x;
    const int lane = tid & 31, wid = tid >> 5;
    const int gid = lane >> 2, tg = lane & 3;
    const int r0 = wid * 16 + gid;
    const int r1 = r0 + 8;

    // ldmatrix lane mappings (identical math to the GEMM core)
    const int rowAf = wid * 16 + ((lane >> 3) & 1) * 8 + (lane & 7);   // P (A-frag)
    const int colAf = (lane >> 4) * 4;
    const int rowBf = ((lane >> 4) & 1) * 8 + (lane & 7);              // K (B-frag)
    const int colBf = ((lane >> 3) & 1) * 4;
    const uint32_t pBase = smem_u32(&QP[0][0]) + (uint32_t)((rowAf * AKPAD + colAf) << 2);
    const uint32_t kBase = smem_u32(&KsB[0][0]) + (uint32_t)((rowBf * AKPAD + colBf) << 2);
    const uint32_t KSTAGE = 64 * AKPAD * 4;

    const float* qb = g_q + ((size_t)bh * SEQ + i0) * HDIM;
    const float* kb = g_k + (size_t)bh * SEQ * HDIM;
    const float* vb = g_v + (size_t)bh * SEQ * HDIM;

    auto load_kv = [&](int st, int j0) {
        float (*K)[AKPAD] = KsB + st * 64;
        float (*V)[AVPAD] = VsB + st * 64;
#pragma unroll
        for (int i = tid; i < 64 * 16; i += 256) {
            int row = i >> 4, c4 = (i & 15) * 4;
            cp16(&K[row][c4], &kb[(size_t)(j0 + row) * HDIM + c4]);
            cp16(&V[row][c4], &vb[(size_t)(j0 + row) * HDIM + c4]);
        }
    };
    auto load_km = [&](int st, int j0) {
        if (tid < 64) {
            int gj = j0 + tid;
            kmB[st * 64 + tid] =
                (gj == 0) ? 1.f : (mask[(size_t)b * (SEQ - 1) + gj - 1] ? 1.f : 0.f);
        }
    };

    load_kv(0, 0);
    cp_commit();
    load_km(0, 0);

    for (int i = tid; i < 128 * 16; i += 256) {
        int row = i >> 4, c4 = (i & 15) * 4;
        *(float4*)&QP[row][c4] = *(const float4*)&qb[(size_t)row * HDIM + c4];
    }
    __syncthreads();

    float qa[8][4];
#pragma unroll
    for (int ks = 0; ks < 8; ks++) {
        qa[ks][0] = QP[r0][ks * 8 + tg];
        qa[ks][1] = QP[r1][ks * 8 + tg];
        qa[ks][2] = QP[r0][ks * 8 + tg + 4];
        qa[ks][3] = QP[r1][ks * 8 + tg + 4];
    }
    const int gi0 = i0 + r0, gi1 = i0 + r1;
    const bool qok0 = (gi0 == 0) || (mask[(size_t)b * (SEQ - 1) + gi0 - 1] != 0);
    const bool qok1 = (gi1 == 0) || (mask[(size_t)b * (SEQ - 1) + gi1 - 1] != 0);

    float m0 = NEGINF, m1 = NEGINF, l0 = 0.f, l1 = 0.f;
    float o[8][4] = {};

    const int NT = SEQ / 64;   // 16
    for (int it = 0; it < NT; it++) {
        const int cur = it & 1;
        if (it + 1 < NT) {
            load_kv(cur ^ 1, (it + 1) * 64);
            cp_commit();
            load_km(cur ^ 1, (it + 1) * 64);
            asm volatile("cp.async.wait_group 1;");
        } else {
            asm volatile("cp.async.wait_group 0;");
        }
        __syncthreads();

        float (*Vs)[AVPAD] = VsB + cur * 64;
        const float* km = kmB + cur * 64;
        const uint32_t kCur = kBase + cur * KSTAGE;

        // S = Q K^T : K fragments via ldmatrix (4 x4 per ks cover 8 ni tiles)
        float s[8][4] = {};
#pragma unroll
        for (int ks = 0; ks < 8; ks++) {
            uint32_t kf[4][4];
#pragma unroll
            for (int np = 0; np < 4; np++)
                ldsm_x4(kCur + (uint32_t)((np * 16 * AKPAD + ks * 8) << 2), kf[np]);
#pragma unroll
            for (int ni = 0; ni < 8; ni++)
                mma_tf32_au(s[ni], (const uint32_t*)&qa[ks][0],
                            (const float*)&kf[ni >> 1][(ni & 1) * 2]);
        }

        float rmax0 = NEGINF, rmax1 = NEGINF;
#pragma unroll
        for (int ni = 0; ni < 8; ni++) {
            bool k0ok = km[ni * 8 + 2 * tg] != 0.f;
            bool k1ok = km[ni * 8 + 2 * tg + 1] != 0.f;
            s[ni][0] = (qok0 && k0ok) ? s[ni][0] * SCALE : MASKV;
            s[ni][1] = (qok0 && k1ok) ? s[ni][1] * SCALE : MASKV;
            s[ni][2] = (qok1 && k0ok) ? s[ni][2] * SCALE : MASKV;
            s[ni][3] = (qok1 && k1ok) ? s[ni][3] * SCALE : MASKV;
            rmax0 = fmaxf(rmax0, fmaxf(s[ni][0], s[ni][1]));
            rmax1 = fmaxf(rmax1, fmaxf(s[ni][2], s[ni][3]));
        }
        rmax0 = fmaxf(rmax0, __shfl_xor_sync(0xffffffffu, rmax0, 1));
        rmax0 = fmaxf(rmax0, __shfl_xor_sync(0xffffffffu, rmax0, 2));
        rmax1 = fmaxf(rmax1, __shfl_xor_sync(0xffffffffu, rmax1, 1));
        rmax1 = fmaxf(rmax1, __shfl_xor_sync(0xffffffffu, rmax1, 2));

        float nm0 = fmaxf(m0, rmax0), nm1 = fmaxf(m1, rmax1);
        float fac0 = __expf(m0 - nm0), fac1 = __expf(m1 - nm1);
        m0 = nm0; m1 = nm1;

        float sum0 = 0.f, sum1 = 0.f;
#pragma unroll
        for (int ni = 0; ni < 8; ni++) {
            float p0 = tf32_rna(__expf(s[ni][0] - m0));
            float p1 = tf32_rna(__expf(s[ni][1] - m0));
            float p2 = tf32_rna(__expf(s[ni][2] - m1));
            float p3 = tf32_rna(__expf(s[ni][3] - m1));
            sum0 += p0 + p1; sum1 += p2 + p3;
            QP[r0][ni * 8 + 2 * tg]     = p0;
            QP[r0][ni * 8 + 2 * tg + 1] = p1;
            QP[r1][ni * 8 + 2 * tg]     = p2;
            QP[r1][ni * 8 + 2 * tg + 1] = p3;
        }
        sum0 += __shfl_xor_sync(0xffffffffu, sum0, 1);
        sum0 += __shfl_xor_sync(0xffffffffu, sum0, 2);
        sum1 += __shfl_xor_sync(0xffffffffu, sum1, 1);
        sum1 += __shfl_xor_sync(0xffffffffu, sum1, 2);
        l0 = l0 * fac0 + sum0;
        l1 = l1 * fac1 + sum1;

#pragma unroll
        for (int ni = 0; ni < 8; ni++) {
            o[ni][0] *= fac0; o[ni][1] *= fac0;
            o[ni][2] *= fac1; o[ni][3] *= fac1;
        }
        __syncwarp();   // P writes visible to the whole warp before ldmatrix reads

        // O += P V : P fragments via ldmatrix (1 x4 per ks)
#pragma unroll
        for (int ks = 0; ks < 8; ks++) {
            uint32_t pf[4];
            ldsm_x4(pBase + (uint32_t)((ks * 8) << 2), pf);
#pragma unroll
            for (int ni = 0; ni < 8; ni++) {
                float bf[2] = { Vs[ks * 8 + tg][ni * 8 + gid],
                                Vs[ks * 8 + tg + 4][ni * 8 + gid] };
                mma_tf32_au(o[ni], pf, bf);
            }
        }
        __syncthreads();   // all reads done before next iter's cp.async overwrites
    }

    float inv0 = 1.f / l0, inv1 = 1.f / l1;
    size_t row0 = (size_t)b * SEQ + i0 + r0;
    size_t row1 = (size_t)b * SEQ + i0 + r1;
#pragma unroll
    for (int ni = 0; ni < 8; ni++) {
        float2 v0 = { tf32_rna(o[ni][0] * inv0), tf32_rna(o[ni][1] * inv0) };
        float2 v1 = { tf32_rna(o[ni][2] * inv1), tf32_rna(o[ni][3] * inv1) };
        *(float2*)&g_attn[row0 * DIM + h * HDIM + ni * 8 + 2 * tg] = v0;
        *(float2*)&g_attn[row1 * DIM + h * HDIM + ni * 8 + 2 * tg] = v1;
    }
}

// ---------------------------------------------------------------------------
extern "C" void kernel_launch(void* const* d_in, const int* in_sizes, int n_in,
                              void* d_out, int out_size)
{
    const float* x    = (const float*)d_in[0];
    const int*   mask = (const int*)d_in[1];     // bool widened to int32 by harness
    const float* pos  = (const float*)d_in[2];
    const float* Wqk  = (const float*)d_in[3];
    const float* Wv   = (const float*)d_in[4];
    const float* Wout = (const float*)d_in[5];
    const float* bout = (const float*)d_in[6];
    float*       out  = (float*)d_out;

    cudaFuncSetAttribute(qkv_gemm_kernel, cudaFuncAttributeMaxDynamicSharedMemorySize,
                         GEMM_SMEM_BYTES);
    cudaFuncSetAttribute(out_gemm_kernel, cudaFuncAttributeMaxDynamicSharedMemorySize,
                         GEMM_SMEM_BYTES);
    cudaFuncSetAttribute(attn_kernel, cudaFuncAttributeMaxDynamicSharedMemorySize,
                         ATT_SMEM_BYTES);

    float* d_xr; float* d_wqkr; float* d_wvr; float* d_woutr;
    cudaGetSymbolAddress((void**)&d_xr,    g_xr);
    cudaGetSymbolAddress((void**)&d_wqkr,  g_wqkr);
    cudaGetSymbolAddress((void**)&d_wvr,   g_wvr);
    cudaGetSymbolAddress((void**)&d_woutr, g_woutr);

    {   // prep: round inputs to tf32 once
        int n4;
        n4 = MROWS * DIM / 4;
        round_kernel<<<(n4 + 255) / 256, 256>>>((const float4*)x, (float4*)d_xr, n4);
        n4 = 2 * DIM * DIM / 4;
        round_kernel<<<(n4 + 255) / 256, 256>>>((const float4*)Wqk, (float4*)d_wqkr, n4);
        n4 = DIM * DIM / 4;
        round_kernel<<<(n4 + 255) / 256, 256>>>((const float4*)Wv, (float4*)d_wvr, n4);
        round_kernel<<<(n4 + 255) / 256, 256>>>((const float4*)Wout, (float4*)d_woutr, n4);
    }
    {   // QKV projection: M=8192, N=3072
        dim3 grid(QKVN / 128, MROWS / 128);
        qkv_gemm_kernel<<<grid, 256, GEMM_SMEM_BYTES>>>(pos);
    }
    {   // Attention: 8 row-tiles x 128 (b,h) pairs
        dim3 grid(SEQ / 128, BATCH * HEADS);
        attn_kernel<<<grid, 256, ATT_SMEM_BYTES>>>(mask);
    }
    {   // Output projection: M=8192, N=1024
        dim3 grid(DIM / 128, MROWS / 128);
        out_gemm_kernel<<<grid, 256, GEMM_SMEM_BYTES>>>(bout, out);
    }
}

// round 13
// speedup vs baseline: 1.2028x; 1.0115x over previous
#include <cuda_runtime.h>
#include <cuda_bf16.h>
#include <cuda_fp16.h>
#include <cstddef>
#include <cstdint>

// Problem constants
#define BATCH 8
#define SEQ   1024
#define DIM   1024
#define HEADS 16
#define HDIM  64
#define MROWS (BATCH * SEQ)          // 8192
#define QKVN  (3 * DIM)              // 3072
#define SCALE 0.03125f               // DIM^-0.5 = 1/32
#define SCALE_L2E 0.045084441522258674f   // SCALE * log2(e)
#define MASKV (-3.402823466e38f)
#define NEGINF (-__int_as_float(0x7f800000) * 1.0f)

// Scratch (static device globals: allocation-free rule)
__device__ float g_q[BATCH * HEADS * SEQ * HDIM];     // [b,h,n,d]  (tf32-rounded)
__device__ float g_k[BATCH * HEADS * SEQ * HDIM];
__device__ __half g_vh[BATCH * HEADS * SEQ * HDIM];   // V in fp16
__device__ float g_attn[BATCH * SEQ * DIM];           // [b,n,h*d]  (tf32-rounded)
// tf32-rounded input copies (rounding hoisted out of GEMM hot loops)
__device__ float g_xr[MROWS * DIM];
__device__ float g_wqkr[2 * DIM * DIM];
__device__ float g_wvr[DIM * DIM];
__device__ float g_woutr[DIM * DIM];

// ---------------------------------------------------------------------------
// helpers
// ---------------------------------------------------------------------------
__device__ __forceinline__ float tf32_rna(float x) {
    uint32_t u;
    asm("cvt.rna.tf32.f32 %0, %1;" : "=r"(u) : "f"(x));
    return __uint_as_float(u);
}
__device__ __forceinline__ float ex2f(float x) {
    float y; asm("ex2.approx.f32 %0, %1;" : "=f"(y) : "f"(x));
    return y;
}

__device__ __forceinline__ void mma_tf32_u(float* c, const uint32_t* a, const uint32_t* b) {
    asm volatile(
        "mma.sync.aligned.m16n8k8.row.col.f32.tf32.tf32.f32 "
        "{%0,%1,%2,%3}, {%4,%5,%6,%7}, {%8,%9}, {%0,%1,%2,%3};"
        : "+f"(c[0]), "+f"(c[1]), "+f"(c[2]), "+f"(c[3])
        : "r"(a[0]), "r"(a[1]), "r"(a[2]), "r"(a[3]),
          "r"(b[0]), "r"(b[1]));
}
__device__ __forceinline__ void mma_tf32_au(float* c, const uint32_t* a, const float* b) {
    asm volatile(
        "mma.sync.aligned.m16n8k8.row.col.f32.tf32.tf32.f32 "
        "{%0,%1,%2,%3}, {%4,%5,%6,%7}, {%8,%9}, {%0,%1,%2,%3};"
        : "+f"(c[0]), "+f"(c[1]), "+f"(c[2]), "+f"(c[3])
        : "r"(a[0]), "r"(a[1]), "r"(a[2]), "r"(a[3]),
          "r"(__float_as_uint(b[0])), "r"(__float_as_uint(b[1])));
}
__device__ __forceinline__ void mma_f16_16x8x16(float* c, const uint32_t* a, const uint32_t* b) {
    asm volatile(
        "mma.sync.aligned.m16n8k16.row.col.f32.f16.f16.f32 "
        "{%0,%1,%2,%3}, {%4,%5,%6,%7}, {%8,%9}, {%0,%1,%2,%3};"
        : "+f"(c[0]), "+f"(c[1]), "+f"(c[2]), "+f"(c[3])
        : "r"(a[0]), "r"(a[1]), "r"(a[2]), "r"(a[3]),
          "r"(b[0]), "r"(b[1]));
}

__device__ __forceinline__ uint32_t smem_u32(const void* p) {
    return (uint32_t)__cvta_generic_to_shared(p);
}
__device__ __forceinline__ void ldsm_x4(uint32_t addr, uint32_t* r) {
    asm volatile("ldmatrix.sync.aligned.m8n8.x4.shared.b16 {%0,%1,%2,%3}, [%4];"
                 : "=r"(r[0]), "=r"(r[1]), "=r"(r[2]), "=r"(r[3]) : "r"(addr));
}
__device__ __forceinline__ void ldsm_x4_t(uint32_t addr, uint32_t* r) {
    asm volatile("ldmatrix.sync.aligned.m8n8.x4.trans.shared.b16 {%0,%1,%2,%3}, [%4];"
                 : "=r"(r[0]), "=r"(r[1]), "=r"(r[2]), "=r"(r[3]) : "r"(addr));
}
__device__ __forceinline__ void cp16(void* smem, const void* g) {
    asm volatile("cp.async.cg.shared.global [%0], [%1], 16;"
                 :: "r"(smem_u32(smem)), "l"(g));
}
__device__ __forceinline__ void cp_commit() {
    asm volatile("cp.async.commit_group;");
}

// ---------------------------------------------------------------------------
// Kernel 0: round fp32 -> tf32-valued fp32 (vectorized)
// ---------------------------------------------------------------------------
__global__ __launch_bounds__(256) void round_kernel(
    const float4* __restrict__ src, float4* __restrict__ dst, int n4)
{
    int i = blockIdx.x * 256 + threadIdx.x;
    if (i < n4) {
        float4 v = src[i];
        v.x = tf32_rna(v.x); v.y = tf32_rna(v.y);
        v.z = tf32_rna(v.z); v.w = tf32_rna(v.w);
        dst[i] = v;
    }
}

// ---------------------------------------------------------------------------
// tf32 GEMM core, cp.async 2-stage pipeline + ldmatrix fragment loads.
// (Unchanged from R10/R11.)
// ---------------------------------------------------------------------------
#define TPAD 36

struct GemmAcc { float acc[4][4][4]; };

__device__ __forceinline__ void gemm_core_async(
    const float* __restrict__ Abase, const float* __restrict__ B0,
    const float* __restrict__ B1, int bm, int bn, bool splitB,
    float* sm, GemmAcc& g)
{
    float (*As)[128][TPAD] = (float(*)[128][TPAD])sm;
    float (*Bs)[128][TPAD] = (float(*)[128][TPAD])(sm + 2 * 128 * TPAD);

    const int tid = threadIdx.x;
    const int lane = tid & 31;
    const int wid = tid >> 5;
    const int wm = (wid & 1) * 64;
    const int wn = (wid >> 1) * 32;

    const int rowA = wm + ((lane >> 3) & 1) * 8 + (lane & 7);
    const int colA = (lane >> 4) * 4;
    const int rowB = wn + ((lane >> 4) & 1) * 8 + (lane & 7);
    const int colB = ((lane >> 3) & 1) * 4;

    const uint32_t aBase = smem_u32(&As[0][0][0]) + (uint32_t)((rowA * TPAD + colA) << 2);
    const uint32_t bBase = smem_u32(&Bs[0][0][0]) + (uint32_t)((rowB * TPAD + colB) << 2);
    const uint32_t STAGE = 128 * TPAD * 4;

#pragma unroll
    for (int mi = 0; mi < 4; mi++)
#pragma unroll
        for (int ni = 0; ni < 4; ni++)
#pragma unroll
            for (int r = 0; r < 4; r++) g.acc[mi][ni][r] = 0.f;

    auto load_tiles = [&](int st, int k0) {
#pragma unroll
        for (int i = tid; i < 128 * 8; i += 256) {
            int row = i >> 3, c4 = (i & 7) * 4;
            cp16(&As[st][row][c4], &Abase[(size_t)(bm + row) * DIM + k0 + c4]);
        }
#pragma unroll
        for (int i = tid; i < 128 * 8; i += 256) {
            int row = i >> 3, c4 = (i & 7) * 4;
            int gn = bn + row;
            const float* Brow = (splitB && gn >= 2 * DIM)
                                ? B1 + (size_t)(gn - 2 * DIM) * DIM
                                : B0 + (size_t)gn * DIM;
            cp16(&Bs[st][row][c4], &Brow[k0 + c4]);
        }
    };

    load_tiles(0, 0);
    cp_commit();

    const int NT = DIM / 32;
    for (int it = 0; it < NT; it++) {
        int cur = it & 1;
        if (it + 1 < NT) {
            load_tiles(cur ^ 1, (it + 1) * 32);
            cp_commit();
            asm volatile("cp.async.wait_group 1;");
        } else {
            asm volatile("cp.async.wait_group 0;");
        }
        __syncthreads();

        const uint32_t aCur = aBase + cur * STAGE;
        const uint32_t bCur = bBase + cur * STAGE;
#pragma unroll
        for (int ks = 0; ks < 32; ks += 8) {
            uint32_t a[4][4];
#pragma unroll
            for (int mi = 0; mi < 4; mi++)
                ldsm_x4(aCur + (uint32_t)((mi * 16 * TPAD + ks) << 2), a[mi]);
            uint32_t b[2][4];
#pragma unroll
            for (int np = 0; np < 2; np++)
                ldsm_x4(bCur + (uint32_t)((np * 16 * TPAD + ks) << 2), b[np]);
#pragma unroll
            for (int mi = 0; mi < 4; mi++)
#pragma unroll
                for (int ni = 0; ni < 4; ni++)
                    mma_tf32_u(g.acc[mi][ni], a[mi], &b[ni >> 1][(ni & 1) * 2]);
        }
        __syncthreads();
    }
}

#define GEMM_SMEM_BYTES (4 * 128 * TPAD * 4)   // 73728

// ---------------------------------------------------------------------------
// Kernel 1: fused QKV projection. V written as fp16 (feeds f16 PV MMA).
// ---------------------------------------------------------------------------
__global__ __launch_bounds__(256) void qkv_gemm_kernel(const float* __restrict__ pos)
{
    extern __shared__ float sm[];
    const int bm = blockIdx.y * 128;
    const int bn = blockIdx.x * 128;
    const int lane = threadIdx.x & 31;
    const int wid = threadIdx.x >> 5;
    const int gid = lane >> 2, tg = lane & 3;
    const int wm = (wid & 1) * 64;
    const int wn = (wid >> 1) * 32;

    GemmAcc g;
    gemm_core_async(g_xr, g_wqkr, g_wvr, bm, bn, true, sm, g);

#pragma unroll
    for (int mi = 0; mi < 4; mi++) {
#pragma unroll
        for (int ni = 0; ni < 4; ni++) {
#pragma unroll
            for (int r = 0; r < 4; r++) {
                int m = bm + wm + mi * 16 + gid + ((r >= 2) ? 8 : 0);
                int gn = bn + wn + ni * 8 + 2 * tg + (r & 1);
                int b = m >> 10, row = m & 1023;
                float val = g.acc[mi][ni][r];
                if (gn < DIM) {
                    int c = gn, h = c >> 6, d = c & 63;
                    val = tf32_rna(val + pos[(size_t)m * DIM + c]);
                    g_q[(((size_t)b * HEADS + h) * SEQ + row) * HDIM + d] = val;
                } else if (gn < 2 * DIM) {
                    int c = gn - DIM, h = c >> 6, d = c & 63;
                    val = tf32_rna(val + pos[(size_t)m * DIM + c]);
                    g_k[(((size_t)b * HEADS + h) * SEQ + row) * HDIM + d] = val;
                } else {
                    int c = gn - 2 * DIM, h = c >> 6, d = c & 63;
                    g_vh[(((size_t)b * HEADS + h) * SEQ + row) * HDIM + d] =
                        __float2half(val);
                }
            }
        }
    }
}

// ---------------------------------------------------------------------------
// Kernel 3: output projection.
// ---------------------------------------------------------------------------
__global__ __launch_bounds__(256) void out_gemm_kernel(
    const float* __restrict__ bout, float* __restrict__ out)
{
    extern __shared__ float sm[];
    const int bm = blockIdx.y * 128;
    const int bn = blockIdx.x * 128;
    const int lane = threadIdx.x & 31;
    const int wid = threadIdx.x >> 5;
    const int gid = lane >> 2, tg = lane & 3;
    const int wm = (wid & 1) * 64;
    const int wn = (wid >> 1) * 32;

    GemmAcc g;
    gemm_core_async(g_attn, g_woutr, nullptr, bm, bn, false, sm, g);

#pragma unroll
    for (int mi = 0; mi < 4; mi++) {
#pragma unroll
        for (int ni = 0; ni < 4; ni++) {
#pragma unroll
            for (int r = 0; r < 4; r++) {
                int m = bm + wm + mi * 16 + gid + ((r >= 2) ? 8 : 0);
                int gn = bn + wn + ni * 8 + 2 * tg + (r & 1);
                out[(size_t)m * DIM + gn] = g.acc[mi][ni][r] + bout[gn];
            }
        }
    }
}

// ---------------------------------------------------------------------------
// Kernel 2: flash attention. S via tf32 (K ldmatrix); PV via fp16 m16n8k16
// with P fp16-packed in smem and V fp16 fragments via ldmatrix.x4.trans.
// exp via ex2.approx with log2e folded into SCALE.
// ---------------------------------------------------------------------------
#define AKPAD 68          // K tile float stride
#define PPAD  72          // P row stride in b16 units (144 B)
#define VPAD  72          // V row stride in b16 units (144 B)
#define ATT_QP_FLOATS   (128 * AKPAD)            // 8704
#define ATT_K_FLOATS    (2 * 64 * AKPAD)         // 8704
#define ATT_V_FLOATS    (2 * 64 * VPAD / 2)      // 4608 (fp16 halves)
#define ATT_SMEM_FLOATS (ATT_QP_FLOATS + ATT_K_FLOATS + ATT_V_FLOATS + 2 * 64)
#define ATT_SMEM_BYTES  (ATT_SMEM_FLOATS * 4)    // 88576

__global__ __launch_bounds__(256) void attn_kernel(const int* __restrict__ mask)
{
    extern __shared__ float sm[];
    float (*QP)[AKPAD]  = (float(*)[AKPAD])sm;                    // Q tile, later P(fp16)
    float (*KsB)[AKPAD] = (float(*)[AKPAD])(sm + ATT_QP_FLOATS);  // [2*64][AKPAD]
    __half* Vb = (__half*)(sm + ATT_QP_FLOATS + ATT_K_FLOATS);
    float* kmB = sm + ATT_QP_FLOATS + ATT_K_FLOATS + ATT_V_FLOATS;

    const int bh = blockIdx.y;
    const int b = bh >> 4, h = bh & 15;
    const int i0 = blockIdx.x * 128;
    const int tid = threadIdx.x;
    const int lane = tid & 31, wid = tid >> 5;
    const int gid = lane >> 2, tg = lane & 3;
    const int r0 = wid * 16 + gid;
    const int r1 = r0 + 8;

    // K B-fragment ldmatrix mapping (tf32, as R11)
    const int rowBf = ((lane >> 4) & 1) * 8 + (lane & 7);
    const int colBf = ((lane >> 3) & 1) * 4;
    const uint32_t kBase = smem_u32(&KsB[0][0]) + (uint32_t)((rowBf * AKPAD + colBf) << 2);
    const uint32_t KSTAGE = 64 * AKPAD * 4;

    // P A-fragment (fp16) and V B-fragment (fp16 trans) lane mappings
    const int l15 = lane & 15, l4 = lane >> 4;
    const uint32_t pBase = smem_u32(&QP[0][0])
        + (uint32_t)(((wid * 16 + l15) * PPAD + l4 * 8) * 2);
    const uint32_t vBase = smem_u32(Vb) + (uint32_t)((l15 * VPAD + l4 * 8) * 2);
    const uint32_t VSTAGE = 64 * VPAD * 2;

    __half* Pb = (__half*)sm;   // P rows stride PPAD (b16)

    const float* qb = g_q + ((size_t)bh * SEQ + i0) * HDIM;
    const float* kb = g_k + (size_t)bh * SEQ * HDIM;
    const __half* vb = g_vh + (size_t)bh * SEQ * HDIM;

    auto load_kv = [&](int st, int j0) {
        float (*K)[AKPAD] = KsB + st * 64;
        __half* V = Vb + st * 64 * VPAD;
#pragma unroll
        for (int i = tid; i < 64 * 16; i += 256) {       // K: 1024 16B chunks
            int row = i >> 4, c4 = (i & 15) * 4;
            cp16(&K[row][c4], &kb[(size_t)(j0 + row) * HDIM + c4]);
        }
#pragma unroll
        for (int i = tid; i < 64 * 8; i += 256) {        // V: 512 16B chunks
            int row = i >> 3, c8 = (i & 7) * 8;
            cp16(&V[row * VPAD + c8], &vb[(size_t)(j0 + row) * HDIM + c8]);
        }
    };
    auto load_km = [&](int st, int j0) {
        if (tid < 64) {
            int gj = j0 + tid;
            kmB[st * 64 + tid] =
                (gj == 0) ? 1.f : (mask[(size_t)b * (SEQ - 1) + gj - 1] ? 1.f : 0.f);
        }
    };

    load_kv(0, 0);
    cp_commit();
    load_km(0, 0);

    for (int i = tid; i < 128 * 16; i += 256) {
        int row = i >> 4, c4 = (i & 15) * 4;
        *(float4*)&QP[row][c4] = *(const float4*)&qb[(size_t)row * HDIM + c4];
    }
    __syncthreads();

    float qa[8][4];
#pragma unroll
    for (int ks = 0; ks < 8; ks++) {
        qa[ks][0] = QP[r0][ks * 8 + tg];
        qa[ks][1] = QP[r1][ks * 8 + tg];
        qa[ks][2] = QP[r0][ks * 8 + tg + 4];
        qa[ks][3] = QP[r1][ks * 8 + tg + 4];
    }
    const int gi0 = i0 + r0, gi1 = i0 + r1;
    const bool qok0 = (gi0 == 0) || (mask[(size_t)b * (SEQ - 1) + gi0 - 1] != 0);
    const bool qok1 = (gi1 == 0) || (mask[(size_t)b * (SEQ - 1) + gi1 - 1] != 0);

    float m0 = NEGINF, m1 = NEGINF, l0 = 0.f, l1 = 0.f;
    float o[8][4] = {};

    const int NT = SEQ / 64;   // 16
    for (int it = 0; it < NT; it++) {
        const int cur = it & 1;
        if (it + 1 < NT) {
            load_kv(cur ^ 1, (it + 1) * 64);
            cp_commit();
            load_km(cur ^ 1, (it + 1) * 64);
            asm volatile("cp.async.wait_group 1;");
        } else {
            asm volatile("cp.async.wait_group 0;");
        }
        __syncthreads();

        const float* km = kmB + cur * 64;
        const uint32_t kCur = kBase + cur * KSTAGE;
        const uint32_t vCur = vBase + cur * VSTAGE;

        // S = Q K^T (tf32; K fragments via ldmatrix)
        float s[8][4] = {};
#pragma unroll
        for (int ks = 0; ks < 8; ks++) {
            uint32_t kf[4][4];
#pragma unroll
            for (int np = 0; np < 4; np++)
                ldsm_x4(kCur + (uint32_t)((np * 16 * AKPAD + ks * 8) << 2), kf[np]);
#pragma unroll
            for (int ni = 0; ni < 8; ni++)
                mma_tf32_au(s[ni], (const uint32_t*)&qa[ks][0],
                            (const float*)&kf[ni >> 1][(ni & 1) * 2]);
        }

        // mask + scale (log2e folded) + row max
        float rmax0 = NEGINF, rmax1 = NEGINF;
#pragma unroll
        for (int ni = 0; ni < 8; ni++) {
            bool k0ok = km[ni * 8 + 2 * tg] != 0.f;
            bool k1ok = km[ni * 8 + 2 * tg + 1] != 0.f;
            s[ni][0] = (qok0 && k0ok) ? s[ni][0] * SCALE_L2E : MASKV;
            s[ni][1] = (qok0 && k1ok) ? s[ni][1] * SCALE_L2E : MASKV;
            s[ni][2] = (qok1 && k0ok) ? s[ni][2] * SCALE_L2E : MASKV;
            s[ni][3] = (qok1 && k1ok) ? s[ni][3] * SCALE_L2E : MASKV;
            rmax0 = fmaxf(rmax0, fmaxf(s[ni][0], s[ni][1]));
            rmax1 = fmaxf(rmax1, fmaxf(s[ni][2], s[ni][3]));
        }
        rmax0 = fmaxf(rmax0, __shfl_xor_sync(0xffffffffu, rmax0, 1));
        rmax0 = fmaxf(rmax0, __shfl_xor_sync(0xffffffffu, rmax0, 2));
        rmax1 = fmaxf(rmax1, __shfl_xor_sync(0xffffffffu, rmax1, 1));
        rmax1 = fmaxf(rmax1, __shfl_xor_sync(0xffffffffu, rmax1, 2));

        float nm0 = fmaxf(m0, rmax0), nm1 = fmaxf(m1, rmax1);
        float fac0 = ex2f(m0 - nm0), fac1 = ex2f(m1 - nm1);
        m0 = nm0; m1 = nm1;

        // P = 2^(s-m) -> fp16 pairs to smem (Q overlay); l sums fp32 p
        float sum0 = 0.f, sum1 = 0.f;
#pragma unroll
        for (int ni = 0; ni < 8; ni++) {
            float p0 = ex2f(s[ni][0] - m0);
            float p1 = ex2f(s[ni][1] - m0);
            float p2 = ex2f(s[ni][2] - m1);
            float p3 = ex2f(s[ni][3] - m1);
            sum0 += p0 + p1; sum1 += p2 + p3;
            *(__half2*)&Pb[r0 * PPAD + ni * 8 + 2 * tg] = __floats2half2_rn(p0, p1);
            *(__half2*)&Pb[r1 * PPAD + ni * 8 + 2 * tg] = __floats2half2_rn(p2, p3);
        }
        sum0 += __shfl_xor_sync(0xffffffffu, sum0, 1);
        sum0 += __shfl_xor_sync(0xffffffffu, sum0, 2);
        sum1 += __shfl_xor_sync(0xffffffffu, sum1, 1);
        sum1 += __shfl_xor_sync(0xffffffffu, sum1, 2);
        l0 = l0 * fac0 + sum0;
        l1 = l1 * fac1 + sum1;

#pragma unroll
        for (int ni = 0; ni < 8; ni++) {
            o[ni][0] *= fac0; o[ni][1] *= fac0;
            o[ni][2] *= fac1; o[ni][3] *= fac1;
        }
        __syncwarp();   // P visible to the whole warp before ldmatrix reads

        // O += P V  (fp16 m16n8k16; V fragments via ldmatrix.trans)
#pragma unroll
        for (int ks = 0; ks < 4; ks++) {          // 16 keys per step
            uint32_t pf[4];
            ldsm_x4(pBase + (uint32_t)(ks * 16 * 2), pf);
#pragma unroll
            for (int np = 0; np < 4; np++) {      // 16 d per pair
                uint32_t vf[4];
                ldsm_x4_t(vCur + (uint32_t)((ks * 16 * VPAD + np * 16) * 2), vf);
                mma_f16_16x8x16(o[np * 2],     pf, &vf[0]);
                mma_f16_16x8x16(o[np * 2 + 1], pf, &vf[2]);
            }
        }
        __syncthreads();   // all reads done before next iter's cp.async overwrites
    }

    float inv0 = 1.f / l0, inv1 = 1.f / l1;
    size_t row0 = (size_t)b * SEQ + i0 + r0;
    size_t row1 = (size_t)b * SEQ + i0 + r1;
#pragma unroll
    for (int ni = 0; ni < 8; ni++) {
        float2 v0 = { tf32_rna(o[ni][0] * inv0), tf32_rna(o[ni][1] * inv0) };
        float2 v1 = { tf32_rna(o[ni][2] * inv1), tf32_rna(o[ni][3] * inv1) };
        *(float2*)&g_attn[row0 * DIM + h * HDIM + ni * 8 + 2 * tg] = v0;
        *(float2*)&g_attn[row1 * DIM + h * HDIM + ni * 8 + 2 * tg] = v1;
    }
}

// ---------------------------------------------------------------------------
extern "C" void kernel_launch(void* const* d_in, const int* in_sizes, int n_in,
                              void* d_out, int out_size)
{
    const float* x    = (const float*)d_in[0];
    const int*   mask = (const int*)d_in[1];     // bool widened to int32 by harness
    const float* pos  = (const float*)d_in[2];
    const float* Wqk  = (const float*)d_in[3];
    const float* Wv   = (const float*)d_in[4];
    const float* Wout = (const float*)d_in[5];
    const float* bout = (const float*)d_in[6];
    float*       out  = (float*)d_out;

    cudaFuncSetAttribute(qkv_gemm_kernel, cudaFuncAttributeMaxDynamicSharedMemorySize,
                         GEMM_SMEM_BYTES);
    cudaFuncSetAttribute(out_gemm_kernel, cudaFuncAttributeMaxDynamicSharedMemorySize,
                         GEMM_SMEM_BYTES);
    cudaFuncSetAttribute(attn_kernel, cudaFuncAttributeMaxDynamicSharedMemorySize,
                         ATT_SMEM_BYTES);

    float* d_xr; float* d_wqkr; float* d_wvr; float* d_woutr;
    cudaGetSymbolAddress((void**)&d_xr,    g_xr);
    cudaGetSymbolAddress((void**)&d_wqkr,  g_wqkr);
    cudaGetSymbolAddress((void**)&d_wvr,   g_wvr);
    cudaGetSymbolAddress((void**)&d_woutr, g_woutr);

    {   // prep: round inputs to tf32 once
        int n4;
        n4 = MROWS * DIM / 4;
        round_kernel<<<(n4 + 255) / 256, 256>>>((const float4*)x, (float4*)d_xr, n4);
        n4 = 2 * DIM * DIM / 4;
        round_kernel<<<(n4 + 255) / 256, 256>>>((const float4*)Wqk, (float4*)d_wqkr, n4);
        n4 = DIM * DIM / 4;
        round_kernel<<<(n4 + 255) / 256, 256>>>((const float4*)Wv, (float4*)d_wvr, n4);
        round_kernel<<<(n4 + 255) / 256, 256>>>((const float4*)Wout, (float4*)d_woutr, n4);
    }
    {   // QKV projection: M=8192, N=3072
        dim3 grid(QKVN / 128, MROWS / 128);
        qkv_gemm_kernel<<<grid, 256, GEMM_SMEM_BYTES>>>(pos);
    }
    {   // Attention: 8 row-tiles x 128 (b,h) pairs
        dim3 grid(SEQ / 128, BATCH * HEADS);
        attn_kernel<<<grid, 256, ATT_SMEM_BYTES>>>(mask);
    }
    {   // Output projection: M=8192, N=1024
        dim3 grid(DIM / 128, MROWS / 128);
        out_gemm_kernel<<<grid, 256, GEMM_SMEM_BYTES>>>(bout, out);
    }
}

// round 14
// speedup vs baseline: 1.4169x; 1.1780x over previous
#include <cuda_runtime.h>
#include <cuda_bf16.h>
#include <cuda_fp16.h>
#include <cstddef>
#include <cstdint>

// Problem constants
#define BATCH 8
#define SEQ   1024
#define DIM   1024
#define HEADS 16
#define HDIM  64
#define MROWS (BATCH * SEQ)          // 8192
#define QKVN  (3 * DIM)              // 3072
#define SCALE 0.03125f               // DIM^-0.5 = 1/32
#define SCALE_L2E 0.045084441522258674f   // SCALE * log2(e)
#define MASKV (-3.402823466e38f)
#define NEGINF (-__int_as_float(0x7f800000) * 1.0f)

// Scratch (static device globals: allocation-free rule)
__device__ __half g_qh[BATCH * HEADS * SEQ * HDIM];   // Q in fp16
__device__ __half g_kh[BATCH * HEADS * SEQ * HDIM];   // K in fp16
__device__ __half g_vh[BATCH * HEADS * SEQ * HDIM];   // V in fp16
__device__ float g_attn[BATCH * SEQ * DIM];           // [b,n,h*d]  (tf32-rounded)
// tf32-rounded input copies (rounding hoisted out of GEMM hot loops)
__device__ float g_xr[MROWS * DIM];
__device__ float g_wqkr[2 * DIM * DIM];
__device__ float g_wvr[DIM * DIM];
__device__ float g_woutr[DIM * DIM];

// ---------------------------------------------------------------------------
// helpers
// ---------------------------------------------------------------------------
__device__ __forceinline__ float tf32_rna(float x) {
    uint32_t u;
    asm("cvt.rna.tf32.f32 %0, %1;" : "=r"(u) : "f"(x));
    return __uint_as_float(u);
}
__device__ __forceinline__ float ex2f(float x) {
    float y; asm("ex2.approx.f32 %0, %1;" : "=f"(y) : "f"(x));
    return y;
}

__device__ __forceinline__ void mma_tf32_u(float* c, const uint32_t* a, const uint32_t* b) {
    asm volatile(
        "mma.sync.aligned.m16n8k8.row.col.f32.tf32.tf32.f32 "
        "{%0,%1,%2,%3}, {%4,%5,%6,%7}, {%8,%9}, {%0,%1,%2,%3};"
        : "+f"(c[0]), "+f"(c[1]), "+f"(c[2]), "+f"(c[3])
        : "r"(a[0]), "r"(a[1]), "r"(a[2]), "r"(a[3]),
          "r"(b[0]), "r"(b[1]));
}
__device__ __forceinline__ void mma_f16_16x8x16(float* c, const uint32_t* a, const uint32_t* b) {
    asm volatile(
        "mma.sync.aligned.m16n8k16.row.col.f32.f16.f16.f32 "
        "{%0,%1,%2,%3}, {%4,%5,%6,%7}, {%8,%9}, {%0,%1,%2,%3};"
        : "+f"(c[0]), "+f"(c[1]), "+f"(c[2]), "+f"(c[3])
        : "r"(a[0]), "r"(a[1]), "r"(a[2]), "r"(a[3]),
          "r"(b[0]), "r"(b[1]));
}

__device__ __forceinline__ uint32_t smem_u32(const void* p) {
    return (uint32_t)__cvta_generic_to_shared(p);
}
__device__ __forceinline__ void ldsm_x4(uint32_t addr, uint32_t* r) {
    asm volatile("ldmatrix.sync.aligned.m8n8.x4.shared.b16 {%0,%1,%2,%3}, [%4];"
                 : "=r"(r[0]), "=r"(r[1]), "=r"(r[2]), "=r"(r[3]) : "r"(addr));
}
__device__ __forceinline__ void ldsm_x4_t(uint32_t addr, uint32_t* r) {
    asm volatile("ldmatrix.sync.aligned.m8n8.x4.trans.shared.b16 {%0,%1,%2,%3}, [%4];"
                 : "=r"(r[0]), "=r"(r[1]), "=r"(r[2]), "=r"(r[3]) : "r"(addr));
}
__device__ __forceinline__ void cp16(void* smem, const void* g) {
    asm volatile("cp.async.cg.shared.global [%0], [%1], 16;"
                 :: "r"(smem_u32(smem)), "l"(g));
}
__device__ __forceinline__ void cp_commit() {
    asm volatile("cp.async.commit_group;");
}

// ---------------------------------------------------------------------------
// Kernel 0: round fp32 -> tf32-valued fp32 (vectorized)
// ---------------------------------------------------------------------------
__global__ __launch_bounds__(256) void round_kernel(
    const float4* __restrict__ src, float4* __restrict__ dst, int n4)
{
    int i = blockIdx.x * 256 + threadIdx.x;
    if (i < n4) {
        float4 v = src[i];
        v.x = tf32_rna(v.x); v.y = tf32_rna(v.y);
        v.z = tf32_rna(v.z); v.w = tf32_rna(v.w);
        dst[i] = v;
    }
}

// ---------------------------------------------------------------------------
// tf32 GEMM core, cp.async 2-stage pipeline + ldmatrix fragment loads.
// (Unchanged from R10/R11.)
// ---------------------------------------------------------------------------
#define TPAD 36

struct GemmAcc { float acc[4][4][4]; };

__device__ __forceinline__ void gemm_core_async(
    const float* __restrict__ Abase, const float* __restrict__ B0,
    const float* __restrict__ B1, int bm, int bn, bool splitB,
    float* sm, GemmAcc& g)
{
    float (*As)[128][TPAD] = (float(*)[128][TPAD])sm;
    float (*Bs)[128][TPAD] = (float(*)[128][TPAD])(sm + 2 * 128 * TPAD);

    const int tid = threadIdx.x;
    const int lane = tid & 31;
    const int wid = tid >> 5;
    const int wm = (wid & 1) * 64;
    const int wn = (wid >> 1) * 32;

    const int rowA = wm + ((lane >> 3) & 1) * 8 + (lane & 7);
    const int colA = (lane >> 4) * 4;
    const int rowB = wn + ((lane >> 4) & 1) * 8 + (lane & 7);
    const int colB = ((lane >> 3) & 1) * 4;

    const uint32_t aBase = smem_u32(&As[0][0][0]) + (uint32_t)((rowA * TPAD + colA) << 2);
    const uint32_t bBase = smem_u32(&Bs[0][0][0]) + (uint32_t)((rowB * TPAD + colB) << 2);
    const uint32_t STAGE = 128 * TPAD * 4;

#pragma unroll
    for (int mi = 0; mi < 4; mi++)
#pragma unroll
        for (int ni = 0; ni < 4; ni++)
#pragma unroll
            for (int r = 0; r < 4; r++) g.acc[mi][ni][r] = 0.f;

    auto load_tiles = [&](int st, int k0) {
#pragma unroll
        for (int i = tid; i < 128 * 8; i += 256) {
            int row = i >> 3, c4 = (i & 7) * 4;
            cp16(&As[st][row][c4], &Abase[(size_t)(bm + row) * DIM + k0 + c4]);
        }
#pragma unroll
        for (int i = tid; i < 128 * 8; i += 256) {
            int row = i >> 3, c4 = (i & 7) * 4;
            int gn = bn + row;
            const float* Brow = (splitB && gn >= 2 * DIM)
                                ? B1 + (size_t)(gn - 2 * DIM) * DIM
                                : B0 + (size_t)gn * DIM;
            cp16(&Bs[st][row][c4], &Brow[k0 + c4]);
        }
    };

    load_tiles(0, 0);
    cp_commit();

    const int NT = DIM / 32;
    for (int it = 0; it < NT; it++) {
        int cur = it & 1;
        if (it + 1 < NT) {
            load_tiles(cur ^ 1, (it + 1) * 32);
            cp_commit();
            asm volatile("cp.async.wait_group 1;");
        } else {
            asm volatile("cp.async.wait_group 0;");
        }
        __syncthreads();

        const uint32_t aCur = aBase + cur * STAGE;
        const uint32_t bCur = bBase + cur * STAGE;
#pragma unroll
        for (int ks = 0; ks < 32; ks += 8) {
            uint32_t a[4][4];
#pragma unroll
            for (int mi = 0; mi < 4; mi++)
                ldsm_x4(aCur + (uint32_t)((mi * 16 * TPAD + ks) << 2), a[mi]);
            uint32_t b[2][4];
#pragma unroll
            for (int np = 0; np < 2; np++)
                ldsm_x4(bCur + (uint32_t)((np * 16 * TPAD + ks) << 2), b[np]);
#pragma unroll
            for (int mi = 0; mi < 4; mi++)
#pragma unroll
                for (int ni = 0; ni < 4; ni++)
                    mma_tf32_u(g.acc[mi][ni], a[mi], &b[ni >> 1][(ni & 1) * 2]);
        }
        __syncthreads();
    }
}

#define GEMM_SMEM_BYTES (4 * 128 * TPAD * 4)   // 73728

// ---------------------------------------------------------------------------
// Kernel 1: fused QKV projection. Q, K, V all written as fp16 (attention is
// fully fp16-MMA now; fp16 mantissa == tf32 mantissa, so precision holds).
// ---------------------------------------------------------------------------
__global__ __launch_bounds__(256) void qkv_gemm_kernel(const float* __restrict__ pos)
{
    extern __shared__ float sm[];
    const int bm = blockIdx.y * 128;
    const int bn = blockIdx.x * 128;
    const int lane = threadIdx.x & 31;
    const int wid = threadIdx.x >> 5;
    const int gid = lane >> 2, tg = lane & 3;
    const int wm = (wid & 1) * 64;
    const int wn = (wid >> 1) * 32;

    GemmAcc g;
    gemm_core_async(g_xr, g_wqkr, g_wvr, bm, bn, true, sm, g);

#pragma unroll
    for (int mi = 0; mi < 4; mi++) {
#pragma unroll
        for (int ni = 0; ni < 4; ni++) {
#pragma unroll
            for (int r = 0; r < 4; r++) {
                int m = bm + wm + mi * 16 + gid + ((r >= 2) ? 8 : 0);
                int gn = bn + wn + ni * 8 + 2 * tg + (r & 1);
                int b = m >> 10, row = m & 1023;
                float val = g.acc[mi][ni][r];
                if (gn < DIM) {
                    int c = gn, h = c >> 6, d = c & 63;
                    g_qh[(((size_t)b * HEADS + h) * SEQ + row) * HDIM + d] =
                        __float2half(val + pos[(size_t)m * DIM + c]);
                } else if (gn < 2 * DIM) {
                    int c = gn - DIM, h = c >> 6, d = c & 63;
                    g_kh[(((size_t)b * HEADS + h) * SEQ + row) * HDIM + d] =
                        __float2half(val + pos[(size_t)m * DIM + c]);
                } else {
                    int c = gn - 2 * DIM, h = c >> 6, d = c & 63;
                    g_vh[(((size_t)b * HEADS + h) * SEQ + row) * HDIM + d] =
                        __float2half(val);
                }
            }
        }
    }
}

// ---------------------------------------------------------------------------
// Kernel 3: output projection.
// ---------------------------------------------------------------------------
__global__ __launch_bounds__(256) void out_gemm_kernel(
    const float* __restrict__ bout, float* __restrict__ out)
{
    extern __shared__ float sm[];
    const int bm = blockIdx.y * 128;
    const int bn = blockIdx.x * 128;
    const int lane = threadIdx.x & 31;
    const int wid = threadIdx.x >> 5;
    const int gid = lane >> 2, tg = lane & 3;
    const int wm = (wid & 1) * 64;
    const int wn = (wid >> 1) * 32;

    GemmAcc g;
    gemm_core_async(g_attn, g_woutr, nullptr, bm, bn, false, sm, g);

#pragma unroll
    for (int mi = 0; mi < 4; mi++) {
#pragma unroll
        for (int ni = 0; ni < 4; ni++) {
#pragma unroll
            for (int r = 0; r < 4; r++) {
                int m = bm + wm + mi * 16 + gid + ((r >= 2) ? 8 : 0);
                int gn = bn + wn + ni * 8 + 2 * tg + (r & 1);
                out[(size_t)m * DIM + gn] = g.acc[mi][ni][r] + bout[gn];
            }
        }
    }
}

// ---------------------------------------------------------------------------
// Kernel 2: flash attention, fully fp16 MMA. S via f16 m16n8k16 (Q fragments
// preloaded via ldmatrix, K fragments via ldmatrix); PV via f16 m16n8k16 with
// P fp16 in smem (Q-tile overlay) and V via ldmatrix.trans. fp32 accumulators
// and softmax; ex2.approx with log2(e) folded into SCALE.
// ---------------------------------------------------------------------------
#define HPAD 72           // b16 row stride for Q/P, K, V tiles (144 B)
#define ATT_QP_BYTES   (128 * HPAD * 2)          // 18432
#define ATT_K_BYTES    (2 * 64 * HPAD * 2)       // 18432
#define ATT_V_BYTES    (2 * 64 * HPAD * 2)       // 18432
#define ATT_KM_BYTES   (2 * 64 * 4)              // 512
#define ATT_SMEM_BYTES (ATT_QP_BYTES + ATT_K_BYTES + ATT_V_BYTES + ATT_KM_BYTES) // 55808

__global__ __launch_bounds__(256) void attn_kernel(const int* __restrict__ mask)
{
    extern __shared__ char smc[];
    __half* QP = (__half*)smc;                         // Q tile, later P
    __half* Kh = (__half*)(smc + ATT_QP_BYTES);        // [2*64][HPAD]
    __half* Vh = (__half*)(smc + ATT_QP_BYTES + ATT_K_BYTES);
    float* kmB = (float*)(smc + ATT_QP_BYTES + ATT_K_BYTES + ATT_V_BYTES);

    const int bh = blockIdx.y;
    const int b = bh >> 4, h = bh & 15;
    const int i0 = blockIdx.x * 128;
    const int tid = threadIdx.x;
    const int lane = tid & 31, wid = tid >> 5;
    const int gid = lane >> 2, tg = lane & 3;
    const int r0 = wid * 16 + gid;
    const int r1 = r0 + 8;

    // fragment lane mappings
    const int l15 = lane & 15, l4 = lane >> 4;
    // A-fragment (Q and P): row = wid*16 + l15, col chunk = l4*8 halves
    const uint32_t qpBase = smem_u32(QP) + (uint32_t)(((wid * 16 + l15) * HPAD + l4 * 8) * 2);
    // B-fragment (K): row = ((lane>>4)&1)*8 + (lane&7), col = ((lane>>3)&1)*8 halves
    const int rowK = ((lane >> 4) & 1) * 8 + (lane & 7);
    const int colK = ((lane >> 3) & 1) * 8;
    const uint32_t kBase = smem_u32(Kh) + (uint32_t)((rowK * HPAD + colK) * 2);
    // B-fragment (V, trans): row = l15 (key), col = l4*8 (d halves)
    const uint32_t vBase = smem_u32(Vh) + (uint32_t)((l15 * HPAD + l4 * 8) * 2);
    const uint32_t HSTAGE = 64 * HPAD * 2;

    const __half* qb = g_qh + ((size_t)bh * SEQ + i0) * HDIM;
    const __half* kb = g_kh + (size_t)bh * SEQ * HDIM;
    const __half* vb = g_vh + (size_t)bh * SEQ * HDIM;

    auto load_kv = [&](int st, int j0) {
        __half* K = Kh + st * 64 * HPAD;
        __half* V = Vh + st * 64 * HPAD;
#pragma unroll
        for (int i = tid; i < 64 * 8; i += 256) {        // 512 chunks each
            int row = i >> 3, c8 = (i & 7) * 8;
            cp16(&K[row * HPAD + c8], &kb[(size_t)(j0 + row) * HDIM + c8]);
            cp16(&V[row * HPAD + c8], &vb[(size_t)(j0 + row) * HDIM + c8]);
        }
    };
    auto load_km = [&](int st, int j0) {
        if (tid < 64) {
            int gj = j0 + tid;
            kmB[st * 64 + tid] =
                (gj == 0) ? 1.f : (mask[(size_t)b * (SEQ - 1) + gj - 1] ? 1.f : 0.f);
        }
    };

    load_kv(0, 0);
    cp_commit();
    load_km(0, 0);

    // stage Q (fp16)
    for (int i = tid; i < 128 * 8; i += 256) {
        int row = i >> 3, c8 = (i & 7) * 8;
        *(float4*)&QP[row * HPAD + c8] = *(const float4*)&qb[(size_t)row * HDIM + c8];
    }
    __syncthreads();

    // Q fragments register-resident: 4 k-chunks of 16
    uint32_t qa[4][4];
#pragma unroll
    for (int kc = 0; kc < 4; kc++)
        ldsm_x4(qpBase + (uint32_t)(kc * 16 * 2), qa[kc]);

    const int gi0 = i0 + r0, gi1 = i0 + r1;
    const bool qok0 = (gi0 == 0) || (mask[(size_t)b * (SEQ - 1) + gi0 - 1] != 0);
    const bool qok1 = (gi1 == 0) || (mask[(size_t)b * (SEQ - 1) + gi1 - 1] != 0);

    float m0 = NEGINF, m1 = NEGINF, l0 = 0.f, l1 = 0.f;
    float o[8][4] = {};

    __half* Pb = QP;   // P overlay, rows stride HPAD

    const int NT = SEQ / 64;   // 16
    for (int it = 0; it < NT; it++) {
        const int cur = it & 1;
        if (it + 1 < NT) {
            load_kv(cur ^ 1, (it + 1) * 64);
            cp_commit();
            load_km(cur ^ 1, (it + 1) * 64);
            asm volatile("cp.async.wait_group 1;");
        } else {
            asm volatile("cp.async.wait_group 0;");
        }
        __syncthreads();

        const float* km = kmB + cur * 64;
        const uint32_t kCur = kBase + cur * HSTAGE;
        const uint32_t vCur = vBase + cur * HSTAGE;

        // S = Q K^T (f16 m16n8k16): 4 k-chunks x 8 ni
        float s[8][4] = {};
#pragma unroll
        for (int kc = 0; kc < 4; kc++) {
            uint32_t kf[4][4];
#pragma unroll
            for (int np = 0; np < 4; np++)
                ldsm_x4(kCur + (uint32_t)((np * 16 * HPAD + kc * 16) * 2), kf[np]);
#pragma unroll
            for (int ni = 0; ni < 8; ni++)
                mma_f16_16x8x16(s[ni], qa[kc], &kf[ni >> 1][(ni & 1) * 2]);
        }

        // mask + scale (log2e folded) + row max
        float rmax0 = NEGINF, rmax1 = NEGINF;
#pragma unroll
        for (int ni = 0; ni < 8; ni++) {
            bool k0ok = km[ni * 8 + 2 * tg] != 0.f;
            bool k1ok = km[ni * 8 + 2 * tg + 1] != 0.f;
            s[ni][0] = (qok0 && k0ok) ? s[ni][0] * SCALE_L2E : MASKV;
            s[ni][1] = (qok0 && k1ok) ? s[ni][1] * SCALE_L2E : MASKV;
            s[ni][2] = (qok1 && k0ok) ? s[ni][2] * SCALE_L2E : MASKV;
            s[ni][3] = (qok1 && k1ok) ? s[ni][3] * SCALE_L2E : MASKV;
            rmax0 = fmaxf(rmax0, fmaxf(s[ni][0], s[ni][1]));
            rmax1 = fmaxf(rmax1, fmaxf(s[ni][2], s[ni][3]));
        }
        rmax0 = fmaxf(rmax0, __shfl_xor_sync(0xffffffffu, rmax0, 1));
        rmax0 = fmaxf(rmax0, __shfl_xor_sync(0xffffffffu, rmax0, 2));
        rmax1 = fmaxf(rmax1, __shfl_xor_sync(0xffffffffu, rmax1, 1));
        rmax1 = fmaxf(rmax1, __shfl_xor_sync(0xffffffffu, rmax1, 2));

        float nm0 = fmaxf(m0, rmax0), nm1 = fmaxf(m1, rmax1);
        float fac0 = ex2f(m0 - nm0), fac1 = ex2f(m1 - nm1);
        m0 = nm0; m1 = nm1;

        // P = 2^(s-m) -> fp16 pairs to smem (Q overlay); l sums fp32 p
        float sum0 = 0.f, sum1 = 0.f;
#pragma unroll
        for (int ni = 0; ni < 8; ni++) {
            float p0 = ex2f(s[ni][0] - m0);
            float p1 = ex2f(s[ni][1] - m0);
            float p2 = ex2f(s[ni][2] - m1);
            float p3 = ex2f(s[ni][3] - m1);
            sum0 += p0 + p1; sum1 += p2 + p3;
            *(__half2*)&Pb[r0 * HPAD + ni * 8 + 2 * tg] = __floats2half2_rn(p0, p1);
            *(__half2*)&Pb[r1 * HPAD + ni * 8 + 2 * tg] = __floats2half2_rn(p2, p3);
        }
        sum0 += __shfl_xor_sync(0xffffffffu, sum0, 1);
        sum0 += __shfl_xor_sync(0xffffffffu, sum0, 2);
        sum1 += __shfl_xor_sync(0xffffffffu, sum1, 1);
        sum1 += __shfl_xor_sync(0xffffffffu, sum1, 2);
        l0 = l0 * fac0 + sum0;
        l1 = l1 * fac1 + sum1;

#pragma unroll
        for (int ni = 0; ni < 8; ni++) {
            o[ni][0] *= fac0; o[ni][1] *= fac0;
            o[ni][2] *= fac1; o[ni][3] *= fac1;
        }
        __syncwarp();   // P visible to the whole warp before ldmatrix reads

        // O += P V  (f16 m16n8k16; V fragments via ldmatrix.trans)
#pragma unroll
        for (int ks = 0; ks < 4; ks++) {          // 16 keys per step
            uint32_t pf[4];
            ldsm_x4(qpBase + (uint32_t)(ks * 16 * 2), pf);
#pragma unroll
            for (int np = 0; np < 4; np++) {      // 16 d per pair
                uint32_t vf[4];
                ldsm_x4_t(vCur + (uint32_t)((ks * 16 * HPAD + np * 16) * 2), vf);
                mma_f16_16x8x16(o[np * 2],     pf, &vf[0]);
                mma_f16_16x8x16(o[np * 2 + 1], pf, &vf[2]);
            }
        }
        __syncthreads();   // all reads done before next iter's cp.async overwrites
    }

    float inv0 = 1.f / l0, inv1 = 1.f / l1;
    size_t row0 = (size_t)b * SEQ + i0 + r0;
    size_t row1 = (size_t)b * SEQ + i0 + r1;
#pragma unroll
    for (int ni = 0; ni < 8; ni++) {
        float2 v0 = { tf32_rna(o[ni][0] * inv0), tf32_rna(o[ni][1] * inv0) };
        float2 v1 = { tf32_rna(o[ni][2] * inv1), tf32_rna(o[ni][3] * inv1) };
        *(float2*)&g_attn[row0 * DIM + h * HDIM + ni * 8 + 2 * tg] = v0;
        *(float2*)&g_attn[row1 * DIM + h * HDIM + ni * 8 + 2 * tg] = v1;
    }
}

// ---------------------------------------------------------------------------
extern "C" void kernel_launch(void* const* d_in, const int* in_sizes, int n_in,
                              void* d_out, int out_size)
{
    const float* x    = (const float*)d_in[0];
    const int*   mask = (const int*)d_in[1];     // bool widened to int32 by harness
    const float* pos  = (const float*)d_in[2];
    const float* Wqk  = (const float*)d_in[3];
    const float* Wv   = (const float*)d_in[4];
    const float* Wout = (const float*)d_in[5];
    const float* bout = (const float*)d_in[6];
    float*       out  = (float*)d_out;

    cudaFuncSetAttribute(qkv_gemm_kernel, cudaFuncAttributeMaxDynamicSharedMemorySize,
                         GEMM_SMEM_BYTES);
    cudaFuncSetAttribute(out_gemm_kernel, cudaFuncAttributeMaxDynamicSharedMemorySize,
                         GEMM_SMEM_BYTES);
    cudaFuncSetAttribute(attn_kernel, cudaFuncAttributeMaxDynamicSharedMemorySize,
                         ATT_SMEM_BYTES);

    float* d_xr; float* d_wqkr; float* d_wvr; float* d_woutr;
    cudaGetSymbolAddress((void**)&d_xr,    g_xr);
    cudaGetSymbolAddress((void**)&d_wqkr,  g_wqkr);
    cudaGetSymbolAddress((void**)&d_wvr,   g_wvr);
    cudaGetSymbolAddress((void**)&d_woutr, g_woutr);

    {   // prep: round inputs to tf32 once
        int n4;
        n4 = MROWS * DIM / 4;
        round_kernel<<<(n4 + 255) / 256, 256>>>((const float4*)x, (float4*)d_xr, n4);
        n4 = 2 * DIM * DIM / 4;
        round_kernel<<<(n4 + 255) / 256, 256>>>((const float4*)Wqk, (float4*)d_wqkr, n4);
        n4 = DIM * DIM / 4;
        round_kernel<<<(n4 + 255) / 256, 256>>>((const float4*)Wv, (float4*)d_wvr, n4);
        round_kernel<<<(n4 + 255) / 256, 256>>>((const float4*)Wout, (float4*)d_woutr, n4);
    }
    {   // QKV projection: M=8192, N=3072
        dim3 grid(QKVN / 128, MROWS / 128);
        qkv_gemm_kernel<<<grid, 256, GEMM_SMEM_BYTES>>>(pos);
    }
    {   // Attention: 8 row-tiles x 128 (b,h) pairs
        dim3 grid(SEQ / 128, BATCH * HEADS);
        attn_kernel<<<grid, 256, ATT_SMEM_BYTES>>>(mask);
    }
    {   // Output projection: M=8192, N=1024
        dim3 grid(DIM / 128, MROWS / 128);
        out_gemm_kernel<<<grid, 256, GEMM_SMEM_BYTES>>>(bout, out);
    }
}

// round 15
// speedup vs baseline: 1.9908x; 1.4050x over previous
#include <cuda_runtime.h>
#include <cuda_bf16.h>
#include <cuda_fp16.h>
#include <cstddef>
#include <cstdint>

// Problem constants
#define BATCH 8
#define SEQ   1024
#define DIM   1024
#define HEADS 16
#define HDIM  64
#define MROWS (BATCH * SEQ)          // 8192
#define QKVN  (3 * DIM)              // 3072
#define SCALE 0.03125f               // DIM^-0.5 = 1/32
#define SCALE_L2E 0.045084441522258674f   // SCALE * log2(e)
#define MASKV (-3.402823466e38f)
#define NEGINF (-__int_as_float(0x7f800000) * 1.0f)

// Scratch (static device globals: allocation-free rule)
__device__ __half g_qh[BATCH * HEADS * SEQ * HDIM];   // Q in fp16
__device__ __half g_kh[BATCH * HEADS * SEQ * HDIM];   // K in fp16
__device__ __half g_vh[BATCH * HEADS * SEQ * HDIM];   // V in fp16
__device__ __half g_attnh[BATCH * SEQ * DIM];         // attention out, fp16
// fp16 input copies (conversion hoisted out of GEMM hot loops)
__device__ __half g_x16[MROWS * DIM];
__device__ __half g_w16[QKVN * DIM];                  // [Wqk; Wv]
__device__ __half g_wo16[DIM * DIM];

// ---------------------------------------------------------------------------
// helpers
// ---------------------------------------------------------------------------
__device__ __forceinline__ float ex2f(float x) {
    float y; asm("ex2.approx.f32 %0, %1;" : "=f"(y) : "f"(x));
    return y;
}
__device__ __forceinline__ void mma_f16_16x8x16(float* c, const uint32_t* a, const uint32_t* b) {
    asm volatile(
        "mma.sync.aligned.m16n8k16.row.col.f32.f16.f16.f32 "
        "{%0,%1,%2,%3}, {%4,%5,%6,%7}, {%8,%9}, {%0,%1,%2,%3};"
        : "+f"(c[0]), "+f"(c[1]), "+f"(c[2]), "+f"(c[3])
        : "r"(a[0]), "r"(a[1]), "r"(a[2]), "r"(a[3]),
          "r"(b[0]), "r"(b[1]));
}
__device__ __forceinline__ uint32_t smem_u32(const void* p) {
    return (uint32_t)__cvta_generic_to_shared(p);
}
__device__ __forceinline__ void ldsm_x4(uint32_t addr, uint32_t* r) {
    asm volatile("ldmatrix.sync.aligned.m8n8.x4.shared.b16 {%0,%1,%2,%3}, [%4];"
                 : "=r"(r[0]), "=r"(r[1]), "=r"(r[2]), "=r"(r[3]) : "r"(addr));
}
__device__ __forceinline__ void ldsm_x4_t(uint32_t addr, uint32_t* r) {
    asm volatile("ldmatrix.sync.aligned.m8n8.x4.trans.shared.b16 {%0,%1,%2,%3}, [%4];"
                 : "=r"(r[0]), "=r"(r[1]), "=r"(r[2]), "=r"(r[3]) : "r"(addr));
}
__device__ __forceinline__ void cp16(void* smem, const void* g) {
    asm volatile("cp.async.cg.shared.global [%0], [%1], 16;"
                 :: "r"(smem_u32(smem)), "l"(g));
}
__device__ __forceinline__ void cp_commit() {
    asm volatile("cp.async.commit_group;");
}

// ---------------------------------------------------------------------------
// Kernel 0: fp32 -> fp16 conversion (vectorized)
// ---------------------------------------------------------------------------
__global__ __launch_bounds__(256) void tohalf_kernel(
    const float4* __restrict__ src, __half2* __restrict__ dst, int n4)
{
    int i = blockIdx.x * 256 + threadIdx.x;
    if (i < n4) {
        float4 v = src[i];
        dst[2 * i]     = __floats2half2_rn(v.x, v.y);
        dst[2 * i + 1] = __floats2half2_rn(v.z, v.w);
    }
}

// ---------------------------------------------------------------------------
// fp16 GEMM core: 128x128 tile, K-chunk 64, cp.async 2-stage, ldmatrix
// fragment loads, f16 m16n8k16 MMA with fp32 accum. 8 warps (2M x 4N),
// warp tile 64x32. Row stride 72 halves (144 B) - proven conflict-free.
// ---------------------------------------------------------------------------
#define GPAD16 72

struct GemmAcc { float acc[4][4][4]; };

__device__ __forceinline__ void gemm16_core(
    const __half* __restrict__ Abase, const __half* __restrict__ Bbase,
    int bm, int bn, char* smc, GemmAcc& g)
{
    __half* As = (__half*)smc;                        // [2][128][GPAD16]
    __half* Bs = (__half*)(smc + 2 * 128 * GPAD16 * 2);

    const int tid = threadIdx.x;
    const int lane = tid & 31;
    const int wid = tid >> 5;
    const int wm = (wid & 1) * 64;
    const int wn = (wid >> 1) * 32;
    const int l15 = lane & 15, l4 = lane >> 4;

    const uint32_t aBase = smem_u32(As) + (uint32_t)(((wm + l15) * GPAD16 + l4 * 8) * 2);
    const int rowB = wn + ((lane >> 4) & 1) * 8 + (lane & 7);
    const int colB = ((lane >> 3) & 1) * 8;
    const uint32_t bBase = smem_u32(Bs) + (uint32_t)((rowB * GPAD16 + colB) * 2);
    const uint32_t STAGE = 128 * GPAD16 * 2;

#pragma unroll
    for (int mi = 0; mi < 4; mi++)
#pragma unroll
        for (int ni = 0; ni < 4; ni++)
#pragma unroll
            for (int r = 0; r < 4; r++) g.acc[mi][ni][r] = 0.f;

    auto load_tiles = [&](int st, int k0) {
#pragma unroll
        for (int i = tid; i < 128 * 8; i += 256) {
            int row = i >> 3, c8 = (i & 7) * 8;
            cp16(As + (size_t)st * 128 * GPAD16 + row * GPAD16 + c8,
                 Abase + (size_t)(bm + row) * DIM + k0 + c8);
        }
#pragma unroll
        for (int i = tid; i < 128 * 8; i += 256) {
            int row = i >> 3, c8 = (i & 7) * 8;
            cp16(Bs + (size_t)st * 128 * GPAD16 + row * GPAD16 + c8,
                 Bbase + (size_t)(bn + row) * DIM + k0 + c8);
        }
    };

    load_tiles(0, 0);
    cp_commit();

    const int NT = DIM / 64;  // 16
    for (int it = 0; it < NT; it++) {
        int cur = it & 1;
        if (it + 1 < NT) {
            load_tiles(cur ^ 1, (it + 1) * 64);
            cp_commit();
            asm volatile("cp.async.wait_group 1;");
        } else {
            asm volatile("cp.async.wait_group 0;");
        }
        __syncthreads();

        const uint32_t aCur = aBase + cur * STAGE;
        const uint32_t bCur = bBase + cur * STAGE;
#pragma unroll
        for (int kc = 0; kc < 4; kc++) {
            uint32_t a[4][4];
#pragma unroll
            for (int mi = 0; mi < 4; mi++)
                ldsm_x4(aCur + (uint32_t)((mi * 16 * GPAD16 + kc * 16) * 2), a[mi]);
            uint32_t b[2][4];
#pragma unroll
            for (int np = 0; np < 2; np++)
                ldsm_x4(bCur + (uint32_t)((np * 16 * GPAD16 + kc * 16) * 2), b[np]);
#pragma unroll
            for (int mi = 0; mi < 4; mi++)
#pragma unroll
                for (int ni = 0; ni < 4; ni++)
                    mma_f16_16x8x16(g.acc[mi][ni], a[mi], &b[ni >> 1][(ni & 1) * 2]);
        }
        __syncthreads();
    }
}

#define GEMM_SMEM_BYTES (4 * 128 * GPAD16 * 2)   // 73728

// ---------------------------------------------------------------------------
// Kernel 1: fused QKV projection (fp16 core). Epilogue: +pos (fp32), write
// Q/K/V fp16 in [b,h,n,d].
// ---------------------------------------------------------------------------
__global__ __launch_bounds__(256) void qkv_gemm_kernel(const float* __restrict__ pos)
{
    extern __shared__ char smc[];
    const int bm = blockIdx.y * 128;
    const int bn = blockIdx.x * 128;
    const int lane = threadIdx.x & 31;
    const int wid = threadIdx.x >> 5;
    const int gid = lane >> 2, tg = lane & 3;
    const int wm = (wid & 1) * 64;
    const int wn = (wid >> 1) * 32;

    GemmAcc g;
    gemm16_core(g_x16, g_w16, bm, bn, smc, g);

#pragma unroll
    for (int mi = 0; mi < 4; mi++) {
#pragma unroll
        for (int ni = 0; ni < 4; ni++) {
#pragma unroll
            for (int r = 0; r < 4; r++) {
                int m = bm + wm + mi * 16 + gid + ((r >= 2) ? 8 : 0);
                int gn = bn + wn + ni * 8 + 2 * tg + (r & 1);
                int b = m >> 10, row = m & 1023;
                float val = g.acc[mi][ni][r];
                if (gn < DIM) {
                    int c = gn, h = c >> 6, d = c & 63;
                    g_qh[(((size_t)b * HEADS + h) * SEQ + row) * HDIM + d] =
                        __float2half(val + pos[(size_t)m * DIM + c]);
                } else if (gn < 2 * DIM) {
                    int c = gn - DIM, h = c >> 6, d = c & 63;
                    g_kh[(((size_t)b * HEADS + h) * SEQ + row) * HDIM + d] =
                        __float2half(val + pos[(size_t)m * DIM + c]);
                } else {
                    int c = gn - 2 * DIM, h = c >> 6, d = c & 63;
                    g_vh[(((size_t)b * HEADS + h) * SEQ + row) * HDIM + d] =
                        __float2half(val);
                }
            }
        }
    }
}

// ---------------------------------------------------------------------------
// Kernel 3: output projection (fp16 core). out = attn @ W_out^T + b_out
// ---------------------------------------------------------------------------
__global__ __launch_bounds__(256) void out_gemm_kernel(
    const float* __restrict__ bout, float* __restrict__ out)
{
    extern __shared__ char smc[];
    const int bm = blockIdx.y * 128;
    const int bn = blockIdx.x * 128;
    const int lane = threadIdx.x & 31;
    const int wid = threadIdx.x >> 5;
    const int gid = lane >> 2, tg = lane & 3;
    const int wm = (wid & 1) * 64;
    const int wn = (wid >> 1) * 32;

    GemmAcc g;
    gemm16_core(g_attnh, g_wo16, bm, bn, smc, g);

#pragma unroll
    for (int mi = 0; mi < 4; mi++) {
#pragma unroll
        for (int ni = 0; ni < 4; ni++) {
#pragma unroll
            for (int r = 0; r < 4; r++) {
                int m = bm + wm + mi * 16 + gid + ((r >= 2) ? 8 : 0);
                int gn = bn + wn + ni * 8 + 2 * tg + (r & 1);
                out[(size_t)m * DIM + gn] = g.acc[mi][ni][r] + bout[gn];
            }
        }
    }
}

// ---------------------------------------------------------------------------
// Kernel 2: flash attention, fully fp16 MMA (identical to R14 except the
// epilogue writes fp16 to g_attnh for the fp16 out projection).
// ---------------------------------------------------------------------------
#define HPAD 72           // b16 row stride for Q/P, K, V tiles (144 B)
#define ATT_QP_BYTES   (128 * HPAD * 2)          // 18432
#define ATT_K_BYTES    (2 * 64 * HPAD * 2)       // 18432
#define ATT_V_BYTES    (2 * 64 * HPAD * 2)       // 18432
#define ATT_KM_BYTES   (2 * 64 * 4)              // 512
#define ATT_SMEM_BYTES (ATT_QP_BYTES + ATT_K_BYTES + ATT_V_BYTES + ATT_KM_BYTES) // 55808

__global__ __launch_bounds__(256) void attn_kernel(const int* __restrict__ mask)
{
    extern __shared__ char smc[];
    __half* QP = (__half*)smc;                         // Q tile, later P
    __half* Kh = (__half*)(smc + ATT_QP_BYTES);        // [2*64][HPAD]
    __half* Vh = (__half*)(smc + ATT_QP_BYTES + ATT_K_BYTES);
    float* kmB = (float*)(smc + ATT_QP_BYTES + ATT_K_BYTES + ATT_V_BYTES);

    const int bh = blockIdx.y;
    const int b = bh >> 4, h = bh & 15;
    const int i0 = blockIdx.x * 128;
    const int tid = threadIdx.x;
    const int lane = tid & 31, wid = tid >> 5;
    const int gid = lane >> 2, tg = lane & 3;
    const int r0 = wid * 16 + gid;
    const int r1 = r0 + 8;

    const int l15 = lane & 15, l4 = lane >> 4;
    const uint32_t qpBase = smem_u32(QP) + (uint32_t)(((wid * 16 + l15) * HPAD + l4 * 8) * 2);
    const int rowK = ((lane >> 4) & 1) * 8 + (lane & 7);
    const int colK = ((lane >> 3) & 1) * 8;
    const uint32_t kBase = smem_u32(Kh) + (uint32_t)((rowK * HPAD + colK) * 2);
    const uint32_t vBase = smem_u32(Vh) + (uint32_t)((l15 * HPAD + l4 * 8) * 2);
    const uint32_t HSTAGE = 64 * HPAD * 2;

    const __half* qb = g_qh + ((size_t)bh * SEQ + i0) * HDIM;
    const __half* kb = g_kh + (size_t)bh * SEQ * HDIM;
    const __half* vb = g_vh + (size_t)bh * SEQ * HDIM;

    auto load_kv = [&](int st, int j0) {
        __half* K = Kh + st * 64 * HPAD;
        __half* V = Vh + st * 64 * HPAD;
#pragma unroll
        for (int i = tid; i < 64 * 8; i += 256) {
            int row = i >> 3, c8 = (i & 7) * 8;
            cp16(&K[row * HPAD + c8], &kb[(size_t)(j0 + row) * HDIM + c8]);
            cp16(&V[row * HPAD + c8], &vb[(size_t)(j0 + row) * HDIM + c8]);
        }
    };
    auto load_km = [&](int st, int j0) {
        if (tid < 64) {
            int gj = j0 + tid;
            kmB[st * 64 + tid] =
                (gj == 0) ? 1.f : (mask[(size_t)b * (SEQ - 1) + gj - 1] ? 1.f : 0.f);
        }
    };

    load_kv(0, 0);
    cp_commit();
    load_km(0, 0);

    for (int i = tid; i < 128 * 8; i += 256) {
        int row = i >> 3, c8 = (i & 7) * 8;
        *(float4*)&QP[row * HPAD + c8] = *(const float4*)&qb[(size_t)row * HDIM + c8];
    }
    __syncthreads();

    uint32_t qa[4][4];
#pragma unroll
    for (int kc = 0; kc < 4; kc++)
        ldsm_x4(qpBase + (uint32_t)(kc * 16 * 2), qa[kc]);

    const int gi0 = i0 + r0, gi1 = i0 + r1;
    const bool qok0 = (gi0 == 0) || (mask[(size_t)b * (SEQ - 1) + gi0 - 1] != 0);
    const bool qok1 = (gi1 == 0) || (mask[(size_t)b * (SEQ - 1) + gi1 - 1] != 0);

    float m0 = NEGINF, m1 = NEGINF, l0 = 0.f, l1 = 0.f;
    float o[8][4] = {};

    __half* Pb = QP;

    const int NT = SEQ / 64;   // 16
    for (int it = 0; it < NT; it++) {
        const int cur = it & 1;
        if (it + 1 < NT) {
            load_kv(cur ^ 1, (it + 1) * 64);
            cp_commit();
            load_km(cur ^ 1, (it + 1) * 64);
            asm volatile("cp.async.wait_group 1;");
        } else {
            asm volatile("cp.async.wait_group 0;");
        }
        __syncthreads();

        const float* km = kmB + cur * 64;
        const uint32_t kCur = kBase + cur * HSTAGE;
        const uint32_t vCur = vBase + cur * HSTAGE;

        // S = Q K^T (f16 m16n8k16)
        float s[8][4] = {};
#pragma unroll
        for (int kc = 0; kc < 4; kc++) {
            uint32_t kf[4][4];
#pragma unroll
            for (int np = 0; np < 4; np++)
                ldsm_x4(kCur + (uint32_t)((np * 16 * HPAD + kc * 16) * 2), kf[np]);
#pragma unroll
            for (int ni = 0; ni < 8; ni++)
                mma_f16_16x8k16:
                mma_f16_16x8x16(s[ni], qa[kc], &kf[ni >> 1][(ni & 1) * 2]);
        }

        float rmax0 = NEGINF, rmax1 = NEGINF;
#pragma unroll
        for (int ni = 0; ni < 8; ni++) {
            bool k0ok = km[ni * 8 + 2 * tg] != 0.f;
            bool k1ok = km[ni * 8 + 2 * tg + 1] != 0.f;
            s[ni][0] = (qok0 && k0ok) ? s[ni][0] * SCALE_L2E : MASKV;
            s[ni][1] = (qok0 && k1ok) ? s[ni][1] * SCALE_L2E : MASKV;
            s[ni][2] = (qok1 && k0ok) ? s[ni][2] * SCALE_L2E : MASKV;
            s[ni][3] = (qok1 && k1ok) ? s[ni][3] * SCALE_L2E : MASKV;
            rmax0 = fmaxf(rmax0, fmaxf(s[ni][0], s[ni][1]));
            rmax1 = fmaxf(rmax1, fmaxf(s[ni][2], s[ni][3]));
        }
        rmax0 = fmaxf(rmax0, __shfl_xor_sync(0xffffffffu, rmax0, 1));
        rmax0 = fmaxf(rmax0, __shfl_xor_sync(0xffffffffu, rmax0, 2));
        rmax1 = fmaxf(rmax1, __shfl_xor_sync(0xffffffffu, rmax1, 1));
        rmax1 = fmaxf(rmax1, __shfl_xor_sync(0xffffffffu, rmax1, 2));

        float nm0 = fmaxf(m0, rmax0), nm1 = fmaxf(m1, rmax1);
        float fac0 = ex2f(m0 - nm0), fac1 = ex2f(m1 - nm1);
        m0 = nm0; m1 = nm1;

        float sum0 = 0.f, sum1 = 0.f;
#pragma unroll
        for (int ni = 0; ni < 8; ni++) {
            float p0 = ex2f(s[ni][0] - m0);
            float p1 = ex2f(s[ni][1] - m0);
            float p2 = ex2f(s[ni][2] - m1);
            float p3 = ex2f(s[ni][3] - m1);
            sum0 += p0 + p1; sum1 += p2 + p3;
            *(__half2*)&Pb[r0 * HPAD + ni * 8 + 2 * tg] = __floats2half2_rn(p0, p1);
            *(__half2*)&Pb[r1 * HPAD + ni * 8 + 2 * tg] = __floats2half2_rn(p2, p3);
        }
        sum0 += __shfl_xor_sync(0xffffffffu, sum0, 1);
        sum0 += __shfl_xor_sync(0xffffffffu, sum0, 2);
        sum1 += __shfl_xor_sync(0xffffffffu, sum1, 1);
        sum1 += __shfl_xor_sync(0xffffffffu, sum1, 2);
        l0 = l0 * fac0 + sum0;
        l1 = l1 * fac1 + sum1;

#pragma unroll
        for (int ni = 0; ni < 8; ni++) {
            o[ni][0] *= fac0; o[ni][1] *= fac0;
            o[ni][2] *= fac1; o[ni][3] *= fac1;
        }
        __syncwarp();

#pragma unroll
        for (int ks = 0; ks < 4; ks++) {
            uint32_t pf[4];
            ldsm_x4(qpBase + (uint32_t)(ks * 16 * 2), pf);
#pragma unroll
            for (int np = 0; np < 4; np++) {
                uint32_t vf[4];
                ldsm_x4_t(vCur + (uint32_t)((ks * 16 * HPAD + np * 16) * 2), vf);
                mma_f16_16x8x16(o[np * 2],     pf, &vf[0]);
                mma_f16_16x8x16(o[np * 2 + 1], pf, &vf[2]);
            }
        }
        __syncthreads();
    }

    float inv0 = 1.f / l0, inv1 = 1.f / l1;
    size_t row0 = (size_t)b * SEQ + i0 + r0;
    size_t row1 = (size_t)b * SEQ + i0 + r1;
#pragma unroll
    for (int ni = 0; ni < 8; ni++) {
        *(__half2*)&g_attnh[row0 * DIM + h * HDIM + ni * 8 + 2 * tg] =
            __floats2half2_rn(o[ni][0] * inv0, o[ni][1] * inv0);
        *(__half2*)&g_attnh[row1 * DIM + h * HDIM + ni * 8 + 2 * tg] =
            __floats2half2_rn(o[ni][2] * inv1, o[ni][3] * inv1);
    }
}

// ---------------------------------------------------------------------------
extern "C" void kernel_launch(void* const* d_in, const int* in_sizes, int n_in,
                              void* d_out, int out_size)
{
    const float* x    = (const float*)d_in[0];
    const int*   mask = (const int*)d_in[1];     // bool widened to int32 by harness
    const float* pos  = (const float*)d_in[2];
    const float* Wqk  = (const float*)d_in[3];
    const float* Wv   = (const float*)d_in[4];
    const float* Wout = (const float*)d_in[5];
    const float* bout = (const float*)d_in[6];
    float*       out  = (float*)d_out;

    cudaFuncSetAttribute(qkv_gemm_kernel, cudaFuncAttributeMaxDynamicSharedMemorySize,
                         GEMM_SMEM_BYTES);
    cudaFuncSetAttribute(out_gemm_kernel, cudaFuncAttributeMaxDynamicSharedMemorySize,
                         GEMM_SMEM_BYTES);
    cudaFuncSetAttribute(attn_kernel, cudaFuncAttributeMaxDynamicSharedMemorySize,
                         ATT_SMEM_BYTES);

    __half *d_x16, *d_w16, *d_wo16;
    cudaGetSymbolAddress((void**)&d_x16,  g_x16);
    cudaGetSymbolAddress((void**)&d_w16,  g_w16);
    cudaGetSymbolAddress((void**)&d_wo16, g_wo16);

    {   // prep: fp32 -> fp16 conversions
        int n4 = MROWS * DIM / 4;
        tohalf_kernel<<<(n4 + 255) / 256, 256>>>(
            (const float4*)x, (__half2*)d_x16, n4);
        n4 = 2 * DIM * DIM / 4;
        tohalf_kernel<<<(n4 + 255) / 256, 256>>>(
            (const float4*)Wqk, (__half2*)d_w16, n4);
        n4 = DIM * DIM / 4;
        tohalf_kernel<<<(n4 + 255) / 256, 256>>>(
            (const float4*)Wv, (__half2*)(d_w16 + 2 * DIM * DIM), n4);
        tohalf_kernel<<<(n4 + 255) / 256, 256>>>(
            (const float4*)Wout, (__half2*)d_wo16, n4);
    }
    {   // QKV projection: M=8192, N=3072
        dim3 grid(QKVN / 128, MROWS / 128);
        qkv_gemm_kernel<<<grid, 256, GEMM_SMEM_BYTES>>>(pos);
    }
    {   // Attention: 8 row-tiles x 128 (b,h) pairs
        dim3 grid(SEQ / 128, BATCH * HEADS);
        attn_kernel<<<grid, 256, ATT_SMEM_BYTES>>>(mask);
    }
    {   // Output projection: M=8192, N=1024
        dim3 grid(DIM / 128, MROWS / 128);
        out_gemm_kernel<<<grid, 256, GEMM_SMEM_BYTES>>>(bout, out);
    }
}

// round 16
// speedup vs baseline: 2.1584x; 1.0842x over previous
#include <cuda_runtime.h>
#include <cuda_bf16.h>
#include <cuda_fp16.h>
#include <cstddef>
#include <cstdint>

// Problem constants
#define BATCH 8
#define SEQ   1024
#define DIM   1024
#define HEADS 16
#define HDIM  64
#define MROWS (BATCH * SEQ)          // 8192
#define QKVN  (3 * DIM)              // 3072
#define SCALE 0.03125f               // DIM^-0.5 = 1/32
#define SCALE_L2E 0.045084441522258674f   // SCALE * log2(e)
#define MASKV (-3.402823466e38f)
#define NEGINF (-__int_as_float(0x7f800000) * 1.0f)

// Scratch (static device globals: allocation-free rule)
__device__ __half g_qh[BATCH * HEADS * SEQ * HDIM];   // Q in fp16
__device__ __half g_kh[BATCH * HEADS * SEQ * HDIM];   // K in fp16
__device__ __half g_vh[BATCH * HEADS * SEQ * HDIM];   // V in fp16
__device__ __half g_attnh[BATCH * SEQ * DIM];         // attention out, fp16
// fp16 input copies (conversion hoisted out of GEMM hot loops)
__device__ __half g_x16[MROWS * DIM];
__device__ __half g_w16[QKVN * DIM];                  // [Wqk; Wv]
__device__ __half g_wo16[DIM * DIM];

// ---------------------------------------------------------------------------
// helpers
// ---------------------------------------------------------------------------
__device__ __forceinline__ float ex2f(float x) {
    float y; asm("ex2.approx.f32 %0, %1;" : "=f"(y) : "f"(x));
    return y;
}
__device__ __forceinline__ void mma_f16_16x8x16(float* c, const uint32_t* a, const uint32_t* b) {
    asm volatile(
        "mma.sync.aligned.m16n8k16.row.col.f32.f16.f16.f32 "
        "{%0,%1,%2,%3}, {%4,%5,%6,%7}, {%8,%9}, {%0,%1,%2,%3};"
        : "+f"(c[0]), "+f"(c[1]), "+f"(c[2]), "+f"(c[3])
        : "r"(a[0]), "r"(a[1]), "r"(a[2]), "r"(a[3]),
          "r"(b[0]), "r"(b[1]));
}
__device__ __forceinline__ uint32_t smem_u32(const void* p) {
    return (uint32_t)__cvta_generic_to_shared(p);
}
__device__ __forceinline__ void ldsm_x4(uint32_t addr, uint32_t* r) {
    asm volatile("ldmatrix.sync.aligned.m8n8.x4.shared.b16 {%0,%1,%2,%3}, [%4];"
                 : "=r"(r[0]), "=r"(r[1]), "=r"(r[2]), "=r"(r[3]) : "r"(addr));
}
__device__ __forceinline__ void ldsm_x4_t(uint32_t addr, uint32_t* r) {
    asm volatile("ldmatrix.sync.aligned.m8n8.x4.trans.shared.b16 {%0,%1,%2,%3}, [%4];"
                 : "=r"(r[0]), "=r"(r[1]), "=r"(r[2]), "=r"(r[3]) : "r"(addr));
}
__device__ __forceinline__ void cp16(void* smem, const void* g) {
    asm volatile("cp.async.cg.shared.global [%0], [%1], 16;"
                 :: "r"(smem_u32(smem)), "l"(g));
}
__device__ __forceinline__ void cp_commit() {
    asm volatile("cp.async.commit_group;");
}

// ---------------------------------------------------------------------------
// Kernel 0: fp32 -> fp16 conversion (vectorized)
// ---------------------------------------------------------------------------
__global__ __launch_bounds__(256) void tohalf_kernel(
    const float4* __restrict__ src, __half2* __restrict__ dst, int n4)
{
    int i = blockIdx.x * 256 + threadIdx.x;
    if (i < n4) {
        float4 v = src[i];
        dst[2 * i]     = __floats2half2_rn(v.x, v.y);
        dst[2 * i + 1] = __floats2half2_rn(v.z, v.w);
    }
}

// ---------------------------------------------------------------------------
// fp16 GEMM core: 128x128 tile, K-chunk 64, cp.async 3-stage ring, ldmatrix
// fragment loads, f16 m16n8k16 MMA with fp32 accum. 8 warps (2M x 4N),
// warp tile 64x32. Row stride 72 halves (144 B) - proven conflict-free.
// ---------------------------------------------------------------------------
#define GPAD16 72

struct GemmAcc { float acc[4][4][4]; };

__device__ __forceinline__ void gemm16_core(
    const __half* __restrict__ Abase, const __half* __restrict__ Bbase,
    int bm, int bn, char* smc, GemmAcc& g)
{
    __half* As = (__half*)smc;                        // [3][128][GPAD16]
    __half* Bs = (__half*)(smc + 3 * 128 * GPAD16 * 2);

    const int tid = threadIdx.x;
    const int lane = tid & 31;
    const int wid = tid >> 5;
    const int wm = (wid & 1) * 64;
    const int wn = (wid >> 1) * 32;
    const int l15 = lane & 15, l4 = lane >> 4;

    const uint32_t aBase = smem_u32(As) + (uint32_t)(((wm + l15) * GPAD16 + l4 * 8) * 2);
    const int rowB = wn + ((lane >> 4) & 1) * 8 + (lane & 7);
    const int colB = ((lane >> 3) & 1) * 8;
    const uint32_t bBase = smem_u32(Bs) + (uint32_t)((rowB * GPAD16 + colB) * 2);
    const uint32_t STAGE = 128 * GPAD16 * 2;

#pragma unroll
    for (int mi = 0; mi < 4; mi++)
#pragma unroll
        for (int ni = 0; ni < 4; ni++)
#pragma unroll
            for (int r = 0; r < 4; r++) g.acc[mi][ni][r] = 0.f;

    auto load_tiles = [&](int st, int k0) {
#pragma unroll
        for (int i = tid; i < 128 * 8; i += 256) {
            int row = i >> 3, c8 = (i & 7) * 8;
            cp16(As + (size_t)st * 128 * GPAD16 + row * GPAD16 + c8,
                 Abase + (size_t)(bm + row) * DIM + k0 + c8);
        }
#pragma unroll
        for (int i = tid; i < 128 * 8; i += 256) {
            int row = i >> 3, c8 = (i & 7) * 8;
            cp16(Bs + (size_t)st * 128 * GPAD16 + row * GPAD16 + c8,
                 Bbase + (size_t)(bn + row) * DIM + k0 + c8);
        }
    };

    load_tiles(0, 0);   cp_commit();
    load_tiles(1, 64);  cp_commit();

    const int NT = DIM / 64;  // 16
    for (int it = 0; it < NT; it++) {
        int cur = it % 3;
        if (it + 2 < NT) {
            load_tiles((it + 2) % 3, (it + 2) * 64);
            cp_commit();
            asm volatile("cp.async.wait_group 2;");
        } else if (it + 1 < NT) {
            asm volatile("cp.async.wait_group 1;");
        } else {
            asm volatile("cp.async.wait_group 0;");
        }
        __syncthreads();

        const uint32_t aCur = aBase + cur * STAGE;
        const uint32_t bCur = bBase + cur * STAGE;
#pragma unroll
        for (int kc = 0; kc < 4; kc++) {
            uint32_t a[4][4];
#pragma unroll
            for (int mi = 0; mi < 4; mi++)
                ldsm_x4(aCur + (uint32_t)((mi * 16 * GPAD16 + kc * 16) * 2), a[mi]);
            uint32_t b[2][4];
#pragma unroll
            for (int np = 0; np < 2; np++)
                ldsm_x4(bCur + (uint32_t)((np * 16 * GPAD16 + kc * 16) * 2), b[np]);
#pragma unroll
            for (int mi = 0; mi < 4; mi++)
#pragma unroll
                for (int ni = 0; ni < 4; ni++)
                    mma_f16_16x8x16(g.acc[mi][ni], a[mi], &b[ni >> 1][(ni & 1) * 2]);
        }
        __syncthreads();
    }
}

#define GEMM_SMEM_BYTES (6 * 128 * GPAD16 * 2)   // 110592

// ---------------------------------------------------------------------------
// Kernel 1: fused QKV projection (fp16 core). Epilogue: stage fp32 acc in
// smem, then one coalesced pass: +pos (fp32), convert, 16B half stores.
// ---------------------------------------------------------------------------
#define EPAD 132   // fp32 staging stride (528 B, 16B-aligned)

__global__ __launch_bounds__(256) void qkv_gemm_kernel(const float* __restrict__ pos)
{
    extern __shared__ char smc[];
    const int bm = blockIdx.y * 128;
    const int bn = blockIdx.x * 128;
    const int tid = threadIdx.x;
    const int lane = tid & 31;
    const int wid = tid >> 5;
    const int gid = lane >> 2, tg = lane & 3;
    const int wm = (wid & 1) * 64;
    const int wn = (wid >> 1) * 32;

    GemmAcc g;
    gemm16_core(g_x16, g_w16, bm, bn, smc, g);

    // stage acc in smem (fp32), then coalesced global pass
    float (*ep)[EPAD] = (float(*)[EPAD])smc;
#pragma unroll
    for (int mi = 0; mi < 4; mi++)
#pragma unroll
        for (int ni = 0; ni < 4; ni++)
#pragma unroll
            for (int r = 0; r < 4; r++) {
                int rl = wm + mi * 16 + gid + ((r >= 2) ? 8 : 0);
                int cl = wn + ni * 8 + 2 * tg + (r & 1);
                ep[rl][cl] = g.acc[mi][ni][r];
            }
    __syncthreads();

    for (int idx = tid; idx < 128 * 16; idx += 256) {
        int row = idx >> 4, cc = (idx & 15) * 8;
        int m = bm + row, gn = bn + cc;
        int b = m >> 10, rowm = m & 1023;
        float4 v0 = *(const float4*)&ep[row][cc];
        float4 v1 = *(const float4*)&ep[row][cc + 4];
        __align__(16) __half hv[8];
        if (gn < 2 * DIM) {
            int c = (gn < DIM) ? gn : gn - DIM;
            const float* pp = &pos[(size_t)m * DIM + c];
            float4 p0 = *(const float4*)&pp[0];
            float4 p1 = *(const float4*)&pp[4];
            hv[0] = __float2half(v0.x + p0.x); hv[1] = __float2half(v0.y + p0.y);
            hv[2] = __float2half(v0.z + p0.z); hv[3] = __float2half(v0.w + p0.w);
            hv[4] = __float2half(v1.x + p1.x); hv[5] = __float2half(v1.y + p1.y);
            hv[6] = __float2half(v1.z + p1.z); hv[7] = __float2half(v1.w + p1.w);
            __half* dst = (gn < DIM) ? g_qh : g_kh;
            int hh = c >> 6, d = c & 63;
            *(float4*)&dst[(((size_t)b * HEADS + hh) * SEQ + rowm) * HDIM + d] =
                *(const float4*)hv;
        } else {
            int c = gn - 2 * DIM;
            hv[0] = __float2half(v0.x); hv[1] = __float2half(v0.y);
            hv[2] = __float2half(v0.z); hv[3] = __float2half(v0.w);
            hv[4] = __float2half(v1.x); hv[5] = __float2half(v1.y);
            hv[6] = __float2half(v1.z); hv[7] = __float2half(v1.w);
            int hh = c >> 6, d = c & 63;
            *(float4*)&g_vh[(((size_t)b * HEADS + hh) * SEQ + rowm) * HDIM + d] =
                *(const float4*)hv;
        }
    }
}

// ---------------------------------------------------------------------------
// Kernel 3: output projection (fp16 core). out = attn @ W_out^T + b_out
// ---------------------------------------------------------------------------
__global__ __launch_bounds__(256) void out_gemm_kernel(
    const float* __restrict__ bout, float* __restrict__ out)
{
    extern __shared__ char smc[];
    const int bm = blockIdx.y * 128;
    const int bn = blockIdx.x * 128;
    const int lane = threadIdx.x & 31;
    const int wid = threadIdx.x >> 5;
    const int gid = lane >> 2, tg = lane & 3;
    const int wm = (wid & 1) * 64;
    const int wn = (wid >> 1) * 32;

    GemmAcc g;
    gemm16_core(g_attnh, g_wo16, bm, bn, smc, g);

#pragma unroll
    for (int mi = 0; mi < 4; mi++) {
#pragma unroll
        for (int ni = 0; ni < 4; ni++) {
#pragma unroll
            for (int r = 0; r < 4; r++) {
                int m = bm + wm + mi * 16 + gid + ((r >= 2) ? 8 : 0);
                int gn = bn + wn + ni * 8 + 2 * tg + (r & 1);
                out[(size_t)m * DIM + gn] = g.acc[mi][ni][r] + bout[gn];
            }
        }
    }
}

// ---------------------------------------------------------------------------
// Kernel 2: flash attention, fully fp16 MMA (R15 structure, label cleaned).
// ---------------------------------------------------------------------------
#define HPAD 72           // b16 row stride for Q/P, K, V tiles (144 B)
#define ATT_QP_BYTES   (128 * HPAD * 2)          // 18432
#define ATT_K_BYTES    (2 * 64 * HPAD * 2)       // 18432
#define ATT_V_BYTES    (2 * 64 * HPAD * 2)       // 18432
#define ATT_KM_BYTES   (2 * 64 * 4)              // 512
#define ATT_SMEM_BYTES (ATT_QP_BYTES + ATT_K_BYTES + ATT_V_BYTES + ATT_KM_BYTES) // 55808

__global__ __launch_bounds__(256) void attn_kernel(const int* __restrict__ mask)
{
    extern __shared__ char smc[];
    __half* QP = (__half*)smc;                         // Q tile, later P
    __half* Kh = (__half*)(smc + ATT_QP_BYTES);        // [2*64][HPAD]
    __half* Vh = (__half*)(smc + ATT_QP_BYTES + ATT_K_BYTES);
    float* kmB = (float*)(smc + ATT_QP_BYTES + ATT_K_BYTES + ATT_V_BYTES);

    const int bh = blockIdx.y;
    const int b = bh >> 4, h = bh & 15;
    const int i0 = blockIdx.x * 128;
    const int tid = threadIdx.x;
    const int lane = tid & 31, wid = tid >> 5;
    const int gid = lane >> 2, tg = lane & 3;
    const int r0 = wid * 16 + gid;
    const int r1 = r0 + 8;

    const int l15 = lane & 15, l4 = lane >> 4;
    const uint32_t qpBase = smem_u32(QP) + (uint32_t)(((wid * 16 + l15) * HPAD + l4 * 8) * 2);
    const int rowK = ((lane >> 4) & 1) * 8 + (lane & 7);
    const int colK = ((lane >> 3) & 1) * 8;
    const uint32_t kBase = smem_u32(Kh) + (uint32_t)((rowK * HPAD + colK) * 2);
    const uint32_t vBase = smem_u32(Vh) + (uint32_t)((l15 * HPAD + l4 * 8) * 2);
    const uint32_t HSTAGE = 64 * HPAD * 2;

    const __half* qb = g_qh + ((size_t)bh * SEQ + i0) * HDIM;
    const __half* kb = g_kh + (size_t)bh * SEQ * HDIM;
    const __half* vb = g_vh + (size_t)bh * SEQ * HDIM;

    auto load_kv = [&](int st, int j0) {
        __half* K = Kh + st * 64 * HPAD;
        __half* V = Vh + st * 64 * HPAD;
#pragma unroll
        for (int i = tid; i < 64 * 8; i += 256) {
            int row = i >> 3, c8 = (i & 7) * 8;
            cp16(&K[row * HPAD + c8], &kb[(size_t)(j0 + row) * HDIM + c8]);
            cp16(&V[row * HPAD + c8], &vb[(size_t)(j0 + row) * HDIM + c8]);
        }
    };
    auto load_km = [&](int st, int j0) {
        if (tid < 64) {
            int gj = j0 + tid;
            kmB[st * 64 + tid] =
                (gj == 0) ? 1.f : (mask[(size_t)b * (SEQ - 1) + gj - 1] ? 1.f : 0.f);
        }
    };

    load_kv(0, 0);
    cp_commit();
    load_km(0, 0);

    for (int i = tid; i < 128 * 8; i += 256) {
        int row = i >> 3, c8 = (i & 7) * 8;
        *(float4*)&QP[row * HPAD + c8] = *(const float4*)&qb[(size_t)row * HDIM + c8];
    }
    __syncthreads();

    uint32_t qa[4][4];
#pragma unroll
    for (int kc = 0; kc < 4; kc++)
        ldsm_x4(qpBase + (uint32_t)(kc * 16 * 2), qa[kc]);

    const int gi0 = i0 + r0, gi1 = i0 + r1;
    const bool qok0 = (gi0 == 0) || (mask[(size_t)b * (SEQ - 1) + gi0 - 1] != 0);
    const bool qok1 = (gi1 == 0) || (mask[(size_t)b * (SEQ - 1) + gi1 - 1] != 0);

    float m0 = NEGINF, m1 = NEGINF, l0 = 0.f, l1 = 0.f;
    float o[8][4] = {};

    __half* Pb = QP;

    const int NT = SEQ / 64;   // 16
    for (int it = 0; it < NT; it++) {
        const int cur = it & 1;
        if (it + 1 < NT) {
            load_kv(cur ^ 1, (it + 1) * 64);
            cp_commit();
            load_km(cur ^ 1, (it + 1) * 64);
            asm volatile("cp.async.wait_group 1;");
        } else {
            asm volatile("cp.async.wait_group 0;");
        }
        __syncthreads();

        const float* km = kmB + cur * 64;
        const uint32_t kCur = kBase + cur * HSTAGE;
        const uint32_t vCur = vBase + cur * HSTAGE;

        // S = Q K^T (f16 m16n8k16)
        float s[8][4] = {};
#pragma unroll
        for (int kc = 0; kc < 4; kc++) {
            uint32_t kf[4][4];
#pragma unroll
            for (int np = 0; np < 4; np++)
                ldsm_x4(kCur + (uint32_t)((np * 16 * HPAD + kc * 16) * 2), kf[np]);
#pragma unroll
            for (int ni = 0; ni < 8; ni++)
                mma_f16_16x8x16(s[ni], qa[kc], &kf[ni >> 1][(ni & 1) * 2]);
        }

        float rmax0 = NEGINF, rmax1 = NEGINF;
#pragma unroll
        for (int ni = 0; ni < 8; ni++) {
            bool k0ok = km[ni * 8 + 2 * tg] != 0.f;
            bool k1ok = km[ni * 8 + 2 * tg + 1] != 0.f;
            s[ni][0] = (qok0 && k0ok) ? s[ni][0] * SCALE_L2E : MASKV;
            s[ni][1] = (qok0 && k1ok) ? s[ni][1] * SCALE_L2E : MASKV;
            s[ni][2] = (qok1 && k0ok) ? s[ni][2] * SCALE_L2E : MASKV;
            s[ni][3] = (qok1 && k1ok) ? s[ni][3] * SCALE_L2E : MASKV;
            rmax0 = fmaxf(rmax0, fmaxf(s[ni][0], s[ni][1]));
            rmax1 = fmaxf(rmax1, fmaxf(s[ni][2], s[ni][3]));
        }
        rmax0 = fmaxf(rmax0, __shfl_xor_sync(0xffffffffu, rmax0, 1));
        rmax0 = fmaxf(rmax0, __shfl_xor_sync(0xffffffffu, rmax0, 2));
        rmax1 = fmaxf(rmax1, __shfl_xor_sync(0xffffffffu, rmax1, 1));
        rmax1 = fmaxf(rmax1, __shfl_xor_sync(0xffffffffu, rmax1, 2));

        float nm0 = fmaxf(m0, rmax0), nm1 = fmaxf(m1, rmax1);
        float fac0 = ex2f(m0 - nm0), fac1 = ex2f(m1 - nm1);
        m0 = nm0; m1 = nm1;

        float sum0 = 0.f, sum1 = 0.f;
#pragma unroll
        for (int ni = 0; ni < 8; ni++) {
            float p0 = ex2f(s[ni][0] - m0);
            float p1 = ex2f(s[ni][1] - m0);
            float p2 = ex2f(s[ni][2] - m1);
            float p3 = ex2f(s[ni][3] - m1);
            sum0 += p0 + p1; sum1 += p2 + p3;
            *(__half2*)&Pb[r0 * HPAD + ni * 8 + 2 * tg] = __floats2half2_rn(p0, p1);
            *(__half2*)&Pb[r1 * HPAD + ni * 8 + 2 * tg] = __floats2half2_rn(p2, p3);
        }
        sum0 += __shfl_xor_sync(0xffffffffu, sum0, 1);
        sum0 += __shfl_xor_sync(0xffffffffu, sum0, 2);
        sum1 += __shfl_xor_sync(0xffffffffu, sum1, 1);
        sum1 += __shfl_xor_sync(0xffffffffu, sum1, 2);
        l0 = l0 * fac0 + sum0;
        l1 = l1 * fac1 + sum1;

#pragma unroll
        for (int ni = 0; ni < 8; ni++) {
            o[ni][0] *= fac0; o[ni][1] *= fac0;
            o[ni][2] *= fac1; o[ni][3] *= fac1;
        }
        __syncwarp();

#pragma unroll
        for (int ks = 0; ks < 4; ks++) {
            uint32_t pf[4];
            ldsm_x4(qpBase + (uint32_t)(ks * 16 * 2), pf);
#pragma unroll
            for (int np = 0; np < 4; np++) {
                uint32_t vf[4];
                ldsm_x4_t(vCur + (uint32_t)((ks * 16 * HPAD + np * 16) * 2), vf);
                mma_f16_16x8x16(o[np * 2],     pf, &vf[0]);
                mma_f16_16x8x16(o[np * 2 + 1], pf, &vf[2]);
            }
        }
        __syncthreads();
    }

    float inv0 = 1.f / l0, inv1 = 1.f / l1;
    size_t row0 = (size_t)b * SEQ + i0 + r0;
    size_t row1 = (size_t)b * SEQ + i0 + r1;
#pragma unroll
    for (int ni = 0; ni < 8; ni++) {
        *(__half2*)&g_attnh[row0 * DIM + h * HDIM + ni * 8 + 2 * tg] =
            __floats2half2_rn(o[ni][0] * inv0, o[ni][1] * inv0);
        *(__half2*)&g_attnh[row1 * DIM + h * HDIM + ni * 8 + 2 * tg] =
            __floats2half2_rn(o[ni][2] * inv1, o[ni][3] * inv1);
    }
}

// ---------------------------------------------------------------------------
extern "C" void kernel_launch(void* const* d_in, const int* in_sizes, int n_in,
                              void* d_out, int out_size)
{
    const float* x    = (const float*)d_in[0];
    const int*   mask = (const int*)d_in[1];     // bool widened to int32 by harness
    const float* pos  = (const float*)d_in[2];
    const float* Wqk  = (const float*)d_in[3];
    const float* Wv   = (const float*)d_in[4];
    const float* Wout = (const float*)d_in[5];
    const float* bout = (const float*)d_in[6];
    float*       out  = (float*)d_out;

    cudaFuncSetAttribute(qkv_gemm_kernel, cudaFuncAttributeMaxDynamicSharedMemorySize,
                         GEMM_SMEM_BYTES);
    cudaFuncSetAttribute(out_gemm_kernel, cudaFuncAttributeMaxDynamicSharedMemorySize,
                         GEMM_SMEM_BYTES);
    cudaFuncSetAttribute(attn_kernel, cudaFuncAttributeMaxDynamicSharedMemorySize,
                         ATT_SMEM_BYTES);

    __half *d_x16, *d_w16, *d_wo16;
    cudaGetSymbolAddress((void**)&d_x16,  g_x16);
    cudaGetSymbolAddress((void**)&d_w16,  g_w16);
    cudaGetSymbolAddress((void**)&d_wo16, g_wo16);

    {   // prep: fp32 -> fp16 conversions
        int n4 = MROWS * DIM / 4;
        tohalf_kernel<<<(n4 + 255) / 256, 256>>>(
            (const float4*)x, (__half2*)d_x16, n4);
        n4 = 2 * DIM * DIM / 4;
        tohalf_kernel<<<(n4 + 255) / 256, 256>>>(
            (const float4*)Wqk, (__half2*)d_w16, n4);
        n4 = DIM * DIM / 4;
        tohalf_kernel<<<(n4 + 255) / 256, 256>>>(
            (const float4*)Wv, (__half2*)(d_w16 + 2 * DIM * DIM), n4);
        tohalf_kernel<<<(n4 + 255) / 256, 256>>>(
            (const float4*)Wout, (__half2*)d_wo16, n4);
    }
    {   // QKV projection: M=8192, N=3072
        dim3 grid(QKVN / 128, MROWS / 128);
        qkv_gemm_kernel<<<grid, 256, GEMM_SMEM_BYTES>>>(pos);
    }
    {   // Attention: 8 row-tiles x 128 (b,h) pairs
        dim3 grid(SEQ / 128, BATCH * HEADS);
        attn_kernel<<<grid, 256, ATT_SMEM_BYTES>>>(mask);
    }
    {   // Output projection: M=8192, N=1024
        dim3 grid(DIM / 128, MROWS / 128);
        out_gemm_kernel<<<grid, 256, GEMM_SMEM_BYTES>>>(bout, out);
    }
}

// round 17
// speedup vs baseline: 2.2946x; 1.0631x over previous
#include <cuda_runtime.h>
#include <cuda_bf16.h>
#include <cuda_fp16.h>
#include <cstddef>
#include <cstdint>

// Problem constants
#define BATCH 8
#define SEQ   1024
#define DIM   1024
#define HEADS 16
#define HDIM  64
#define MROWS (BATCH * SEQ)          // 8192
#define QKVN  (3 * DIM)              // 3072
#define SCALE 0.03125f               // DIM^-0.5 = 1/32
#define SCALE_L2E 0.045084441522258674f   // SCALE * log2(e)
#define MASKV (-3.402823466e38f)
#define NEGINF (-__int_as_float(0x7f800000) * 1.0f)

// Scratch (static device globals: allocation-free rule)
__device__ __half g_qh[BATCH * HEADS * SEQ * HDIM];   // Q in fp16
__device__ __half g_kh[BATCH * HEADS * SEQ * HDIM];   // K in fp16
__device__ __half g_vh[BATCH * HEADS * SEQ * HDIM];   // V in fp16
__device__ __half g_attnh[BATCH * SEQ * DIM];         // attention out, fp16
// fp16 input copies (conversion hoisted out of GEMM hot loops)
__device__ __half g_x16[MROWS * DIM];
__device__ __half g_w16[QKVN * DIM];                  // [Wqk; Wv]
__device__ __half g_wo16[DIM * DIM];

// ---------------------------------------------------------------------------
// helpers
// ---------------------------------------------------------------------------
__device__ __forceinline__ float ex2f(float x) {
    float y; asm("ex2.approx.f32 %0, %1;" : "=f"(y) : "f"(x));
    return y;
}
__device__ __forceinline__ void mma_f16_16x8x16(float* c, const uint32_t* a, const uint32_t* b) {
    asm volatile(
        "mma.sync.aligned.m16n8k16.row.col.f32.f16.f16.f32 "
        "{%0,%1,%2,%3}, {%4,%5,%6,%7}, {%8,%9}, {%0,%1,%2,%3};"
        : "+f"(c[0]), "+f"(c[1]), "+f"(c[2]), "+f"(c[3])
        : "r"(a[0]), "r"(a[1]), "r"(a[2]), "r"(a[3]),
          "r"(b[0]), "r"(b[1]));
}
__device__ __forceinline__ uint32_t smem_u32(const void* p) {
    return (uint32_t)__cvta_generic_to_shared(p);
}
__device__ __forceinline__ void ldsm_x4(uint32_t addr, uint32_t* r) {
    asm volatile("ldmatrix.sync.aligned.m8n8.x4.shared.b16 {%0,%1,%2,%3}, [%4];"
                 : "=r"(r[0]), "=r"(r[1]), "=r"(r[2]), "=r"(r[3]) : "r"(addr));
}
__device__ __forceinline__ void ldsm_x4_t(uint32_t addr, uint32_t* r) {
    asm volatile("ldmatrix.sync.aligned.m8n8.x4.trans.shared.b16 {%0,%1,%2,%3}, [%4];"
                 : "=r"(r[0]), "=r"(r[1]), "=r"(r[2]), "=r"(r[3]) : "r"(addr));
}
__device__ __forceinline__ void cp16(void* smem, const void* g) {
    asm volatile("cp.async.cg.shared.global [%0], [%1], 16;"
                 :: "r"(smem_u32(smem)), "l"(g));
}
__device__ __forceinline__ void cp_commit() {
    asm volatile("cp.async.commit_group;");
}

// ---------------------------------------------------------------------------
// Kernel 0: fused fp32 -> fp16 conversion for all four inputs (one launch)
// Regions in float4 units: x 2097152 | Wqk 524288 | Wv 262144 | Wout 262144
// ---------------------------------------------------------------------------
#define P_X   2097152
#define P_WQK  524288
#define P_WV   262144
#define P_WO   262144
#define P_TOT (P_X + P_WQK + P_WV + P_WO)   // 3145728

__global__ __launch_bounds__(256) void prep_kernel(
    const float4* __restrict__ x, const float4* __restrict__ wqk,
    const float4* __restrict__ wv, const float4* __restrict__ wout,
    __half2* __restrict__ x16, __half2* __restrict__ w16,
    __half2* __restrict__ wo16)
{
    int i = blockIdx.x * 256 + threadIdx.x;
    if (i >= P_TOT) return;
    const float4* src; __half2* dst; int off;
    if (i < P_X)                    { src = x;    dst = x16;  off = i; }
    else if (i < P_X + P_WQK)       { src = wqk;  dst = w16;  off = i - P_X; }
    else if (i < P_X + P_WQK + P_WV){ src = wv;   dst = w16 + DIM * DIM; off = i - P_X - P_WQK; }
    else                            { src = wout; dst = wo16; off = i - P_X - P_WQK - P_WV; }
    float4 v = src[off];
    dst[2 * off]     = __floats2half2_rn(v.x, v.y);
    dst[2 * off + 1] = __floats2half2_rn(v.z, v.w);
}

// ---------------------------------------------------------------------------
// fp16 GEMM core: 128x128 tile, K-chunk 64, cp.async 3-stage ring with a
// SINGLE __syncthreads per iteration (loads issued after the sync; the stage
// written at iter i was read at iter i-1, which the sync ordered). Ends with
// a sync so callers may overlay the smem with an epilogue staging buffer.
// ---------------------------------------------------------------------------
#define GPAD16 72

struct GemmAcc { float acc[4][4][4]; };

__device__ __forceinline__ void gemm16_core(
    const __half* __restrict__ Abase, const __half* __restrict__ Bbase,
    int bm, int bn, char* smc, GemmAcc& g)
{
    __half* As = (__half*)smc;                        // [3][128][GPAD16]
    __half* Bs = (__half*)(smc + 3 * 128 * GPAD16 * 2);

    const int tid = threadIdx.x;
    const int lane = tid & 31;
    const int wid = tid >> 5;
    const int wm = (wid & 1) * 64;
    const int wn = (wid >> 1) * 32;
    const int l15 = lane & 15, l4 = lane >> 4;

    const uint32_t aBase = smem_u32(As) + (uint32_t)(((wm + l15) * GPAD16 + l4 * 8) * 2);
    const int rowB = wn + ((lane >> 4) & 1) * 8 + (lane & 7);
    const int colB = ((lane >> 3) & 1) * 8;
    const uint32_t bBase = smem_u32(Bs) + (uint32_t)((rowB * GPAD16 + colB) * 2);
    const uint32_t STAGE = 128 * GPAD16 * 2;

#pragma unroll
    for (int mi = 0; mi < 4; mi++)
#pragma unroll
        for (int ni = 0; ni < 4; ni++)
#pragma unroll
            for (int r = 0; r < 4; r++) g.acc[mi][ni][r] = 0.f;

    auto load_tiles = [&](int st, int k0) {
#pragma unroll
        for (int i = tid; i < 128 * 8; i += 256) {
            int row = i >> 3, c8 = (i & 7) * 8;
            cp16(As + (size_t)st * 128 * GPAD16 + row * GPAD16 + c8,
                 Abase + (size_t)(bm + row) * DIM + k0 + c8);
        }
#pragma unroll
        for (int i = tid; i < 128 * 8; i += 256) {
            int row = i >> 3, c8 = (i & 7) * 8;
            cp16(Bs + (size_t)st * 128 * GPAD16 + row * GPAD16 + c8,
                 Bbase + (size_t)(bn + row) * DIM + k0 + c8);
        }
    };

    load_tiles(0, 0);   cp_commit();
    load_tiles(1, 64);  cp_commit();

    const int NT = DIM / 64;  // 16
    for (int it = 0; it < NT; it++) {
        int cur = it % 3;
        if (it + 1 < NT) asm volatile("cp.async.wait_group 1;");
        else             asm volatile("cp.async.wait_group 0;");
        __syncthreads();
        if (it + 2 < NT) {
            load_tiles((it + 2) % 3, (it + 2) * 64);
            cp_commit();
        }

        const uint32_t aCur = aBase + cur * STAGE;
        const uint32_t bCur = bBase + cur * STAGE;
#pragma unroll
        for (int kc = 0; kc < 4; kc++) {
            uint32_t a[4][4];
#pragma unroll
            for (int mi = 0; mi < 4; mi++)
                ldsm_x4(aCur + (uint32_t)((mi * 16 * GPAD16 + kc * 16) * 2), a[mi]);
            uint32_t b[2][4];
#pragma unroll
            for (int np = 0; np < 2; np++)
                ldsm_x4(bCur + (uint32_t)((np * 16 * GPAD16 + kc * 16) * 2), b[np]);
#pragma unroll
            for (int mi = 0; mi < 4; mi++)
#pragma unroll
                for (int ni = 0; ni < 4; ni++)
                    mma_f16_16x8x16(g.acc[mi][ni], a[mi], &b[ni >> 1][(ni & 1) * 2]);
        }
        // no bottom sync: next iteration's top sync orders stage reuse
    }
    __syncthreads();   // protect smem before caller's epilogue overlay
}

#define GEMM_SMEM_BYTES (6 * 128 * GPAD16 * 2)   // 110592
#define EPAD 132   // fp32 staging stride

// ---------------------------------------------------------------------------
// Kernel 1: fused QKV projection (fp16 core), coalesced epilogue.
// ---------------------------------------------------------------------------
__global__ __launch_bounds__(256) void qkv_gemm_kernel(const float* __restrict__ pos)
{
    extern __shared__ char smc[];
    const int bm = blockIdx.y * 128;
    const int bn = blockIdx.x * 128;
    const int tid = threadIdx.x;
    const int lane = tid & 31;
    const int wid = tid >> 5;
    const int gid = lane >> 2, tg = lane & 3;
    const int wm = (wid & 1) * 64;
    const int wn = (wid >> 1) * 32;

    GemmAcc g;
    gemm16_core(g_x16, g_w16, bm, bn, smc, g);

    float (*ep)[EPAD] = (float(*)[EPAD])smc;
#pragma unroll
    for (int mi = 0; mi < 4; mi++)
#pragma unroll
        for (int ni = 0; ni < 4; ni++)
#pragma unroll
            for (int r = 0; r < 4; r++) {
                int rl = wm + mi * 16 + gid + ((r >= 2) ? 8 : 0);
                int cl = wn + ni * 8 + 2 * tg + (r & 1);
                ep[rl][cl] = g.acc[mi][ni][r];
            }
    __syncthreads();

    for (int idx = tid; idx < 128 * 16; idx += 256) {
        int row = idx >> 4, cc = (idx & 15) * 8;
        int m = bm + row, gn = bn + cc;
        int b = m >> 10, rowm = m & 1023;
        float4 v0 = *(const float4*)&ep[row][cc];
        float4 v1 = *(const float4*)&ep[row][cc + 4];
        __align__(16) __half hv[8];
        if (gn < 2 * DIM) {
            int c = (gn < DIM) ? gn : gn - DIM;
            const float* pp = &pos[(size_t)m * DIM + c];
            float4 p0 = *(const float4*)&pp[0];
            float4 p1 = *(const float4*)&pp[4];
            hv[0] = __float2half(v0.x + p0.x); hv[1] = __float2half(v0.y + p0.y);
            hv[2] = __float2half(v0.z + p0.z); hv[3] = __float2half(v0.w + p0.w);
            hv[4] = __float2half(v1.x + p1.x); hv[5] = __float2half(v1.y + p1.y);
            hv[6] = __float2half(v1.z + p1.z); hv[7] = __float2half(v1.w + p1.w);
            __half* dst = (gn < DIM) ? g_qh : g_kh;
            int hh = c >> 6, d = c & 63;
            *(float4*)&dst[(((size_t)b * HEADS + hh) * SEQ + rowm) * HDIM + d] =
                *(const float4*)hv;
        } else {
            int c = gn - 2 * DIM;
            hv[0] = __float2half(v0.x); hv[1] = __float2half(v0.y);
            hv[2] = __float2half(v0.z); hv[3] = __float2half(v0.w);
            hv[4] = __float2half(v1.x); hv[5] = __float2half(v1.y);
            hv[6] = __float2half(v1.z); hv[7] = __float2half(v1.w);
            int hh = c >> 6, d = c & 63;
            *(float4*)&g_vh[(((size_t)b * HEADS + hh) * SEQ + rowm) * HDIM + d] =
                *(const float4*)hv;
        }
    }
}

// ---------------------------------------------------------------------------
// Kernel 3: output projection (fp16 core), coalesced epilogue.
// ---------------------------------------------------------------------------
__global__ __launch_bounds__(256) void out_gemm_kernel(
    const float* __restrict__ bout, float* __restrict__ out)
{
    extern __shared__ char smc[];
    const int bm = blockIdx.y * 128;
    const int bn = blockIdx.x * 128;
    const int tid = threadIdx.x;
    const int lane = tid & 31;
    const int wid = tid >> 5;
    const int gid = lane >> 2, tg = lane & 3;
    const int wm = (wid & 1) * 64;
    const int wn = (wid >> 1) * 32;

    GemmAcc g;
    gemm16_core(g_attnh, g_wo16, bm, bn, smc, g);

    float (*ep)[EPAD] = (float(*)[EPAD])smc;
#pragma unroll
    for (int mi = 0; mi < 4; mi++)
#pragma unroll
        for (int ni = 0; ni < 4; ni++)
#pragma unroll
            for (int r = 0; r < 4; r++) {
                int rl = wm + mi * 16 + gid + ((r >= 2) ? 8 : 0);
                int cl = wn + ni * 8 + 2 * tg + (r & 1);
                ep[rl][cl] = g.acc[mi][ni][r];
            }
    __syncthreads();

    for (int idx = tid; idx < 128 * 32; idx += 256) {
        int row = idx >> 5, c4 = (idx & 31) * 4;
        float4 v = *(const float4*)&ep[row][c4];
        float4 bb = *(const float4*)&bout[bn + c4];
        v.x += bb.x; v.y += bb.y; v.z += bb.z; v.w += bb.w;
        *(float4*)&out[(size_t)(bm + row) * DIM + bn + c4] = v;
    }
}

// ---------------------------------------------------------------------------
// Kernel 2: flash attention, fully fp16 MMA, 3-stage cp.async ring with a
// single __syncthreads per j-tile (same reuse argument as the GEMM core).
// ---------------------------------------------------------------------------
#define HPAD 72           // b16 row stride (144 B)
#define ATT_QP_BYTES   (128 * HPAD * 2)          // 18432
#define ATT_K_BYTES    (3 * 64 * HPAD * 2)       // 27648
#define ATT_V_BYTES    (3 * 64 * HPAD * 2)       // 27648
#define ATT_KM_BYTES   (3 * 64 * 4)              // 768
#define ATT_SMEM_BYTES (ATT_QP_BYTES + ATT_K_BYTES + ATT_V_BYTES + ATT_KM_BYTES) // 74496

__global__ __launch_bounds__(256) void attn_kernel(const int* __restrict__ mask)
{
    extern __shared__ char smc[];
    __half* QP = (__half*)smc;                         // Q tile, later P
    __half* Kh = (__half*)(smc + ATT_QP_BYTES);        // [3*64][HPAD]
    __half* Vh = (__half*)(smc + ATT_QP_BYTES + ATT_K_BYTES);
    float* kmB = (float*)(smc + ATT_QP_BYTES + ATT_K_BYTES + ATT_V_BYTES);

    const int bh = blockIdx.y;
    const int b = bh >> 4, h = bh & 15;
    const int i0 = blockIdx.x * 128;
    const int tid = threadIdx.x;
    const int lane = tid & 31, wid = tid >> 5;
    const int gid = lane >> 2, tg = lane & 3;
    const int r0 = wid * 16 + gid;
    const int r1 = r0 + 8;

    const int l15 = lane & 15, l4 = lane >> 4;
    const uint32_t qpBase = smem_u32(QP) + (uint32_t)(((wid * 16 + l15) * HPAD + l4 * 8) * 2);
    const int rowK = ((lane >> 4) & 1) * 8 + (lane & 7);
    const int colK = ((lane >> 3) & 1) * 8;
    const uint32_t kBase = smem_u32(Kh) + (uint32_t)((rowK * HPAD + colK) * 2);
    const uint32_t vBase = smem_u32(Vh) + (uint32_t)((l15 * HPAD + l4 * 8) * 2);
    const uint32_t HSTAGE = 64 * HPAD * 2;

    const __half* qb = g_qh + ((size_t)bh * SEQ + i0) * HDIM;
    const __half* kb = g_kh + (size_t)bh * SEQ * HDIM;
    const __half* vb = g_vh + (size_t)bh * SEQ * HDIM;

    auto load_kv = [&](int st, int j0) {
        __half* K = Kh + st * 64 * HPAD;
        __half* V = Vh + st * 64 * HPAD;
#pragma unroll
        for (int i = tid; i < 64 * 8; i += 256) {
            int row = i >> 3, c8 = (i & 7) * 8;
            cp16(&K[row * HPAD + c8], &kb[(size_t)(j0 + row) * HDIM + c8]);
            cp16(&V[row * HPAD + c8], &vb[(size_t)(j0 + row) * HDIM + c8]);
        }
    };
    auto load_km = [&](int st, int j0) {
        if (tid < 64) {
            int gj = j0 + tid;
            kmB[st * 64 + tid] =
                (gj == 0) ? 1.f : (mask[(size_t)b * (SEQ - 1) + gj - 1] ? 1.f : 0.f);
        }
    };

    load_kv(0, 0);  cp_commit();
    load_kv(1, 64); cp_commit();
    load_km(0, 0);
    load_km(1, 64);

    for (int i = tid; i < 128 * 8; i += 256) {
        int row = i >> 3, c8 = (i & 7) * 8;
        *(float4*)&QP[row * HPAD + c8] = *(const float4*)&qb[(size_t)row * HDIM + c8];
    }
    __syncthreads();

    uint32_t qa[4][4];
#pragma unroll
    for (int kc = 0; kc < 4; kc++)
        ldsm_x4(qpBase + (uint32_t)(kc * 16 * 2), qa[kc]);

    const int gi0 = i0 + r0, gi1 = i0 + r1;
    const bool qok0 = (gi0 == 0) || (mask[(size_t)b * (SEQ - 1) + gi0 - 1] != 0);
    const bool qok1 = (gi1 == 0) || (mask[(size_t)b * (SEQ - 1) + gi1 - 1] != 0);

    float m0 = NEGINF, m1 = NEGINF, l0 = 0.f, l1 = 0.f;
    float o[8][4] = {};

    __half* Pb = QP;

    const int NT = SEQ / 64;   // 16
    for (int it = 0; it < NT; it++) {
        const int cur = it % 3;
        if (it + 1 < NT) asm volatile("cp.async.wait_group 1;");
        else             asm volatile("cp.async.wait_group 0;");
        __syncthreads();
        if (it + 2 < NT) {
            load_kv((it + 2) % 3, (it + 2) * 64);
            cp_commit();
            load_km((it + 2) % 3, (it + 2) * 64);
        }

        const float* km = kmB + cur * 64;
        const uint32_t kCur = kBase + cur * HSTAGE;
        const uint32_t vCur = vBase + cur * HSTAGE;

        // S = Q K^T (f16 m16n8k16)
        float s[8][4] = {};
#pragma unroll
        for (int kc = 0; kc < 4; kc++) {
            uint32_t kf[4][4];
#pragma unroll
            for (int np = 0; np < 4; np++)
                ldsm_x4(kCur + (uint32_t)((np * 16 * HPAD + kc * 16) * 2), kf[np]);
#pragma unroll
            for (int ni = 0; ni < 8; ni++)
                mma_f16_16x8x16(s[ni], qa[kc], &kf[ni >> 1][(ni & 1) * 2]);
        }

        float rmax0 = NEGINF, rmax1 = NEGINF;
#pragma unroll
        for (int ni = 0; ni < 8; ni++) {
            bool k0ok = km[ni * 8 + 2 * tg] != 0.f;
            bool k1ok = km[ni * 8 + 2 * tg + 1] != 0.f;
            s[ni][0] = (qok0 && k0ok) ? s[ni][0] * SCALE_L2E : MASKV;
            s[ni][1] = (qok0 && k1ok) ? s[ni][1] * SCALE_L2E : MASKV;
            s[ni][2] = (qok1 && k0ok) ? s[ni][2] * SCALE_L2E : MASKV;
            s[ni][3] = (qok1 && k1ok) ? s[ni][3] * SCALE_L2E : MASKV;
            rmax0 = fmaxf(rmax0, fmaxf(s[ni][0], s[ni][1]));
            rmax1 = fmaxf(rmax1, fmaxf(s[ni][2], s[ni][3]));
        }
        rmax0 = fmaxf(rmax0, __shfl_xor_sync(0xffffffffu, rmax0, 1));
        rmax0 = fmaxf(rmax0, __shfl_xor_sync(0xffffffffu, rmax0, 2));
        rmax1 = fmaxf(rmax1, __shfl_xor_sync(0xffffffffu, rmax1, 1));
        rmax1 = fmaxf(rmax1, __shfl_xor_sync(0xffffffffu, rmax1, 2));

        float nm0 = fmaxf(m0, rmax0), nm1 = fmaxf(m1, rmax1);
        float fac0 = ex2f(m0 - nm0), fac1 = ex2f(m1 - nm1);
        m0 = nm0; m1 = nm1;

        float sum0 = 0.f, sum1 = 0.f;
#pragma unroll
        for (int ni = 0; ni < 8; ni++) {
            float p0 = ex2f(s[ni][0] - m0);
            float p1 = ex2f(s[ni][1] - m0);
            float p2 = ex2f(s[ni][2] - m1);
            float p3 = ex2f(s[ni][3] - m1);
            sum0 += p0 + p1; sum1 += p2 + p3;
            *(__half2*)&Pb[r0 * HPAD + ni * 8 + 2 * tg] = __floats2half2_rn(p0, p1);
            *(__half2*)&Pb[r1 * HPAD + ni * 8 + 2 * tg] = __floats2half2_rn(p2, p3);
        }
        sum0 += __shfl_xor_sync(0xffffffffu, sum0, 1);
        sum0 += __shfl_xor_sync(0xffffffffu, sum0, 2);
        sum1 += __shfl_xor_sync(0xffffffffu, sum1, 1);
        sum1 += __shfl_xor_sync(0xffffffffu, sum1, 2);
        l0 = l0 * fac0 + sum0;
        l1 = l1 * fac1 + sum1;

#pragma unroll
        for (int ni = 0; ni < 8; ni++) {
            o[ni][0] *= fac0; o[ni][1] *= fac0;
            o[ni][2] *= fac1; o[ni][3] *= fac1;
        }
        __syncwarp();   // P visible to the whole warp before ldmatrix reads

#pragma unroll
        for (int ks = 0; ks < 4; ks++) {
            uint32_t pf[4];
            ldsm_x4(qpBase + (uint32_t)(ks * 16 * 2), pf);
#pragma unroll
            for (int np = 0; np < 4; np++) {
                uint32_t vf[4];
                ldsm_x4_t(vCur + (uint32_t)((ks * 16 * HPAD + np * 16) * 2), vf);
                mma_f16_16x8x16(o[np * 2],     pf, &vf[0]);
                mma_f16_16x8x16(o[np * 2 + 1], pf, &vf[2]);
            }
        }
        // no bottom sync: next iteration's top sync orders stage reuse
    }

    float inv0 = 1.f / l0, inv1 = 1.f / l1;
    size_t row0 = (size_t)b * SEQ + i0 + r0;
    size_t row1 = (size_t)b * SEQ + i0 + r1;
#pragma unroll
    for (int ni = 0; ni < 8; ni++) {
        *(__half2*)&g_attnh[row0 * DIM + h * HDIM + ni * 8 + 2 * tg] =
            __floats2half2_rn(o[ni][0] * inv0, o[ni][1] * inv0);
        *(__half2*)&g_attnh[row1 * DIM + h * HDIM + ni * 8 + 2 * tg] =
            __floats2half2_rn(o[ni][2] * inv1, o[ni][3] * inv1);
    }
}

// ---------------------------------------------------------------------------
extern "C" void kernel_launch(void* const* d_in, const int* in_sizes, int n_in,
                              void* d_out, int out_size)
{
    const float* x    = (const float*)d_in[0];
    const int*   mask = (const int*)d_in[1];     // bool widened to int32 by harness
    const float* pos  = (const float*)d_in[2];
    const float* Wqk  = (const float*)d_in[3];
    const float* Wv   = (const float*)d_in[4];
    const float* Wout = (const float*)d_in[5];
    const float* bout = (const float*)d_in[6];
    float*       out  = (float*)d_out;

    cudaFuncSetAttribute(qkv_gemm_kernel, cudaFuncAttributeMaxDynamicSharedMemorySize,
                         GEMM_SMEM_BYTES);
    cudaFuncSetAttribute(out_gemm_kernel, cudaFuncAttributeMaxDynamicSharedMemorySize,
                         GEMM_SMEM_BYTES);
    cudaFuncSetAttribute(attn_kernel, cudaFuncAttributeMaxDynamicSharedMemorySize,
                         ATT_SMEM_BYTES);

    __half *d_x16, *d_w16, *d_wo16;
    cudaGetSymbolAddress((void**)&d_x16,  g_x16);
    cudaGetSymbolAddress((void**)&d_w16,  g_w16);
    cudaGetSymbolAddress((void**)&d_wo16, g_wo16);

    {   // prep: all fp32 -> fp16 conversions in one launch
        prep_kernel<<<(P_TOT + 255) / 256, 256>>>(
            (const float4*)x, (const float4*)Wqk, (const float4*)Wv,
            (const float4*)Wout,
            (__half2*)d_x16, (__half2*)d_w16, (__half2*)d_wo16);
    }
    {   // QKV projection: M=8192, N=3072
        dim3 grid(QKVN / 128, MROWS / 128);
        qkv_gemm_kernel<<<grid, 256, GEMM_SMEM_BYTES>>>(pos);
    }
    {   // Attention: 8 row-tiles x 128 (b,h) pairs
        dim3 grid(SEQ / 128, BATCH * HEADS);
        attn_kernel<<<grid, 256, ATT_SMEM_BYTES>>>(mask);
    }
    {   // Output projection: M=8192, N=1024
        dim3 grid(DIM / 128, MROWS / 128);
        out_gemm_kernel<<<grid, 256, GEMM_SMEM_BYTES>>>(bout, out);
    }
}